// round 7
// baseline (speedup 1.0000x reference)
#include <cuda_runtime.h>
#include <cuda_bf16.h>
#include <cstdint>

#define BB    8192
#define NVV   778
#define NJJ   16
#define CTOT  2334
#define CPAD  2496          // 13 * 192
#define GK    192           // padded K (145 feat + pad)

// ---------------- device scratch (static; no runtime alloc) ----------------
__device__ __align__(16) float          g_V[(size_t)BB * CPAD];      // GEMM out + bias
__device__ __align__(16) __nv_bfloat16  g_A[BB * GK];
__device__ __align__(16) __nv_bfloat16  g_B[CPAD * GK];              // B^T [n][k]
__device__ __align__(16) float g_J0[NJJ * 3];
__device__ __align__(16) float g_JS[NJJ * 3 * 10];
// M'' batch-pair interleaved: [b/2][j][k][parity]
__device__ __align__(16) float g_M[(BB / 2) * NJJ * 12 * 2];

__constant__ int c_par[16] = {0,0,1,2,0,4,5,0,7,8,0,10,11,0,13,14};
__constant__ int c_inv[16] = {0,5,6,7,9,10,11,17,18,19,13,14,15,1,2,3};

typedef unsigned long long ull;

__device__ __forceinline__ ull pk2(float lo, float hi) {
    ull r;
    asm("mov.b64 %0, {%1, %2};" : "=l"(r) : "f"(lo), "f"(hi));
    return r;
}
__device__ __forceinline__ void upk2(ull v, float& lo, float& hi) {
    asm("mov.b64 {%0, %1}, %2;" : "=f"(lo), "=f"(hi) : "l"(v));
}
__device__ __forceinline__ ull f2fma(ull a, ull b, ull c) {
    ull d;
    asm("fma.rn.f32x2 %0, %1, %2, %3;" : "=l"(d) : "l"(a), "l"(b), "l"(c));
    return d;
}

__device__ __forceinline__ void mma16816(float* d, const uint32_t* a,
                                         const uint32_t* b) {
    asm volatile(
        "mma.sync.aligned.m16n8k16.row.col.f32.bf16.bf16.f32 "
        "{%0,%1,%2,%3}, {%4,%5,%6,%7}, {%8,%9}, {%0,%1,%2,%3};"
        : "+f"(d[0]), "+f"(d[1]), "+f"(d[2]), "+f"(d[3])
        : "r"(a[0]), "r"(a[1]), "r"(a[2]), "r"(a[3]), "r"(b[0]), "r"(b[1]));
}

__device__ __forceinline__ uint32_t smem_u32(const void* p) {
    uint32_t a;
    asm("{ .reg .u64 t; cvta.to.shared.u64 t, %1; cvt.u32.u64 %0, t; }"
        : "=r"(a) : "l"(p));
    return a;
}
__device__ __forceinline__ void cpasync16(uint32_t dst, const void* src) {
    asm volatile("cp.async.ca.shared.global [%0], [%1], 16;"
                 :: "r"(dst), "l"(src));
}
#define CP_COMMIT()  asm volatile("cp.async.commit_group;" ::: "memory")
#define CP_WAIT(n)   asm volatile("cp.async.wait_group %0;" :: "n"(n) : "memory")

// ---------------------------------------------------------------------------
// K0: merged prep.  blocks [0,6144): A build; [6144,6384): B build;
//                   [6384,6400): joint-regressor contractions
// ---------------------------------------------------------------------------
__global__ __launch_bounds__(256) void k0_prep(const float* __restrict__ vt,
                                               const float* __restrict__ sd,
                                               const float* __restrict__ pd,
                                               const float* __restrict__ shape,
                                               const float* __restrict__ finger,
                                               const float* __restrict__ jreg) {
    __shared__ float red[33 * 256];
    const int blk = blockIdx.x, tid = threadIdx.x;

    if (blk < 6144) {                       // ---- A: feat bf16 [B x 192]
        int idx = blk * 256 + tid;
        int b = idx / GK, k = idx - b * GK;
        float val = 0.f;
        if (k < 10) val = shape[b * 10 + k];
        else if (k < 145) {
            int q = k - 10;
            val = finger[b * 135 + q];
            if (((q % 9) & 3) == 0) val -= 1.0f;
        }
        g_A[idx] = __float2bfloat16_rn(val);
        return;
    }
    if (blk < 6384) {                       // ---- B^T bf16 [n][k]
        int q = blk - 6144;
        int kg = q / 10, nb = q - kg * 10;
        int n = nb * 256 + tid;
        if (n >= CPAD) return;
        unsigned short hs[8];
#pragma unroll
        for (int i = 0; i < 8; i++) {
            int k = kg * 8 + i;
            float val = 0.f;
            if (n < CTOT) {
                if (k < 10)       val = sd[n * 10 + k];
                else if (k < 145) val = pd[(k - 10) * CTOT + n];
            }
            hs[i] = __bfloat16_as_ushort(__float2bfloat16_rn(val));
        }
        uint4 ph;
        ph.x = hs[0] | ((uint32_t)hs[1] << 16);
        ph.y = hs[2] | ((uint32_t)hs[3] << 16);
        ph.z = hs[4] | ((uint32_t)hs[5] << 16);
        ph.w = hs[6] | ((uint32_t)hs[7] << 16);
        *reinterpret_cast<uint4*>(&g_B[n * GK + kg * 8]) = ph;
        return;
    }
    // ---- joint regressor: one block per joint
    const int j = blk - 6384;
    float acc[33];
#pragma unroll
    for (int o = 0; o < 33; o++) acc[o] = 0.f;
    for (int v = tid; v < NVV; v += 256) {
        float w = jreg[j * NVV + v];
#pragma unroll
        for (int k = 0; k < 3; k++) {
            acc[k] += w * vt[v * 3 + k];
#pragma unroll
            for (int l = 0; l < 10; l++)
                acc[3 + k * 10 + l] += w * sd[(v * 3 + k) * 10 + l];
        }
    }
    for (int o = 0; o < 33; o++) red[o * 256 + tid] = acc[o];
    __syncthreads();
    if (tid < 33) {
        float s = 0.f;
        for (int i = 0; i < 256; i++) s += red[tid * 256 + i];
        if (tid < 3) g_J0[j * 3 + tid] = s;
        else {
            int o = tid - 3;
            int k = o / 10, l = o - k * 10;
            g_JS[(j * 3 + k) * 10 + l] = s;
        }
    }
}

// ---------------------------------------------------------------------------
// K2: joint chain — 4 batches per 256-thread CTA, coalesced frmt staging
// ---------------------------------------------------------------------------
__device__ __forceinline__ void mul4(const float* a, float* d) {
    float t[16];
#pragma unroll
    for (int r = 0; r < 4; r++)
#pragma unroll
        for (int c = 0; c < 4; c++)
            t[r * 4 + c] = a[r * 4 + 0] * d[0 + c] + a[r * 4 + 1] * d[4 + c] +
                           a[r * 4 + 2] * d[8 + c] + a[r * 4 + 3] * d[12 + c];
#pragma unroll
    for (int i = 0; i < 16; i++) d[i] = t[i];
}

__global__ __launch_bounds__(256) void k2_joints(const float* __restrict__ grmt,
                          const float* __restrict__ frmt,
                          const float* __restrict__ shape,
                          const float* __restrict__ trans,
                          float* __restrict__ outJ) {
    __shared__ float sJ[4][16][3];
    __shared__ float sM[4][16][16];
    __shared__ float sF[4][136];
    __shared__ float sg[4][9], st[4][3], ssh[4][10];
    const int tid = threadIdx.x;
    const int bs = tid >> 6;
    const int tl = tid & 63;
    const int b = blockIdx.x * 4 + bs;
    const int b0 = blockIdx.x * 4;

    for (int i = tid; i < 540; i += 256) {
        int s = i / 135, q = i - s * 135;
        sF[s][q] = frmt[(b0 + s) * 135 + q];
    }
    if (tl < 9)  sg[bs][tl]  = grmt[b * 9 + tl];
    if (tl < 3)  st[bs][tl]  = trans[b * 3 + tl];
    if (tl < 10) ssh[bs][tl] = shape[b * 10 + tl];
    __syncthreads();

    if (tl < 48) {
        int j = tl / 3, k = tl - j * 3;
        float a = g_J0[j * 3 + k];
#pragma unroll
        for (int l = 0; l < 10; l++) a += ssh[bs][l] * g_JS[(j * 3 + k) * 10 + l];
        sJ[bs][j][k] = a;
    }
    __syncthreads();

    if (tl < 16) {
        int j = tl;
        float R[9];
        if (j == 0) {
            R[0]=1;R[1]=0;R[2]=0;R[3]=0;R[4]=1;R[5]=0;R[6]=0;R[7]=0;R[8]=1;
        } else {
#pragma unroll
            for (int i = 0; i < 9; i++) R[i] = sF[bs][(j - 1) * 9 + i];
        }
        float t0 = sJ[bs][j][0], t1 = sJ[bs][j][1], t2 = sJ[bs][j][2];
        if (j > 0) {
            int p = c_par[j];
            t0 -= sJ[bs][p][0]; t1 -= sJ[bs][p][1]; t2 -= sJ[bs][p][2];
        }
        float* m = sM[bs][j];
        m[0]=R[0]; m[1]=R[1]; m[2]=R[2];  m[3]=t0;
        m[4]=R[3]; m[5]=R[4]; m[6]=R[5];  m[7]=t1;
        m[8]=R[6]; m[9]=R[7]; m[10]=R[8]; m[11]=t2;
        m[12]=0.f; m[13]=0.f; m[14]=0.f;  m[15]=1.f;
    }
    __syncthreads();

    if (tl < 5) {
        int j = 1 + 3 * tl;
        mul4(sM[bs][0], sM[bs][j]);
        mul4(sM[bs][j], sM[bs][j + 1]);
        mul4(sM[bs][j + 1], sM[bs][j + 2]);
    }
    __syncthreads();

    if (tl < 16) {
        int j = tl;
        const float* m = sM[bs][j];
        float jt0 = m[3], jt1 = m[7], jt2 = m[11];
        float J0 = sJ[bs][j][0], J1 = sJ[bs][j][1], J2 = sJ[bs][j][2];
        float tc0 = jt0 - (m[0] * J0 + m[1] * J1 + m[2]  * J2);
        float tc1 = jt1 - (m[4] * J0 + m[5] * J1 + m[6]  * J2);
        float tc2 = jt2 - (m[8] * J0 + m[9] * J1 + m[10] * J2);
        float* o = &g_M[(((b >> 1) * 16 + j) * 12) * 2 + (b & 1)];
        float row[12];
        int jp = c_inv[j];
#pragma unroll
        for (int r = 0; r < 3; r++) {
            float a = sg[bs][r * 3 + 0], bb = sg[bs][r * 3 + 1], cc = sg[bs][r * 3 + 2];
            row[r * 4 + 0] = a * m[0] + bb * m[4] + cc * m[8];
            row[r * 4 + 1] = a * m[1] + bb * m[5] + cc * m[9];
            row[r * 4 + 2] = a * m[2] + bb * m[6] + cc * m[10];
            row[r * 4 + 3] = a * tc0  + bb * tc1  + cc * tc2 + st[bs][r];
            outJ[(b * 21 + jp) * 3 + r] = a * jt0 + bb * jt1 + cc * jt2 + st[bs][r];
        }
#pragma unroll
        for (int k = 0; k < 12; k++) o[k * 2] = row[k];
    }
}

// ---------------------------------------------------------------------------
// K3: single-bf16 mma.sync GEMM, cp.async 2-stage -> g_V (+fp32 bias)
// ---------------------------------------------------------------------------
#define STG_SZ  46080
#define SM_K3   92160

__global__ __launch_bounds__(512, 1) void k3_gemm(const float* __restrict__ vt) {
    extern __shared__ __align__(16) char smem[];
    __shared__ float sBias[192];
    const uint32_t sbase = smem_u32(smem);
    const int tid = threadIdx.x;
    const int wid = tid >> 5, lane = tid & 31;
    const int wm = wid & 1, wn = wid >> 1;
    const int gid = lane >> 2, tig = lane & 3;
    const int b0 = blockIdx.x * 128;
    const int t  = blockIdx.y;

    if (tid < 192) {
        int c = t * 192 + tid;
        sBias[tid] = (c < CTOT) ? vt[c] : 0.f;
    }

    auto stage_chunk = [&](int s, int ch) {
        const uint32_t stg = sbase + s * STG_SZ;
        for (int i = tid; i < 2560; i += 512) {
            if (i < 1024) {
                int r = i >> 3, q = i & 7;
                cpasync16(stg + r * 144 + q * 16,
                          &g_A[(b0 + r) * GK + ch * 64 + q * 8]);
            } else {
                int i2 = i - 1024;
                int r = i2 >> 3, q = i2 & 7;
                cpasync16(stg + 18432 + r * 144 + q * 16,
                          &g_B[(t * 192 + r) * GK + ch * 64 + q * 8]);
            }
        }
    };

    float d[4][3][4];
#pragma unroll
    for (int mt = 0; mt < 4; mt++)
#pragma unroll
        for (int nt = 0; nt < 3; nt++)
#pragma unroll
            for (int q = 0; q < 4; q++) d[mt][nt][q] = 0.f;

    stage_chunk(0, 0); CP_COMMIT();
    stage_chunk(1, 1); CP_COMMIT();

    auto mma_chunk = [&](int s) {
        const char* stg = smem + s * STG_SZ;
#pragma unroll
        for (int ks = 0; ks < 4; ks++) {
            const int kb = ks * 32 + tig * 4;
            uint32_t ah[4][4];
#pragma unroll
            for (int mt = 0; mt < 4; mt++) {
                int r0 = wm * 64 + mt * 16 + gid;
                const char* ph = stg + r0 * 144 + kb;
                ah[mt][0] = *(const uint32_t*)(ph);
                ah[mt][1] = *(const uint32_t*)(ph + 8 * 144);
                ah[mt][2] = *(const uint32_t*)(ph + 16);
                ah[mt][3] = *(const uint32_t*)(ph + 8 * 144 + 16);
            }
            uint32_t bh[3][2];
#pragma unroll
            for (int nt = 0; nt < 3; nt++) {
                int n0 = wn * 24 + nt * 8 + gid;
                const char* ph = stg + 18432 + n0 * 144 + kb;
                bh[nt][0] = *(const uint32_t*)(ph);
                bh[nt][1] = *(const uint32_t*)(ph + 16);
            }
#pragma unroll
            for (int mt = 0; mt < 4; mt++)
#pragma unroll
                for (int nt = 0; nt < 3; nt++)
                    mma16816(d[mt][nt], ah[mt], bh[nt]);
        }
    };

    CP_WAIT(1); __syncthreads();
    mma_chunk(0);
    __syncthreads();
    stage_chunk(0, 2); CP_COMMIT();
    CP_WAIT(1); __syncthreads();
    mma_chunk(1);
    CP_WAIT(0); __syncthreads();
    mma_chunk(0);

#pragma unroll
    for (int mt = 0; mt < 4; mt++) {
        int r0 = b0 + wm * 64 + mt * 16 + gid;
#pragma unroll
        for (int nt = 0; nt < 3; nt++) {
            int cl = wn * 24 + nt * 8 + tig * 2;
            int c = t * 192 + cl;
            float bx = sBias[cl], by = sBias[cl + 1];
            *reinterpret_cast<float2*>(&g_V[(size_t)r0 * CPAD + c]) =
                make_float2(d[mt][nt][0] + bx, d[mt][nt][1] + by);
            *reinterpret_cast<float2*>(&g_V[(size_t)(r0 + 8) * CPAD + c]) =
                make_float2(d[mt][nt][2] + bx, d[mt][nt][3] + by);
        }
    }
}

// ---------------------------------------------------------------------------
// K4: LBS epilogue, f32x2 over batch pairs. 4 verts x 1 pair per thread.
//   CTA: 256 thr, tile 32 batch x 64 verts.
// ---------------------------------------------------------------------------
__global__ __launch_bounds__(256, 2) void k4_epi(const float* __restrict__ lbs,
                                                 float* __restrict__ outV,
                                                 float* __restrict__ outJ) {
    __shared__ __align__(16) float sMmP[16 * 392];   // [pair][j*24 + k*2 + par]
    __shared__ __align__(16) float sW2[16 * 64 * 2]; // [j][v][dup]
    const int tid = threadIdx.x;
    const int b0 = blockIdx.x * 32;
    const int v0 = blockIdx.y * 64;
    const int c0 = v0 * 3;

    {
        const float4* src = reinterpret_cast<const float4*>(
            &g_M[(size_t)(b0 / 2) * 384]);
        for (int i = tid; i < 1536; i += 256) {
            int pr = i / 96, q = i - pr * 96;
            *reinterpret_cast<float4*>(&sMmP[pr * 392 + q * 4]) = src[i];
        }
    }
    for (int i = tid; i < 1024; i += 256) {
        int v = i >> 4, j = i & 15;
        float w = (v0 + v < NVV) ? lbs[(v0 + v) * 16 + j] : 0.f;
        sW2[(j * 64 + v) * 2]     = w;
        sW2[(j * 64 + v) * 2 + 1] = w;
    }
    __syncthreads();

    const int vq = tid & 15;      // vert group (4 verts)
    const int pq = tid >> 4;      // pair 0..15
    const int bA = b0 + pq * 2;
    const int cbase = c0 + vq * 12;

    // load V for both batches (fp32, bias already included)
    float va[12], vb[12];
    {
        const float* p0 = &g_V[(size_t)bA * CPAD + cbase];
        const float* p1 = p0 + CPAD;
#pragma unroll
        for (int q = 0; q < 3; q++) {
            float4 x0 = reinterpret_cast<const float4*>(p0)[q];
            float4 x1 = reinterpret_cast<const float4*>(p1)[q];
            va[q*4+0]=x0.x; va[q*4+1]=x0.y; va[q*4+2]=x0.z; va[q*4+3]=x0.w;
            vb[q*4+0]=x1.x; vb[q*4+1]=x1.y; vb[q*4+2]=x1.z; vb[q*4+3]=x1.w;
        }
    }
    ull pX[4], pY[4], pZ[4];
#pragma unroll
    for (int vi = 0; vi < 4; vi++) {
        pX[vi] = pk2(va[vi * 3 + 0], vb[vi * 3 + 0]);
        pY[vi] = pk2(va[vi * 3 + 1], vb[vi * 3 + 1]);
        pZ[vi] = pk2(va[vi * 3 + 2], vb[vi * 3 + 2]);
    }

    ull o[12];
#pragma unroll
    for (int i = 0; i < 12; i++) o[i] = 0ull;

#pragma unroll 4
    for (int j = 0; j < 16; j++) {
        const ulonglong2* mp =
            reinterpret_cast<const ulonglong2*>(&sMmP[pq * 392 + j * 24]);
        const ulonglong2* wp =
            reinterpret_cast<const ulonglong2*>(&sW2[(j * 64 + vq * 4) * 2]);
        ulonglong2 mm0 = mp[0], mm1 = mp[1], mm2 = mp[2];
        ulonglong2 mm3 = mp[3], mm4 = mp[4], mm5 = mp[5];
        ulonglong2 ww0 = wp[0], ww1 = wp[1];
        ull m0 = mm0.x, m1 = mm0.y, m2 = mm1.x,  m3 = mm1.y;
        ull m4 = mm2.x, m5 = mm2.y, m6 = mm3.x,  m7 = mm3.y;
        ull m8 = mm4.x, m9 = mm4.y, m10 = mm5.x, m11 = mm5.y;
        ull w[4] = {ww0.x, ww0.y, ww1.x, ww1.y};
#pragma unroll
        for (int vi = 0; vi < 4; vi++) {
            ull t0 = f2fma(m0, pX[vi], f2fma(m1, pY[vi], f2fma(m2,  pZ[vi], m3)));
            ull t1 = f2fma(m4, pX[vi], f2fma(m5, pY[vi], f2fma(m6,  pZ[vi], m7)));
            ull t2 = f2fma(m8, pX[vi], f2fma(m9, pY[vi], f2fma(m10, pZ[vi], m11)));
            o[vi * 3 + 0] = f2fma(w[vi], t0, o[vi * 3 + 0]);
            o[vi * 3 + 1] = f2fma(w[vi], t1, o[vi * 3 + 1]);
            o[vi * 3 + 2] = f2fma(w[vi], t2, o[vi * 3 + 2]);
        }
    }

    float oa[12], ob[12];
#pragma unroll
    for (int i = 0; i < 12; i++) upk2(o[i], oa[i], ob[i]);

#pragma unroll
    for (int vi = 0; vi < 4; vi++) {
        int v = v0 + vq * 4 + vi;
        int tp = -1;
        if (v == 745) tp = 4; else if (v == 317) tp = 8;
        else if (v == 444) tp = 12; else if (v == 556) tp = 16;
        else if (v == 673) tp = 20;
        if (tp >= 0) {
            int base = vi * 3;
            outJ[((bA)     * 21 + tp) * 3 + 0] = oa[base + 0];
            outJ[((bA)     * 21 + tp) * 3 + 1] = oa[base + 1];
            outJ[((bA)     * 21 + tp) * 3 + 2] = oa[base + 2];
            outJ[((bA + 1) * 21 + tp) * 3 + 0] = ob[base + 0];
            outJ[((bA + 1) * 21 + tp) * 3 + 1] = ob[base + 1];
            outJ[((bA + 1) * 21 + tp) * 3 + 2] = ob[base + 2];
        }
    }

    if (cbase + 12 <= CTOT) {
        float* p0 = &outV[(size_t)bA * CTOT + cbase];
        float* p1 = p0 + CTOT;
#pragma unroll
        for (int q = 0; q < 6; q++) {
            reinterpret_cast<float2*>(p0)[q] = make_float2(oa[q*2], oa[q*2+1]);
            reinterpret_cast<float2*>(p1)[q] = make_float2(ob[q*2], ob[q*2+1]);
        }
    } else if (cbase < CTOT) {
        int nval = CTOT - cbase;
        float* p0 = &outV[(size_t)bA * CTOT + cbase];
        float* p1 = p0 + CTOT;
        for (int q = 0; q < nval; q++) { p0[q] = oa[q]; p1[q] = ob[q]; }
    }
}

// ---------------------------------------------------------------------------
extern "C" void kernel_launch(void* const* d_in, const int* in_sizes, int n_in,
                              void* d_out, int out_size) {
    const float* grmt  = (const float*)d_in[0];
    const float* frmt  = (const float*)d_in[1];
    const float* shape = (const float*)d_in[2];
    const float* trans = (const float*)d_in[3];
    const float* vt    = (const float*)d_in[4];
    const float* sd    = (const float*)d_in[5];
    const float* jreg  = (const float*)d_in[6];
    const float* pd    = (const float*)d_in[7];
    const float* lbs   = (const float*)d_in[8];

    float* out  = (float*)d_out;
    float* outV = out;
    float* outJ = out + (size_t)BB * CTOT;

    static bool attr_done = false;
    if (!attr_done) {
        cudaFuncSetAttribute(k3_gemm, cudaFuncAttributeMaxDynamicSharedMemorySize,
                             SM_K3);
        attr_done = true;
    }

    k0_prep<<<6400, 256>>>(vt, sd, pd, shape, frmt, jreg);
    k2_joints<<<BB / 4, 256>>>(grmt, frmt, shape, trans, outJ);
    k3_gemm<<<dim3(BB / 128, 13), 512, SM_K3>>>(vt);
    k4_epi<<<dim3(BB / 32, 13), 256>>>(lbs, outV, outJ);
}

// round 8
// speedup vs baseline: 1.0960x; 1.0960x over previous
#include <cuda_runtime.h>
#include <cuda_bf16.h>
#include <cstdint>

#define BB    8192
#define NVV   778
#define NJJ   16
#define CTOT  2334
#define CPAD  2496          // 13 * 192
#define GK    192           // padded K (145 feat + pad)
#define NVP   832           // 13 * 64 padded verts

// ---------------- device scratch (static; no runtime alloc) ----------------
__device__ __align__(16) float          g_V[(size_t)BB * CPAD];      // GEMM out + bias
__device__ __align__(16) __nv_bfloat16  g_A[BB * GK];
__device__ __align__(16) __nv_bfloat16  g_B[CPAD * GK];              // B^T [n][k]
__device__ __align__(16) __nv_bfloat16  g_Whi[NVP * 16];             // lbs hi/lo
__device__ __align__(16) __nv_bfloat16  g_Wlo[NVP * 16];
__device__ __align__(16) __nv_bfloat16  g_MH[(size_t)BB * 12 * 16];  // M'' hi [(b*12+m)*16+j]
__device__ __align__(16) __nv_bfloat16  g_ML[(size_t)BB * 12 * 16];  // M'' lo
__device__ __align__(16) float g_J0[NJJ * 3];
__device__ __align__(16) float g_JS[NJJ * 3 * 10];

__constant__ int c_par[16] = {0,0,1,2,0,4,5,0,7,8,0,10,11,0,13,14};
__constant__ int c_inv[16] = {0,5,6,7,9,10,11,17,18,19,13,14,15,1,2,3};

__device__ __forceinline__ void mma16816(float* d, const uint32_t* a,
                                         const uint32_t* b) {
    asm volatile(
        "mma.sync.aligned.m16n8k16.row.col.f32.bf16.bf16.f32 "
        "{%0,%1,%2,%3}, {%4,%5,%6,%7}, {%8,%9}, {%0,%1,%2,%3};"
        : "+f"(d[0]), "+f"(d[1]), "+f"(d[2]), "+f"(d[3])
        : "r"(a[0]), "r"(a[1]), "r"(a[2]), "r"(a[3]), "r"(b[0]), "r"(b[1]));
}

__device__ __forceinline__ uint32_t smem_u32(const void* p) {
    uint32_t a;
    asm("{ .reg .u64 t; cvta.to.shared.u64 t, %1; cvt.u32.u64 %0, t; }"
        : "=r"(a) : "l"(p));
    return a;
}
__device__ __forceinline__ void cpasync16(uint32_t dst, const void* src) {
    asm volatile("cp.async.ca.shared.global [%0], [%1], 16;"
                 :: "r"(dst), "l"(src));
}
#define CP_COMMIT()  asm volatile("cp.async.commit_group;" ::: "memory")
#define CP_WAIT(n)   asm volatile("cp.async.wait_group %0;" :: "n"(n) : "memory")

// ---------------------------------------------------------------------------
// K0: merged prep.  [0,6144): A; [6144,6384): B; [6384,6400): jreg;
//                   [6400,6452): lbs hi/lo split
// ---------------------------------------------------------------------------
__global__ __launch_bounds__(256) void k0_prep(const float* __restrict__ vt,
                                               const float* __restrict__ sd,
                                               const float* __restrict__ pd,
                                               const float* __restrict__ shape,
                                               const float* __restrict__ finger,
                                               const float* __restrict__ jreg,
                                               const float* __restrict__ lbs) {
    __shared__ float red[33 * 256];
    const int blk = blockIdx.x, tid = threadIdx.x;

    if (blk < 6144) {                       // ---- A: feat bf16 [B x 192]
        int idx = blk * 256 + tid;
        int b = idx / GK, k = idx - b * GK;
        float val = 0.f;
        if (k < 10) val = shape[b * 10 + k];
        else if (k < 145) {
            int q = k - 10;
            val = finger[b * 135 + q];
            if (((q % 9) & 3) == 0) val -= 1.0f;
        }
        g_A[idx] = __float2bfloat16_rn(val);
        return;
    }
    if (blk < 6384) {                       // ---- B^T bf16 [n][k]
        int q = blk - 6144;
        int kg = q / 10, nb = q - kg * 10;
        int n = nb * 256 + tid;
        if (n >= CPAD) return;
        unsigned short hs[8];
#pragma unroll
        for (int i = 0; i < 8; i++) {
            int k = kg * 8 + i;
            float val = 0.f;
            if (n < CTOT) {
                if (k < 10)       val = sd[n * 10 + k];
                else if (k < 145) val = pd[(k - 10) * CTOT + n];
            }
            hs[i] = __bfloat16_as_ushort(__float2bfloat16_rn(val));
        }
        uint4 ph;
        ph.x = hs[0] | ((uint32_t)hs[1] << 16);
        ph.y = hs[2] | ((uint32_t)hs[3] << 16);
        ph.z = hs[4] | ((uint32_t)hs[5] << 16);
        ph.w = hs[6] | ((uint32_t)hs[7] << 16);
        *reinterpret_cast<uint4*>(&g_B[n * GK + kg * 8]) = ph;
        return;
    }
    if (blk >= 6400) {                      // ---- lbs hi/lo
        int idx = (blk - 6400) * 256 + tid;
        if (idx >= NVP * 16) return;
        int v = idx >> 4, j = idx & 15;
        float w = (v < NVV) ? lbs[v * 16 + j] : 0.f;
        __nv_bfloat16 hi = __float2bfloat16_rn(w);
        __nv_bfloat16 lo = __float2bfloat16_rn(w - __bfloat162float(hi));
        g_Whi[idx] = hi;
        g_Wlo[idx] = lo;
        return;
    }
    // ---- joint regressor: one block per joint
    const int j = blk - 6384;
    float acc[33];
#pragma unroll
    for (int o = 0; o < 33; o++) acc[o] = 0.f;
    for (int v = tid; v < NVV; v += 256) {
        float w = jreg[j * NVV + v];
#pragma unroll
        for (int k = 0; k < 3; k++) {
            acc[k] += w * vt[v * 3 + k];
#pragma unroll
            for (int l = 0; l < 10; l++)
                acc[3 + k * 10 + l] += w * sd[(v * 3 + k) * 10 + l];
        }
    }
    for (int o = 0; o < 33; o++) red[o * 256 + tid] = acc[o];
    __syncthreads();
    if (tid < 33) {
        float s = 0.f;
        for (int i = 0; i < 256; i++) s += red[tid * 256 + i];
        if (tid < 3) g_J0[j * 3 + tid] = s;
        else {
            int o = tid - 3;
            int k = o / 10, l = o - k * 10;
            g_JS[(j * 3 + k) * 10 + l] = s;
        }
    }
}

// ---------------------------------------------------------------------------
// K2: joint chain — 4 batches per CTA; writes M'' as split-bf16 (b*12+m)x16
// ---------------------------------------------------------------------------
__device__ __forceinline__ void mul4(const float* a, float* d) {
    float t[16];
#pragma unroll
    for (int r = 0; r < 4; r++)
#pragma unroll
        for (int c = 0; c < 4; c++)
            t[r * 4 + c] = a[r * 4 + 0] * d[0 + c] + a[r * 4 + 1] * d[4 + c] +
                           a[r * 4 + 2] * d[8 + c] + a[r * 4 + 3] * d[12 + c];
#pragma unroll
    for (int i = 0; i < 16; i++) d[i] = t[i];
}

__global__ __launch_bounds__(256) void k2_joints(const float* __restrict__ grmt,
                          const float* __restrict__ frmt,
                          const float* __restrict__ shape,
                          const float* __restrict__ trans,
                          float* __restrict__ outJ) {
    __shared__ float sJ[4][16][3];
    __shared__ float sM[4][16][16];
    __shared__ float sF[4][136];
    __shared__ float sg[4][9], st[4][3], ssh[4][10];
    const int tid = threadIdx.x;
    const int bs = tid >> 6;
    const int tl = tid & 63;
    const int b = blockIdx.x * 4 + bs;
    const int b0 = blockIdx.x * 4;

    for (int i = tid; i < 540; i += 256) {
        int s = i / 135, q = i - s * 135;
        sF[s][q] = frmt[(b0 + s) * 135 + q];
    }
    if (tl < 9)  sg[bs][tl]  = grmt[b * 9 + tl];
    if (tl < 3)  st[bs][tl]  = trans[b * 3 + tl];
    if (tl < 10) ssh[bs][tl] = shape[b * 10 + tl];
    __syncthreads();

    if (tl < 48) {
        int j = tl / 3, k = tl - j * 3;
        float a = g_J0[j * 3 + k];
#pragma unroll
        for (int l = 0; l < 10; l++) a += ssh[bs][l] * g_JS[(j * 3 + k) * 10 + l];
        sJ[bs][j][k] = a;
    }
    __syncthreads();

    if (tl < 16) {
        int j = tl;
        float R[9];
        if (j == 0) {
            R[0]=1;R[1]=0;R[2]=0;R[3]=0;R[4]=1;R[5]=0;R[6]=0;R[7]=0;R[8]=1;
        } else {
#pragma unroll
            for (int i = 0; i < 9; i++) R[i] = sF[bs][(j - 1) * 9 + i];
        }
        float t0 = sJ[bs][j][0], t1 = sJ[bs][j][1], t2 = sJ[bs][j][2];
        if (j > 0) {
            int p = c_par[j];
            t0 -= sJ[bs][p][0]; t1 -= sJ[bs][p][1]; t2 -= sJ[bs][p][2];
        }
        float* m = sM[bs][j];
        m[0]=R[0]; m[1]=R[1]; m[2]=R[2];  m[3]=t0;
        m[4]=R[3]; m[5]=R[4]; m[6]=R[5];  m[7]=t1;
        m[8]=R[6]; m[9]=R[7]; m[10]=R[8]; m[11]=t2;
        m[12]=0.f; m[13]=0.f; m[14]=0.f;  m[15]=1.f;
    }
    __syncthreads();

    if (tl < 5) {
        int j = 1 + 3 * tl;
        mul4(sM[bs][0], sM[bs][j]);
        mul4(sM[bs][j], sM[bs][j + 1]);
        mul4(sM[bs][j + 1], sM[bs][j + 2]);
    }
    __syncthreads();

    if (tl < 16) {
        int j = tl;
        const float* m = sM[bs][j];
        float jt0 = m[3], jt1 = m[7], jt2 = m[11];
        float J0 = sJ[bs][j][0], J1 = sJ[bs][j][1], J2 = sJ[bs][j][2];
        float tc0 = jt0 - (m[0] * J0 + m[1] * J1 + m[2]  * J2);
        float tc1 = jt1 - (m[4] * J0 + m[5] * J1 + m[6]  * J2);
        float tc2 = jt2 - (m[8] * J0 + m[9] * J1 + m[10] * J2);
        float row[12];
        int jp = c_inv[j];
#pragma unroll
        for (int r = 0; r < 3; r++) {
            float a = sg[bs][r * 3 + 0], bb = sg[bs][r * 3 + 1], cc = sg[bs][r * 3 + 2];
            row[r * 4 + 0] = a * m[0] + bb * m[4] + cc * m[8];
            row[r * 4 + 1] = a * m[1] + bb * m[5] + cc * m[9];
            row[r * 4 + 2] = a * m[2] + bb * m[6] + cc * m[10];
            row[r * 4 + 3] = a * tc0  + bb * tc1  + cc * tc2 + st[bs][r];
            outJ[(b * 21 + jp) * 3 + r] = a * jt0 + bb * jt1 + cc * jt2 + st[bs][r];
        }
        // split-bf16 M'' columns: row m of (b*12+m)x16 layout, k index = j
#pragma unroll
        for (int mm = 0; mm < 12; mm++) {
            float x = row[mm];
            __nv_bfloat16 hi = __float2bfloat16_rn(x);
            __nv_bfloat16 lo = __float2bfloat16_rn(x - __bfloat162float(hi));
            size_t off = ((size_t)b * 12 + mm) * 16 + j;
            g_MH[off] = hi;
            g_ML[off] = lo;
        }
    }
}

// ---------------------------------------------------------------------------
// K3: single-bf16 mma.sync GEMM, cp.async 2-stage -> g_V (+fp32 bias)
// ---------------------------------------------------------------------------
#define STG_SZ  46080
#define SM_K3   92160

__global__ __launch_bounds__(512, 1) void k3_gemm(const float* __restrict__ vt) {
    extern __shared__ __align__(16) char smem[];
    __shared__ float sBias[192];
    const uint32_t sbase = smem_u32(smem);
    const int tid = threadIdx.x;
    const int wid = tid >> 5, lane = tid & 31;
    const int wm = wid & 1, wn = wid >> 1;
    const int gid = lane >> 2, tig = lane & 3;
    const int b0 = blockIdx.x * 128;
    const int t  = blockIdx.y;

    if (tid < 192) {
        int c = t * 192 + tid;
        sBias[tid] = (c < CTOT) ? vt[c] : 0.f;
    }

    auto stage_chunk = [&](int s, int ch) {
        const uint32_t stg = sbase + s * STG_SZ;
        for (int i = tid; i < 2560; i += 512) {
            if (i < 1024) {
                int r = i >> 3, q = i & 7;
                cpasync16(stg + r * 144 + q * 16,
                          &g_A[(b0 + r) * GK + ch * 64 + q * 8]);
            } else {
                int i2 = i - 1024;
                int r = i2 >> 3, q = i2 & 7;
                cpasync16(stg + 18432 + r * 144 + q * 16,
                          &g_B[(t * 192 + r) * GK + ch * 64 + q * 8]);
            }
        }
    };

    float d[4][3][4];
#pragma unroll
    for (int mt = 0; mt < 4; mt++)
#pragma unroll
        for (int nt = 0; nt < 3; nt++)
#pragma unroll
            for (int q = 0; q < 4; q++) d[mt][nt][q] = 0.f;

    stage_chunk(0, 0); CP_COMMIT();
    stage_chunk(1, 1); CP_COMMIT();

    auto mma_chunk = [&](int s) {
        const char* stg = smem + s * STG_SZ;
#pragma unroll
        for (int ks = 0; ks < 4; ks++) {
            const int kb = ks * 32 + tig * 4;
            uint32_t ah[4][4];
#pragma unroll
            for (int mt = 0; mt < 4; mt++) {
                int r0 = wm * 64 + mt * 16 + gid;
                const char* ph = stg + r0 * 144 + kb;
                ah[mt][0] = *(const uint32_t*)(ph);
                ah[mt][1] = *(const uint32_t*)(ph + 8 * 144);
                ah[mt][2] = *(const uint32_t*)(ph + 16);
                ah[mt][3] = *(const uint32_t*)(ph + 8 * 144 + 16);
            }
            uint32_t bh[3][2];
#pragma unroll
            for (int nt = 0; nt < 3; nt++) {
                int n0 = wn * 24 + nt * 8 + gid;
                const char* ph = stg + 18432 + n0 * 144 + kb;
                bh[nt][0] = *(const uint32_t*)(ph);
                bh[nt][1] = *(const uint32_t*)(ph + 16);
            }
#pragma unroll
            for (int mt = 0; mt < 4; mt++)
#pragma unroll
                for (int nt = 0; nt < 3; nt++)
                    mma16816(d[mt][nt], ah[mt], bh[nt]);
        }
    };

    CP_WAIT(1); __syncthreads();
    mma_chunk(0);
    __syncthreads();
    stage_chunk(0, 2); CP_COMMIT();
    CP_WAIT(1); __syncthreads();
    mma_chunk(1);
    CP_WAIT(0); __syncthreads();
    mma_chunk(0);

#pragma unroll
    for (int mt = 0; mt < 4; mt++) {
        int r0 = b0 + wm * 64 + mt * 16 + gid;
#pragma unroll
        for (int nt = 0; nt < 3; nt++) {
            int cl = wn * 24 + nt * 8 + tig * 2;
            int c = t * 192 + cl;
            float bx = sBias[cl], by = sBias[cl + 1];
            *reinterpret_cast<float2*>(&g_V[(size_t)r0 * CPAD + c]) =
                make_float2(d[mt][nt][0] + bx, d[mt][nt][1] + by);
            *reinterpret_cast<float2*>(&g_V[(size_t)(r0 + 8) * CPAD + c]) =
                make_float2(d[mt][nt][2] + bx, d[mt][nt][3] + by);
        }
    }
}

// ---------------------------------------------------------------------------
// K4: LBS via tensor-core matrix blend.
//   CTA 256 thr, tile 64 verts x 16 batches. grid (512, 13)
//   Phase 1: Mv[64v x 192(b,m)] = W[64x16] @ Mcat[16 x 192] (split bf16, MMA)
//   Phase 2: per-(v,b) 3x4 matvec from smem Mv.
//   dyn smem: sWh@0(2K) sWl@2K sMh@4K(6K) sMl@10K sMv@16K(64x196 f) = 66560B
// ---------------------------------------------------------------------------
#define SM_K4 66560

__global__ __launch_bounds__(256, 3) void k4_epi(float* __restrict__ outV,
                                                 float* __restrict__ outJ) {
    extern __shared__ __align__(16) char smem[];
    __nv_bfloat16* sWh = reinterpret_cast<__nv_bfloat16*>(smem);
    __nv_bfloat16* sWl = reinterpret_cast<__nv_bfloat16*>(smem + 2048);
    __nv_bfloat16* sMh = reinterpret_cast<__nv_bfloat16*>(smem + 4096);
    __nv_bfloat16* sMl = reinterpret_cast<__nv_bfloat16*>(smem + 10240);
    float*         sMv = reinterpret_cast<float*>(smem + 16384);

    const int tid = threadIdx.x;
    const int b0 = blockIdx.x * 16;
    const int v0 = blockIdx.y * 64;
    const int c0 = v0 * 3;

    // ---- stage W (256 uint4 tasks: 2 splits x 64 rows x 2 halves) ----
    {
        int split = tid >> 7, i2 = tid & 127;
        int row = i2 >> 1, half = i2 & 1;
        const __nv_bfloat16* src = split ? g_Wlo : g_Whi;
        __nv_bfloat16* dst = split ? sWl : sWh;
        *reinterpret_cast<uint4*>(&dst[row * 16 + half * 8]) =
            *reinterpret_cast<const uint4*>(&src[(v0 + row) * 16 + half * 8]);
    }
    // ---- stage Mcat (768 uint4 tasks: 2 splits x 192 rows x 2 halves) ----
    for (int i = tid; i < 768; i += 256) {
        int split = i / 384, i2 = i - split * 384;
        int n = i2 >> 1, half = i2 & 1;
        const __nv_bfloat16* src = split ? g_ML : g_MH;
        __nv_bfloat16* dst = split ? sMl : sMh;
        *reinterpret_cast<uint4*>(&dst[n * 16 + half * 8]) =
            *reinterpret_cast<const uint4*>(
                &src[((size_t)b0 * 12 + n) * 16 + half * 8]);
    }
    __syncthreads();

    // ---- MMA: 4 mtiles x 3 ntiles per warp (8 warps cover 24 ntiles) ----
    const int wid = tid >> 5, lane = tid & 31;
    const int gid = lane >> 2, tig = lane & 3;

    float d[4][3][4];
#pragma unroll
    for (int mt = 0; mt < 4; mt++)
#pragma unroll
        for (int nt = 0; nt < 3; nt++)
#pragma unroll
            for (int q = 0; q < 4; q++) d[mt][nt][q] = 0.f;

#pragma unroll
    for (int mt = 0; mt < 4; mt++) {
        int r0 = mt * 16 + gid;
        uint32_t awh[4], awl[4];
        awh[0] = *reinterpret_cast<const uint32_t*>(&sWh[r0 * 16 + tig * 2]);
        awh[1] = *reinterpret_cast<const uint32_t*>(&sWh[(r0 + 8) * 16 + tig * 2]);
        awh[2] = *reinterpret_cast<const uint32_t*>(&sWh[r0 * 16 + 8 + tig * 2]);
        awh[3] = *reinterpret_cast<const uint32_t*>(&sWh[(r0 + 8) * 16 + 8 + tig * 2]);
        awl[0] = *reinterpret_cast<const uint32_t*>(&sWl[r0 * 16 + tig * 2]);
        awl[1] = *reinterpret_cast<const uint32_t*>(&sWl[(r0 + 8) * 16 + tig * 2]);
        awl[2] = *reinterpret_cast<const uint32_t*>(&sWl[r0 * 16 + 8 + tig * 2]);
        awl[3] = *reinterpret_cast<const uint32_t*>(&sWl[(r0 + 8) * 16 + 8 + tig * 2]);
#pragma unroll
        for (int ntl = 0; ntl < 3; ntl++) {
            int n0 = (wid * 3 + ntl) * 8 + gid;
            uint32_t bh[2], bl[2];
            bh[0] = *reinterpret_cast<const uint32_t*>(&sMh[n0 * 16 + tig * 2]);
            bh[1] = *reinterpret_cast<const uint32_t*>(&sMh[n0 * 16 + 8 + tig * 2]);
            bl[0] = *reinterpret_cast<const uint32_t*>(&sMl[n0 * 16 + tig * 2]);
            bl[1] = *reinterpret_cast<const uint32_t*>(&sMl[n0 * 16 + 8 + tig * 2]);
            mma16816(d[mt][ntl], awh, bh);
            mma16816(d[mt][ntl], awh, bl);
            mma16816(d[mt][ntl], awl, bh);
        }
    }

    // ---- write fragments to sMv [v][196] ----
#pragma unroll
    for (int mt = 0; mt < 4; mt++) {
#pragma unroll
        for (int ntl = 0; ntl < 3; ntl++) {
            int row = mt * 16 + gid;
            int col = (wid * 3 + ntl) * 8 + tig * 2;
            *reinterpret_cast<float2*>(&sMv[row * 196 + col]) =
                make_float2(d[mt][ntl][0], d[mt][ntl][1]);
            *reinterpret_cast<float2*>(&sMv[(row + 8) * 196 + col]) =
                make_float2(d[mt][ntl][2], d[mt][ntl][3]);
        }
    }
    __syncthreads();

    // ---- matvec: 4 (v,b) items per thread ----
#pragma unroll
    for (int u = 0; u < 4; u++) {
        int item = tid + 256 * u;
        int bl = item >> 6;            // batch slot 0..15
        int v  = item & 63;            // local vertex
        int vg = v0 + v;
        if (vg >= NVV) continue;
        const float* mv = &sMv[v * 196 + bl * 12];
        float4 m0 = *reinterpret_cast<const float4*>(mv);
        float4 m1 = *reinterpret_cast<const float4*>(mv + 4);
        float4 m2 = *reinterpret_cast<const float4*>(mv + 8);
        int b = b0 + bl;
        const float* vp = &g_V[(size_t)b * CPAD + c0 + v * 3];
        float x = vp[0], y = vp[1], z = vp[2];
        float o0 = fmaf(m0.x, x, fmaf(m0.y, y, fmaf(m0.z, z, m0.w)));
        float o1 = fmaf(m1.x, x, fmaf(m1.y, y, fmaf(m1.z, z, m1.w)));
        float o2 = fmaf(m2.x, x, fmaf(m2.y, y, fmaf(m2.z, z, m2.w)));
        float* op = &outV[(size_t)b * CTOT + c0 + v * 3];
        op[0] = o0; op[1] = o1; op[2] = o2;

        int tp = -1;
        if (vg == 745) tp = 4; else if (vg == 317) tp = 8;
        else if (vg == 444) tp = 12; else if (vg == 556) tp = 16;
        else if (vg == 673) tp = 20;
        if (tp >= 0) {
            outJ[(b * 21 + tp) * 3 + 0] = o0;
            outJ[(b * 21 + tp) * 3 + 1] = o1;
            outJ[(b * 21 + tp) * 3 + 2] = o2;
        }
    }
}

// ---------------------------------------------------------------------------
extern "C" void kernel_launch(void* const* d_in, const int* in_sizes, int n_in,
                              void* d_out, int out_size) {
    const float* grmt  = (const float*)d_in[0];
    const float* frmt  = (const float*)d_in[1];
    const float* shape = (const float*)d_in[2];
    const float* trans = (const float*)d_in[3];
    const float* vt    = (const float*)d_in[4];
    const float* sd    = (const float*)d_in[5];
    const float* jreg  = (const float*)d_in[6];
    const float* pd    = (const float*)d_in[7];
    const float* lbs   = (const float*)d_in[8];

    float* out  = (float*)d_out;
    float* outV = out;
    float* outJ = out + (size_t)BB * CTOT;

    static bool attr_done = false;
    if (!attr_done) {
        cudaFuncSetAttribute(k3_gemm, cudaFuncAttributeMaxDynamicSharedMemorySize,
                             SM_K3);
        cudaFuncSetAttribute(k4_epi, cudaFuncAttributeMaxDynamicSharedMemorySize,
                             SM_K4);
        attr_done = true;
    }

    k0_prep<<<6452, 256>>>(vt, sd, pd, shape, frmt, jreg, lbs);
    k2_joints<<<BB / 4, 256>>>(grmt, frmt, shape, trans, outJ);
    k3_gemm<<<dim3(BB / 128, 13), 512, SM_K3>>>(vt);
    k4_epi<<<dim3(BB / 16, 13), 256, SM_K4>>>(outV, outJ);
}

// round 9
// speedup vs baseline: 1.1712x; 1.0687x over previous
#include <cuda_runtime.h>
#include <cuda_bf16.h>
#include <cstdint>

#define BB    8192
#define NVV   778
#define NJJ   16
#define CTOT  2334
#define CPAD  2496          // 13 * 192
#define GK    192           // padded K (145 feat + pad)
#define NVP   832           // 13 * 64 padded verts

// ---------------- device scratch (static; no runtime alloc) ----------------
__device__ __align__(16) float          g_V[(size_t)BB * CPAD];      // GEMM out + bias
__device__ __align__(16) __nv_bfloat16  g_A[BB * GK];
__device__ __align__(16) __nv_bfloat16  g_B[CPAD * GK];              // B^T [n][k]
__device__ __align__(16) __nv_bfloat16  g_Whi[NVP * 16];             // lbs hi/lo
__device__ __align__(16) __nv_bfloat16  g_Wlo[NVP * 16];
__device__ __align__(16) __nv_bfloat16  g_MH[(size_t)BB * 12 * 16];  // M'' hi [(b*12+m)*16+j]
__device__ __align__(16) __nv_bfloat16  g_ML[(size_t)BB * 12 * 16];  // M'' lo
__device__ __align__(16) float g_J0[NJJ * 3];
__device__ __align__(16) float g_JS[NJJ * 3 * 10];

__constant__ int c_par[16] = {0,0,1,2,0,4,5,0,7,8,0,10,11,0,13,14};
__constant__ int c_inv[16] = {0,5,6,7,9,10,11,17,18,19,13,14,15,1,2,3};

__device__ __forceinline__ void mma16816(float* d, const uint32_t* a,
                                         const uint32_t* b) {
    asm volatile(
        "mma.sync.aligned.m16n8k16.row.col.f32.bf16.bf16.f32 "
        "{%0,%1,%2,%3}, {%4,%5,%6,%7}, {%8,%9}, {%0,%1,%2,%3};"
        : "+f"(d[0]), "+f"(d[1]), "+f"(d[2]), "+f"(d[3])
        : "r"(a[0]), "r"(a[1]), "r"(a[2]), "r"(a[3]), "r"(b[0]), "r"(b[1]));
}

__device__ __forceinline__ uint32_t smem_u32(const void* p) {
    uint32_t a;
    asm("{ .reg .u64 t; cvta.to.shared.u64 t, %1; cvt.u32.u64 %0, t; }"
        : "=r"(a) : "l"(p));
    return a;
}
__device__ __forceinline__ void cpasync16(uint32_t dst, const void* src) {
    asm volatile("cp.async.ca.shared.global [%0], [%1], 16;"
                 :: "r"(dst), "l"(src));
}
#define CP_COMMIT()  asm volatile("cp.async.commit_group;" ::: "memory")
#define CP_WAIT(n)   asm volatile("cp.async.wait_group %0;" :: "n"(n) : "memory")

// ---------------------------------------------------------------------------
// K0: merged prep.  [0,6144): A; [6144,6384): B; [6384,6400): jreg;
//                   [6400,6452): lbs hi/lo split
// ---------------------------------------------------------------------------
__global__ __launch_bounds__(256) void k0_prep(const float* __restrict__ vt,
                                               const float* __restrict__ sd,
                                               const float* __restrict__ pd,
                                               const float* __restrict__ shape,
                                               const float* __restrict__ finger,
                                               const float* __restrict__ jreg,
                                               const float* __restrict__ lbs) {
    __shared__ float red[33 * 256];
    const int blk = blockIdx.x, tid = threadIdx.x;

    if (blk < 6144) {                       // ---- A: feat bf16 [B x 192]
        int idx = blk * 256 + tid;
        int b = idx / GK, k = idx - b * GK;
        float val = 0.f;
        if (k < 10) val = shape[b * 10 + k];
        else if (k < 145) {
            int q = k - 10;
            val = finger[b * 135 + q];
            if (((q % 9) & 3) == 0) val -= 1.0f;
        }
        g_A[idx] = __float2bfloat16_rn(val);
        return;
    }
    if (blk < 6384) {                       // ---- B^T bf16 [n][k]
        int q = blk - 6144;
        int kg = q / 10, nb = q - kg * 10;
        int n = nb * 256 + tid;
        if (n >= CPAD) return;
        unsigned short hs[8];
#pragma unroll
        for (int i = 0; i < 8; i++) {
            int k = kg * 8 + i;
            float val = 0.f;
            if (n < CTOT) {
                if (k < 10)       val = sd[n * 10 + k];
                else if (k < 145) val = pd[(k - 10) * CTOT + n];
            }
            hs[i] = __bfloat16_as_ushort(__float2bfloat16_rn(val));
        }
        uint4 ph;
        ph.x = hs[0] | ((uint32_t)hs[1] << 16);
        ph.y = hs[2] | ((uint32_t)hs[3] << 16);
        ph.z = hs[4] | ((uint32_t)hs[5] << 16);
        ph.w = hs[6] | ((uint32_t)hs[7] << 16);
        *reinterpret_cast<uint4*>(&g_B[n * GK + kg * 8]) = ph;
        return;
    }
    if (blk >= 6400) {                      // ---- lbs hi/lo
        int idx = (blk - 6400) * 256 + tid;
        if (idx >= NVP * 16) return;
        int v = idx >> 4, j = idx & 15;
        float w = (v < NVV) ? lbs[v * 16 + j] : 0.f;
        __nv_bfloat16 hi = __float2bfloat16_rn(w);
        __nv_bfloat16 lo = __float2bfloat16_rn(w - __bfloat162float(hi));
        g_Whi[idx] = hi;
        g_Wlo[idx] = lo;
        return;
    }
    // ---- joint regressor: one block per joint
    const int j = blk - 6384;
    float acc[33];
#pragma unroll
    for (int o = 0; o < 33; o++) acc[o] = 0.f;
    for (int v = tid; v < NVV; v += 256) {
        float w = jreg[j * NVV + v];
#pragma unroll
        for (int k = 0; k < 3; k++) {
            acc[k] += w * vt[v * 3 + k];
#pragma unroll
            for (int l = 0; l < 10; l++)
                acc[3 + k * 10 + l] += w * sd[(v * 3 + k) * 10 + l];
        }
    }
    for (int o = 0; o < 33; o++) red[o * 256 + tid] = acc[o];
    __syncthreads();
    if (tid < 33) {
        float s = 0.f;
        for (int i = 0; i < 256; i++) s += red[tid * 256 + i];
        if (tid < 3) g_J0[j * 3 + tid] = s;
        else {
            int o = tid - 3;
            int k = o / 10, l = o - k * 10;
            g_JS[(j * 3 + k) * 10 + l] = s;
        }
    }
}

// ---------------------------------------------------------------------------
// K2: joint chain — 4 batches per CTA; writes M'' as split-bf16 (b*12+m)x16
// ---------------------------------------------------------------------------
__device__ __forceinline__ void mul4(const float* a, float* d) {
    float t[16];
#pragma unroll
    for (int r = 0; r < 4; r++)
#pragma unroll
        for (int c = 0; c < 4; c++)
            t[r * 4 + c] = a[r * 4 + 0] * d[0 + c] + a[r * 4 + 1] * d[4 + c] +
                           a[r * 4 + 2] * d[8 + c] + a[r * 4 + 3] * d[12 + c];
#pragma unroll
    for (int i = 0; i < 16; i++) d[i] = t[i];
}

__global__ __launch_bounds__(256) void k2_joints(const float* __restrict__ grmt,
                          const float* __restrict__ frmt,
                          const float* __restrict__ shape,
                          const float* __restrict__ trans,
                          float* __restrict__ outJ) {
    __shared__ float sJ[4][16][3];
    __shared__ float sM[4][16][16];
    __shared__ float sF[4][136];
    __shared__ float sg[4][9], st[4][3], ssh[4][10];
    const int tid = threadIdx.x;
    const int bs = tid >> 6;
    const int tl = tid & 63;
    const int b = blockIdx.x * 4 + bs;
    const int b0 = blockIdx.x * 4;

    for (int i = tid; i < 540; i += 256) {
        int s = i / 135, q = i - s * 135;
        sF[s][q] = frmt[(b0 + s) * 135 + q];
    }
    if (tl < 9)  sg[bs][tl]  = grmt[b * 9 + tl];
    if (tl < 3)  st[bs][tl]  = trans[b * 3 + tl];
    if (tl < 10) ssh[bs][tl] = shape[b * 10 + tl];
    __syncthreads();

    if (tl < 48) {
        int j = tl / 3, k = tl - j * 3;
        float a = g_J0[j * 3 + k];
#pragma unroll
        for (int l = 0; l < 10; l++) a += ssh[bs][l] * g_JS[(j * 3 + k) * 10 + l];
        sJ[bs][j][k] = a;
    }
    __syncthreads();

    if (tl < 16) {
        int j = tl;
        float R[9];
        if (j == 0) {
            R[0]=1;R[1]=0;R[2]=0;R[3]=0;R[4]=1;R[5]=0;R[6]=0;R[7]=0;R[8]=1;
        } else {
#pragma unroll
            for (int i = 0; i < 9; i++) R[i] = sF[bs][(j - 1) * 9 + i];
        }
        float t0 = sJ[bs][j][0], t1 = sJ[bs][j][1], t2 = sJ[bs][j][2];
        if (j > 0) {
            int p = c_par[j];
            t0 -= sJ[bs][p][0]; t1 -= sJ[bs][p][1]; t2 -= sJ[bs][p][2];
        }
        float* m = sM[bs][j];
        m[0]=R[0]; m[1]=R[1]; m[2]=R[2];  m[3]=t0;
        m[4]=R[3]; m[5]=R[4]; m[6]=R[5];  m[7]=t1;
        m[8]=R[6]; m[9]=R[7]; m[10]=R[8]; m[11]=t2;
        m[12]=0.f; m[13]=0.f; m[14]=0.f;  m[15]=1.f;
    }
    __syncthreads();

    if (tl < 5) {
        int j = 1 + 3 * tl;
        mul4(sM[bs][0], sM[bs][j]);
        mul4(sM[bs][j], sM[bs][j + 1]);
        mul4(sM[bs][j + 1], sM[bs][j + 2]);
    }
    __syncthreads();

    if (tl < 16) {
        int j = tl;
        const float* m = sM[bs][j];
        float jt0 = m[3], jt1 = m[7], jt2 = m[11];
        float J0 = sJ[bs][j][0], J1 = sJ[bs][j][1], J2 = sJ[bs][j][2];
        float tc0 = jt0 - (m[0] * J0 + m[1] * J1 + m[2]  * J2);
        float tc1 = jt1 - (m[4] * J0 + m[5] * J1 + m[6]  * J2);
        float tc2 = jt2 - (m[8] * J0 + m[9] * J1 + m[10] * J2);
        float row[12];
        int jp = c_inv[j];
#pragma unroll
        for (int r = 0; r < 3; r++) {
            float a = sg[bs][r * 3 + 0], bb = sg[bs][r * 3 + 1], cc = sg[bs][r * 3 + 2];
            row[r * 4 + 0] = a * m[0] + bb * m[4] + cc * m[8];
            row[r * 4 + 1] = a * m[1] + bb * m[5] + cc * m[9];
            row[r * 4 + 2] = a * m[2] + bb * m[6] + cc * m[10];
            row[r * 4 + 3] = a * tc0  + bb * tc1  + cc * tc2 + st[bs][r];
            outJ[(b * 21 + jp) * 3 + r] = a * jt0 + bb * jt1 + cc * jt2 + st[bs][r];
        }
#pragma unroll
        for (int mm = 0; mm < 12; mm++) {
            float x = row[mm];
            __nv_bfloat16 hi = __float2bfloat16_rn(x);
            __nv_bfloat16 lo = __float2bfloat16_rn(x - __bfloat162float(hi));
            size_t off = ((size_t)b * 12 + mm) * 16 + j;
            g_MH[off] = hi;
            g_ML[off] = lo;
        }
    }
}

// ---------------------------------------------------------------------------
// K3: single-bf16 mma.sync GEMM, cp.async 2-stage -> g_V (+fp32 bias)
// ---------------------------------------------------------------------------
#define STG_SZ  46080
#define SM_K3   92160

__global__ __launch_bounds__(512, 1) void k3_gemm(const float* __restrict__ vt) {
    extern __shared__ __align__(16) char smem[];
    __shared__ float sBias[192];
    const uint32_t sbase = smem_u32(smem);
    const int tid = threadIdx.x;
    const int wid = tid >> 5, lane = tid & 31;
    const int wm = wid & 1, wn = wid >> 1;
    const int gid = lane >> 2, tig = lane & 3;
    const int b0 = blockIdx.x * 128;
    const int t  = blockIdx.y;

    if (tid < 192) {
        int c = t * 192 + tid;
        sBias[tid] = (c < CTOT) ? vt[c] : 0.f;
    }

    auto stage_chunk = [&](int s, int ch) {
        const uint32_t stg = sbase + s * STG_SZ;
        for (int i = tid; i < 2560; i += 512) {
            if (i < 1024) {
                int r = i >> 3, q = i & 7;
                cpasync16(stg + r * 144 + q * 16,
                          &g_A[(b0 + r) * GK + ch * 64 + q * 8]);
            } else {
                int i2 = i - 1024;
                int r = i2 >> 3, q = i2 & 7;
                cpasync16(stg + 18432 + r * 144 + q * 16,
                          &g_B[(t * 192 + r) * GK + ch * 64 + q * 8]);
            }
        }
    };

    float d[4][3][4];
#pragma unroll
    for (int mt = 0; mt < 4; mt++)
#pragma unroll
        for (int nt = 0; nt < 3; nt++)
#pragma unroll
            for (int q = 0; q < 4; q++) d[mt][nt][q] = 0.f;

    stage_chunk(0, 0); CP_COMMIT();
    stage_chunk(1, 1); CP_COMMIT();

    auto mma_chunk = [&](int s) {
        const char* stg = smem + s * STG_SZ;
#pragma unroll
        for (int ks = 0; ks < 4; ks++) {
            const int kb = ks * 32 + tig * 4;
            uint32_t ah[4][4];
#pragma unroll
            for (int mt = 0; mt < 4; mt++) {
                int r0 = wm * 64 + mt * 16 + gid;
                const char* ph = stg + r0 * 144 + kb;
                ah[mt][0] = *(const uint32_t*)(ph);
                ah[mt][1] = *(const uint32_t*)(ph + 8 * 144);
                ah[mt][2] = *(const uint32_t*)(ph + 16);
                ah[mt][3] = *(const uint32_t*)(ph + 8 * 144 + 16);
            }
            uint32_t bh[3][2];
#pragma unroll
            for (int nt = 0; nt < 3; nt++) {
                int n0 = wn * 24 + nt * 8 + gid;
                const char* ph = stg + 18432 + n0 * 144 + kb;
                bh[nt][0] = *(const uint32_t*)(ph);
                bh[nt][1] = *(const uint32_t*)(ph + 16);
            }
#pragma unroll
            for (int mt = 0; mt < 4; mt++)
#pragma unroll
                for (int nt = 0; nt < 3; nt++)
                    mma16816(d[mt][nt], ah[mt], bh[nt]);
        }
    };

    CP_WAIT(1); __syncthreads();
    mma_chunk(0);
    __syncthreads();
    stage_chunk(0, 2); CP_COMMIT();
    CP_WAIT(1); __syncthreads();
    mma_chunk(1);
    CP_WAIT(0); __syncthreads();
    mma_chunk(0);

#pragma unroll
    for (int mt = 0; mt < 4; mt++) {
        int r0 = b0 + wm * 64 + mt * 16 + gid;
#pragma unroll
        for (int nt = 0; nt < 3; nt++) {
            int cl = wn * 24 + nt * 8 + tig * 2;
            int c = t * 192 + cl;
            float bx = sBias[cl], by = sBias[cl + 1];
            *reinterpret_cast<float2*>(&g_V[(size_t)r0 * CPAD + c]) =
                make_float2(d[mt][nt][0] + bx, d[mt][nt][1] + by);
            *reinterpret_cast<float2*>(&g_V[(size_t)(r0 + 8) * CPAD + c]) =
                make_float2(d[mt][nt][2] + bx, d[mt][nt][3] + by);
        }
    }
}

// ---------------------------------------------------------------------------
// K4: LBS via tensor-core matrix blend, multi-tile CTAs.
//   CTA: 256 thr, 16 batches x {4|3} vertex tiles. grid (512, 4)
//   smem: sMh@0(6K) sMl@6K  sW double-buffer@12K (2x4K: hi 2K + lo 2K)
//         sMv@20480 (64x196 f = 50176)   total 70656 B -> 3 CTAs/SM
//   M'' staged once per CTA (cp.async); B-fragments hoisted (tile-invariant);
//   W slice (4KB) prefetched per tile via cp.async double buffer.
// ---------------------------------------------------------------------------
#define SM_K4 70656

__global__ __launch_bounds__(256, 3) void k4_epi(float* __restrict__ outV,
                                                 float* __restrict__ outJ) {
    extern __shared__ __align__(16) char smem[];
    const uint32_t sbase = smem_u32(smem);
    __nv_bfloat16* sMh = reinterpret_cast<__nv_bfloat16*>(smem);
    __nv_bfloat16* sMl = reinterpret_cast<__nv_bfloat16*>(smem + 6144);
    float*         sMv = reinterpret_cast<float*>(smem + 20480);

    const int tid = threadIdx.x;
    const int b0 = blockIdx.x * 16;
    const int y  = blockIdx.y;
    const int tstart = (y == 0) ? 0 : 1 + y * 3;      // {0,4,7,10}
    const int tend   = tstart + ((y == 0) ? 4 : 3);   // {4,7,10,13}

    auto stage_W = [&](int s, int t) {
        int split = tid >> 7, i2 = tid & 127;
        int row = i2 >> 1, half = i2 & 1;
        const __nv_bfloat16* src = split ? g_Wlo : g_Whi;
        cpasync16(sbase + 12288 + s * 4096 + split * 2048 +
                      (row * 16 + half * 8) * 2,
                  &src[(t * 64 + row) * 16 + half * 8]);
    };

    // stage M'' (12KB) + first W slice
    for (int i = tid; i < 768; i += 256) {
        int split = i / 384, i2 = i - split * 384;
        int n = i2 >> 1, half = i2 & 1;
        const __nv_bfloat16* src = split ? g_ML : g_MH;
        cpasync16(sbase + split * 6144 + (n * 16 + half * 8) * 2,
                  &src[((size_t)b0 * 12 + n) * 16 + half * 8]);
    }
    stage_W(0, tstart);
    CP_COMMIT();
    CP_WAIT(0);
    __syncthreads();

    const int wid = tid >> 5, lane = tid & 31;
    const int gid = lane >> 2, tig = lane & 3;

    // hoisted B fragments (M'' columns) — tile-invariant
    uint32_t fbh[3][2], fbl[3][2];
#pragma unroll
    for (int ntl = 0; ntl < 3; ntl++) {
        int n0 = (wid * 3 + ntl) * 8 + gid;
        fbh[ntl][0] = *reinterpret_cast<const uint32_t*>(&sMh[n0 * 16 + tig * 2]);
        fbh[ntl][1] = *reinterpret_cast<const uint32_t*>(&sMh[n0 * 16 + 8 + tig * 2]);
        fbl[ntl][0] = *reinterpret_cast<const uint32_t*>(&sMl[n0 * 16 + tig * 2]);
        fbl[ntl][1] = *reinterpret_cast<const uint32_t*>(&sMl[n0 * 16 + 8 + tig * 2]);
    }

    for (int t = tstart; t < tend; t++) {
        const int s = (t - tstart) & 1;
        const __nv_bfloat16* sWh =
            reinterpret_cast<const __nv_bfloat16*>(smem + 12288 + s * 4096);
        const __nv_bfloat16* sWl = sWh + 1024;

        // ---- MMA: one mt slab at a time (low register pressure) ----
#pragma unroll
        for (int mt = 0; mt < 4; mt++) {
            int r0 = mt * 16 + gid;
            uint32_t awh[4], awl[4];
            awh[0] = *reinterpret_cast<const uint32_t*>(&sWh[r0 * 16 + tig * 2]);
            awh[1] = *reinterpret_cast<const uint32_t*>(&sWh[(r0 + 8) * 16 + tig * 2]);
            awh[2] = *reinterpret_cast<const uint32_t*>(&sWh[r0 * 16 + 8 + tig * 2]);
            awh[3] = *reinterpret_cast<const uint32_t*>(&sWh[(r0 + 8) * 16 + 8 + tig * 2]);
            awl[0] = *reinterpret_cast<const uint32_t*>(&sWl[r0 * 16 + tig * 2]);
            awl[1] = *reinterpret_cast<const uint32_t*>(&sWl[(r0 + 8) * 16 + tig * 2]);
            awl[2] = *reinterpret_cast<const uint32_t*>(&sWl[r0 * 16 + 8 + tig * 2]);
            awl[3] = *reinterpret_cast<const uint32_t*>(&sWl[(r0 + 8) * 16 + 8 + tig * 2]);
#pragma unroll
            for (int ntl = 0; ntl < 3; ntl++) {
                float d[4] = {0.f, 0.f, 0.f, 0.f};
                mma16816(d, awh, fbh[ntl]);
                mma16816(d, awh, fbl[ntl]);
                mma16816(d, awl, fbh[ntl]);
                int col = (wid * 3 + ntl) * 8 + tig * 2;
                *reinterpret_cast<float2*>(&sMv[r0 * 196 + col]) =
                    make_float2(d[0], d[1]);
                *reinterpret_cast<float2*>(&sMv[(r0 + 8) * 196 + col]) =
                    make_float2(d[2], d[3]);
            }
        }
        __syncthreads();   // sMv ready

        // prefetch next W slice (overlaps matvec)
        if (t + 1 < tend) { stage_W(s ^ 1, t + 1); CP_COMMIT(); }

        // ---- matvec: 4 (v,b) items per thread ----
        const int c0 = t * 192;
#pragma unroll
        for (int u = 0; u < 4; u++) {
            int item = tid + 256 * u;
            int bq = item >> 6;            // batch slot 0..15
            int v  = item & 63;
            int vg = t * 64 + v;
            if (vg >= NVV) continue;
            const float* mv = &sMv[v * 196 + bq * 12];
            float4 m0 = *reinterpret_cast<const float4*>(mv);
            float4 m1 = *reinterpret_cast<const float4*>(mv + 4);
            float4 m2 = *reinterpret_cast<const float4*>(mv + 8);
            int b = b0 + bq;
            const float* vp = &g_V[(size_t)b * CPAD + c0 + v * 3];
            float x = vp[0], yv = vp[1], z = vp[2];
            float o0 = fmaf(m0.x, x, fmaf(m0.y, yv, fmaf(m0.z, z, m0.w)));
            float o1 = fmaf(m1.x, x, fmaf(m1.y, yv, fmaf(m1.z, z, m1.w)));
            float o2 = fmaf(m2.x, x, fmaf(m2.y, yv, fmaf(m2.z, z, m2.w)));
            float* op = &outV[(size_t)b * CTOT + c0 + v * 3];
            op[0] = o0; op[1] = o1; op[2] = o2;

            int tp = -1;
            if (vg == 745) tp = 4; else if (vg == 317) tp = 8;
            else if (vg == 444) tp = 12; else if (vg == 556) tp = 16;
            else if (vg == 673) tp = 20;
            if (tp >= 0) {
                outJ[(b * 21 + tp) * 3 + 0] = o0;
                outJ[(b * 21 + tp) * 3 + 1] = o1;
                outJ[(b * 21 + tp) * 3 + 2] = o2;
            }
        }

        if (t + 1 < tend) CP_WAIT(0);
        __syncthreads();   // matvec done; next W visible
    }
}

// ---------------------------------------------------------------------------
extern "C" void kernel_launch(void* const* d_in, const int* in_sizes, int n_in,
                              void* d_out, int out_size) {
    const float* grmt  = (const float*)d_in[0];
    const float* frmt  = (const float*)d_in[1];
    const float* shape = (const float*)d_in[2];
    const float* trans = (const float*)d_in[3];
    const float* vt    = (const float*)d_in[4];
    const float* sd    = (const float*)d_in[5];
    const float* jreg  = (const float*)d_in[6];
    const float* pd    = (const float*)d_in[7];
    const float* lbs   = (const float*)d_in[8];

    float* out  = (float*)d_out;
    float* outV = out;
    float* outJ = out + (size_t)BB * CTOT;

    static bool attr_done = false;
    if (!attr_done) {
        cudaFuncSetAttribute(k3_gemm, cudaFuncAttributeMaxDynamicSharedMemorySize,
                             SM_K3);
        cudaFuncSetAttribute(k4_epi, cudaFuncAttributeMaxDynamicSharedMemorySize,
                             SM_K4);
        attr_done = true;
    }

    k0_prep<<<6452, 256>>>(vt, sd, pd, shape, frmt, jreg, lbs);
    k2_joints<<<BB / 4, 256>>>(grmt, frmt, shape, trans, outJ);
    k3_gemm<<<dim3(BB / 128, 13), 512, SM_K3>>>(vt);
    k4_epi<<<dim3(BB / 16, 4), 256, SM_K4>>>(outV, outJ);
}

// round 10
// speedup vs baseline: 1.2682x; 1.0828x over previous
#include <cuda_runtime.h>
#include <cuda_bf16.h>
#include <cstdint>

#define BB    8192
#define NVV   778
#define NJJ   16
#define CTOT  2334
#define CPAD  2496          // 13 * 192
#define GK    192           // padded K (145 feat + pad)
#define NVP   832           // 13 * 64 padded verts

// ---------------- device scratch (static; no runtime alloc) ----------------
__device__ __align__(16) float          g_V[(size_t)BB * CPAD];      // GEMM out + bias
__device__ __align__(16) __nv_bfloat16  g_A[BB * GK];
__device__ __align__(16) __nv_bfloat16  g_B[CPAD * GK];              // B^T [n][k]
__device__ __align__(16) __nv_bfloat16  g_Whi[NVP * 16];             // lbs hi/lo
__device__ __align__(16) __nv_bfloat16  g_Wlo[NVP * 16];
__device__ __align__(16) __nv_bfloat16  g_MH[(size_t)BB * 12 * 16];  // M'' hi [(b*12+m)*16+j]
__device__ __align__(16) __nv_bfloat16  g_ML[(size_t)BB * 12 * 16];  // M'' lo
__device__ __align__(16) float g_J0[NJJ * 3];
__device__ __align__(16) float g_JS[NJJ * 3 * 10];

__constant__ int c_par[16] = {0,0,1,2,0,4,5,0,7,8,0,10,11,0,13,14};
__constant__ int c_inv[16] = {0,5,6,7,9,10,11,17,18,19,13,14,15,1,2,3};

__device__ __forceinline__ void mma16816(float* d, const uint32_t* a,
                                         const uint32_t* b) {
    asm volatile(
        "mma.sync.aligned.m16n8k16.row.col.f32.bf16.bf16.f32 "
        "{%0,%1,%2,%3}, {%4,%5,%6,%7}, {%8,%9}, {%0,%1,%2,%3};"
        : "+f"(d[0]), "+f"(d[1]), "+f"(d[2]), "+f"(d[3])
        : "r"(a[0]), "r"(a[1]), "r"(a[2]), "r"(a[3]), "r"(b[0]), "r"(b[1]));
}

__device__ __forceinline__ uint32_t smem_u32(const void* p) {
    uint32_t a;
    asm("{ .reg .u64 t; cvta.to.shared.u64 t, %1; cvt.u32.u64 %0, t; }"
        : "=r"(a) : "l"(p));
    return a;
}
__device__ __forceinline__ void cpasync16(uint32_t dst, const void* src) {
    asm volatile("cp.async.ca.shared.global [%0], [%1], 16;"
                 :: "r"(dst), "l"(src));
}
#define CP_COMMIT()  asm volatile("cp.async.commit_group;" ::: "memory")
#define CP_WAIT(n)   asm volatile("cp.async.wait_group %0;" :: "n"(n) : "memory")

// ---------------------------------------------------------------------------
// K0: merged prep.  [0,6144): A; [6144,6384): B; [6384,6400): jreg;
//                   [6400,6452): lbs hi/lo split
// ---------------------------------------------------------------------------
__global__ __launch_bounds__(256) void k0_prep(const float* __restrict__ vt,
                                               const float* __restrict__ sd,
                                               const float* __restrict__ pd,
                                               const float* __restrict__ shape,
                                               const float* __restrict__ finger,
                                               const float* __restrict__ jreg,
                                               const float* __restrict__ lbs) {
    __shared__ float red[33 * 256];
    const int blk = blockIdx.x, tid = threadIdx.x;

    if (blk < 6144) {                       // ---- A: feat bf16 [B x 192]
        int idx = blk * 256 + tid;
        int b = idx / GK, k = idx - b * GK;
        float val = 0.f;
        if (k < 10) val = shape[b * 10 + k];
        else if (k < 145) {
            int q = k - 10;
            val = finger[b * 135 + q];
            if (((q % 9) & 3) == 0) val -= 1.0f;
        }
        g_A[idx] = __float2bfloat16_rn(val);
        return;
    }
    if (blk < 6384) {                       // ---- B^T bf16 [n][k]
        int q = blk - 6144;
        int kg = q / 10, nb = q - kg * 10;
        int n = nb * 256 + tid;
        if (n >= CPAD) return;
        unsigned short hs[8];
#pragma unroll
        for (int i = 0; i < 8; i++) {
            int k = kg * 8 + i;
            float val = 0.f;
            if (n < CTOT) {
                if (k < 10)       val = sd[n * 10 + k];
                else if (k < 145) val = pd[(k - 10) * CTOT + n];
            }
            hs[i] = __bfloat16_as_ushort(__float2bfloat16_rn(val));
        }
        uint4 ph;
        ph.x = hs[0] | ((uint32_t)hs[1] << 16);
        ph.y = hs[2] | ((uint32_t)hs[3] << 16);
        ph.z = hs[4] | ((uint32_t)hs[5] << 16);
        ph.w = hs[6] | ((uint32_t)hs[7] << 16);
        *reinterpret_cast<uint4*>(&g_B[n * GK + kg * 8]) = ph;
        return;
    }
    if (blk >= 6400) {                      // ---- lbs hi/lo
        int idx = (blk - 6400) * 256 + tid;
        if (idx >= NVP * 16) return;
        int v = idx >> 4, j = idx & 15;
        float w = (v < NVV) ? lbs[v * 16 + j] : 0.f;
        __nv_bfloat16 hi = __float2bfloat16_rn(w);
        __nv_bfloat16 lo = __float2bfloat16_rn(w - __bfloat162float(hi));
        g_Whi[idx] = hi;
        g_Wlo[idx] = lo;
        return;
    }
    // ---- joint regressor: one block per joint
    const int j = blk - 6384;
    float acc[33];
#pragma unroll
    for (int o = 0; o < 33; o++) acc[o] = 0.f;
    for (int v = tid; v < NVV; v += 256) {
        float w = jreg[j * NVV + v];
#pragma unroll
        for (int k = 0; k < 3; k++) {
            acc[k] += w * vt[v * 3 + k];
#pragma unroll
            for (int l = 0; l < 10; l++)
                acc[3 + k * 10 + l] += w * sd[(v * 3 + k) * 10 + l];
        }
    }
    for (int o = 0; o < 33; o++) red[o * 256 + tid] = acc[o];
    __syncthreads();
    if (tid < 33) {
        float s = 0.f;
        for (int i = 0; i < 256; i++) s += red[tid * 256 + i];
        if (tid < 3) g_J0[j * 3 + tid] = s;
        else {
            int o = tid - 3;
            int k = o / 10, l = o - k * 10;
            g_JS[(j * 3 + k) * 10 + l] = s;
        }
    }
}

// ---------------------------------------------------------------------------
// K2: joint chain — 4 batches per CTA; writes M'' as split-bf16 (b*12+m)x16
// ---------------------------------------------------------------------------
__device__ __forceinline__ void mul4(const float* a, float* d) {
    float t[16];
#pragma unroll
    for (int r = 0; r < 4; r++)
#pragma unroll
        for (int c = 0; c < 4; c++)
            t[r * 4 + c] = a[r * 4 + 0] * d[0 + c] + a[r * 4 + 1] * d[4 + c] +
                           a[r * 4 + 2] * d[8 + c] + a[r * 4 + 3] * d[12 + c];
#pragma unroll
    for (int i = 0; i < 16; i++) d[i] = t[i];
}

__global__ __launch_bounds__(256) void k2_joints(const float* __restrict__ grmt,
                          const float* __restrict__ frmt,
                          const float* __restrict__ shape,
                          const float* __restrict__ trans,
                          float* __restrict__ outJ) {
    __shared__ float sJ[4][16][3];
    __shared__ float sM[4][16][16];
    __shared__ float sF[4][136];
    __shared__ float sg[4][9], st[4][3], ssh[4][10];
    const int tid = threadIdx.x;
    const int bs = tid >> 6;
    const int tl = tid & 63;
    const int b = blockIdx.x * 4 + bs;
    const int b0 = blockIdx.x * 4;

    for (int i = tid; i < 540; i += 256) {
        int s = i / 135, q = i - s * 135;
        sF[s][q] = frmt[(b0 + s) * 135 + q];
    }
    if (tl < 9)  sg[bs][tl]  = grmt[b * 9 + tl];
    if (tl < 3)  st[bs][tl]  = trans[b * 3 + tl];
    if (tl < 10) ssh[bs][tl] = shape[b * 10 + tl];
    __syncthreads();

    if (tl < 48) {
        int j = tl / 3, k = tl - j * 3;
        float a = g_J0[j * 3 + k];
#pragma unroll
        for (int l = 0; l < 10; l++) a += ssh[bs][l] * g_JS[(j * 3 + k) * 10 + l];
        sJ[bs][j][k] = a;
    }
    __syncthreads();

    if (tl < 16) {
        int j = tl;
        float R[9];
        if (j == 0) {
            R[0]=1;R[1]=0;R[2]=0;R[3]=0;R[4]=1;R[5]=0;R[6]=0;R[7]=0;R[8]=1;
        } else {
#pragma unroll
            for (int i = 0; i < 9; i++) R[i] = sF[bs][(j - 1) * 9 + i];
        }
        float t0 = sJ[bs][j][0], t1 = sJ[bs][j][1], t2 = sJ[bs][j][2];
        if (j > 0) {
            int p = c_par[j];
            t0 -= sJ[bs][p][0]; t1 -= sJ[bs][p][1]; t2 -= sJ[bs][p][2];
        }
        float* m = sM[bs][j];
        m[0]=R[0]; m[1]=R[1]; m[2]=R[2];  m[3]=t0;
        m[4]=R[3]; m[5]=R[4]; m[6]=R[5];  m[7]=t1;
        m[8]=R[6]; m[9]=R[7]; m[10]=R[8]; m[11]=t2;
        m[12]=0.f; m[13]=0.f; m[14]=0.f;  m[15]=1.f;
    }
    __syncthreads();

    if (tl < 5) {
        int j = 1 + 3 * tl;
        mul4(sM[bs][0], sM[bs][j]);
        mul4(sM[bs][j], sM[bs][j + 1]);
        mul4(sM[bs][j + 1], sM[bs][j + 2]);
    }
    __syncthreads();

    if (tl < 16) {
        int j = tl;
        const float* m = sM[bs][j];
        float jt0 = m[3], jt1 = m[7], jt2 = m[11];
        float J0 = sJ[bs][j][0], J1 = sJ[bs][j][1], J2 = sJ[bs][j][2];
        float tc0 = jt0 - (m[0] * J0 + m[1] * J1 + m[2]  * J2);
        float tc1 = jt1 - (m[4] * J0 + m[5] * J1 + m[6]  * J2);
        float tc2 = jt2 - (m[8] * J0 + m[9] * J1 + m[10] * J2);
        float row[12];
        int jp = c_inv[j];
#pragma unroll
        for (int r = 0; r < 3; r++) {
            float a = sg[bs][r * 3 + 0], bb = sg[bs][r * 3 + 1], cc = sg[bs][r * 3 + 2];
            row[r * 4 + 0] = a * m[0] + bb * m[4] + cc * m[8];
            row[r * 4 + 1] = a * m[1] + bb * m[5] + cc * m[9];
            row[r * 4 + 2] = a * m[2] + bb * m[6] + cc * m[10];
            row[r * 4 + 3] = a * tc0  + bb * tc1  + cc * tc2 + st[bs][r];
            outJ[(b * 21 + jp) * 3 + r] = a * jt0 + bb * jt1 + cc * jt2 + st[bs][r];
        }
#pragma unroll
        for (int mm = 0; mm < 12; mm++) {
            float x = row[mm];
            __nv_bfloat16 hi = __float2bfloat16_rn(x);
            __nv_bfloat16 lo = __float2bfloat16_rn(x - __bfloat162float(hi));
            size_t off = ((size_t)b * 12 + mm) * 16 + j;
            g_MH[off] = hi;
            g_ML[off] = lo;
        }
    }
}

// ---------------------------------------------------------------------------
// K3: single-bf16 mma.sync GEMM, cp.async 2-stage -> g_V (+fp32 bias)
// ---------------------------------------------------------------------------
#define STG_SZ  46080
#define SM_K3   92160

__global__ __launch_bounds__(512, 1) void k3_gemm(const float* __restrict__ vt) {
    extern __shared__ __align__(16) char smem[];
    __shared__ float sBias[192];
    const uint32_t sbase = smem_u32(smem);
    const int tid = threadIdx.x;
    const int wid = tid >> 5, lane = tid & 31;
    const int wm = wid & 1, wn = wid >> 1;
    const int gid = lane >> 2, tig = lane & 3;
    const int b0 = blockIdx.x * 128;
    const int t  = blockIdx.y;

    if (tid < 192) {
        int c = t * 192 + tid;
        sBias[tid] = (c < CTOT) ? vt[c] : 0.f;
    }

    auto stage_chunk = [&](int s, int ch) {
        const uint32_t stg = sbase + s * STG_SZ;
        for (int i = tid; i < 2560; i += 512) {
            if (i < 1024) {
                int r = i >> 3, q = i & 7;
                cpasync16(stg + r * 144 + q * 16,
                          &g_A[(b0 + r) * GK + ch * 64 + q * 8]);
            } else {
                int i2 = i - 1024;
                int r = i2 >> 3, q = i2 & 7;
                cpasync16(stg + 18432 + r * 144 + q * 16,
                          &g_B[(t * 192 + r) * GK + ch * 64 + q * 8]);
            }
        }
    };

    float d[4][3][4];
#pragma unroll
    for (int mt = 0; mt < 4; mt++)
#pragma unroll
        for (int nt = 0; nt < 3; nt++)
#pragma unroll
            for (int q = 0; q < 4; q++) d[mt][nt][q] = 0.f;

    stage_chunk(0, 0); CP_COMMIT();
    stage_chunk(1, 1); CP_COMMIT();

    auto mma_chunk = [&](int s) {
        const char* stg = smem + s * STG_SZ;
#pragma unroll
        for (int ks = 0; ks < 4; ks++) {
            const int kb = ks * 32 + tig * 4;
            uint32_t ah[4][4];
#pragma unroll
            for (int mt = 0; mt < 4; mt++) {
                int r0 = wm * 64 + mt * 16 + gid;
                const char* ph = stg + r0 * 144 + kb;
                ah[mt][0] = *(const uint32_t*)(ph);
                ah[mt][1] = *(const uint32_t*)(ph + 8 * 144);
                ah[mt][2] = *(const uint32_t*)(ph + 16);
                ah[mt][3] = *(const uint32_t*)(ph + 8 * 144 + 16);
            }
            uint32_t bh[3][2];
#pragma unroll
            for (int nt = 0; nt < 3; nt++) {
                int n0 = wn * 24 + nt * 8 + gid;
                const char* ph = stg + 18432 + n0 * 144 + kb;
                bh[nt][0] = *(const uint32_t*)(ph);
                bh[nt][1] = *(const uint32_t*)(ph + 16);
            }
#pragma unroll
            for (int mt = 0; mt < 4; mt++)
#pragma unroll
                for (int nt = 0; nt < 3; nt++)
                    mma16816(d[mt][nt], ah[mt], bh[nt]);
        }
    };

    CP_WAIT(1); __syncthreads();
    mma_chunk(0);
    __syncthreads();
    stage_chunk(0, 2); CP_COMMIT();
    CP_WAIT(1); __syncthreads();
    mma_chunk(1);
    CP_WAIT(0); __syncthreads();
    mma_chunk(0);

#pragma unroll
    for (int mt = 0; mt < 4; mt++) {
        int r0 = b0 + wm * 64 + mt * 16 + gid;
#pragma unroll
        for (int nt = 0; nt < 3; nt++) {
            int cl = wn * 24 + nt * 8 + tig * 2;
            int c = t * 192 + cl;
            float bx = sBias[cl], by = sBias[cl + 1];
            *reinterpret_cast<float2*>(&g_V[(size_t)r0 * CPAD + c]) =
                make_float2(d[mt][nt][0] + bx, d[mt][nt][1] + by);
            *reinterpret_cast<float2*>(&g_V[(size_t)(r0 + 8) * CPAD + c]) =
                make_float2(d[mt][nt][2] + bx, d[mt][nt][3] + by);
        }
    }
}

// ---------------------------------------------------------------------------
// K4: LBS via tensor-core matrix blend, multi-tile CTAs, V prefetch.
//   CTA: 256 thr, 16 batches x {4|3} vertex tiles. grid (512, 4)
//   smem: sMh@0(6K) sMl@6K | sW dbuf@12288 (2x4K) | sV dbuf@20480 (2x12K)
//         sMv@45056 (32x196 f = 25088)   total 70144 B -> 3 CTAs/SM
//   Per tile: MMA slabs 0-1 -> matvec v0..31 -> MMA slabs 2-3 -> matvec v32..63
//   W+V of tile t+1 prefetched via cp.async right after first MMA phase.
// ---------------------------------------------------------------------------
#define SM_K4 70144

__global__ __launch_bounds__(256, 3) void k4_epi(float* __restrict__ outV,
                                                 float* __restrict__ outJ) {
    extern __shared__ __align__(16) char smem[];
    const uint32_t sbase = smem_u32(smem);
    __nv_bfloat16* sMh = reinterpret_cast<__nv_bfloat16*>(smem);
    __nv_bfloat16* sMl = reinterpret_cast<__nv_bfloat16*>(smem + 6144);
    float*         sMv = reinterpret_cast<float*>(smem + 45056);

    const int tid = threadIdx.x;
    const int b0 = blockIdx.x * 16;
    const int y  = blockIdx.y;
    const int tstart = (y == 0) ? 0 : 1 + y * 3;      // {0,4,7,10}
    const int tend   = tstart + ((y == 0) ? 4 : 3);   // {4,7,10,13}

    auto stage_W = [&](int s, int t) {
        int split = tid >> 7, i2 = tid & 127;
        int row = i2 >> 1, half = i2 & 1;
        const __nv_bfloat16* src = split ? g_Wlo : g_Whi;
        cpasync16(sbase + 12288 + s * 4096 + split * 2048 +
                      (row * 16 + half * 8) * 2,
                  &src[(t * 64 + row) * 16 + half * 8]);
    };
    auto stage_V = [&](int s, int t) {
        for (int i = tid; i < 768; i += 256) {
            int r = i / 48, q = i - r * 48;
            cpasync16(sbase + 20480 + s * 12288 + (r * 192 + q * 4) * 4,
                      &g_V[(size_t)(b0 + r) * CPAD + t * 192 + q * 4]);
        }
    };

    // stage M'' (12KB) + first W and V slices
    for (int i = tid; i < 768; i += 256) {
        int split = i / 384, i2 = i - split * 384;
        int n = i2 >> 1, half = i2 & 1;
        const __nv_bfloat16* src = split ? g_ML : g_MH;
        cpasync16(sbase + split * 6144 + (n * 16 + half * 8) * 2,
                  &src[((size_t)b0 * 12 + n) * 16 + half * 8]);
    }
    stage_W(0, tstart);
    stage_V(0, tstart);
    CP_COMMIT();
    CP_WAIT(0);
    __syncthreads();

    const int wid = tid >> 5, lane = tid & 31;
    const int gid = lane >> 2, tig = lane & 3;

    // hoisted B fragments (M'' columns) — tile-invariant
    uint32_t fbh[3][2], fbl[3][2];
#pragma unroll
    for (int ntl = 0; ntl < 3; ntl++) {
        int n0 = (wid * 3 + ntl) * 8 + gid;
        fbh[ntl][0] = *reinterpret_cast<const uint32_t*>(&sMh[n0 * 16 + tig * 2]);
        fbh[ntl][1] = *reinterpret_cast<const uint32_t*>(&sMh[n0 * 16 + 8 + tig * 2]);
        fbl[ntl][0] = *reinterpret_cast<const uint32_t*>(&sMl[n0 * 16 + tig * 2]);
        fbl[ntl][1] = *reinterpret_cast<const uint32_t*>(&sMl[n0 * 16 + 8 + tig * 2]);
    }

    for (int t = tstart; t < tend; t++) {
        const int s = (t - tstart) & 1;
        const __nv_bfloat16* sWh =
            reinterpret_cast<const __nv_bfloat16*>(smem + 12288 + s * 4096);
        const __nv_bfloat16* sWl = sWh + 1024;
        const float* sVf =
            reinterpret_cast<const float*>(smem + 20480 + s * 12288);
        const int c0 = t * 192;

        // ---- MMA half-slab + matvec half, twice ----
#pragma unroll
        for (int ph = 0; ph < 2; ph++) {
            // MMA slabs {2*ph, 2*ph+1} -> sMv rows 0..31
#pragma unroll
            for (int ms = 0; ms < 2; ms++) {
                int mt = ph * 2 + ms;
                int r0 = mt * 16 + gid;
                uint32_t awh[4], awl[4];
                awh[0] = *reinterpret_cast<const uint32_t*>(&sWh[r0 * 16 + tig * 2]);
                awh[1] = *reinterpret_cast<const uint32_t*>(&sWh[(r0 + 8) * 16 + tig * 2]);
                awh[2] = *reinterpret_cast<const uint32_t*>(&sWh[r0 * 16 + 8 + tig * 2]);
                awh[3] = *reinterpret_cast<const uint32_t*>(&sWh[(r0 + 8) * 16 + 8 + tig * 2]);
                awl[0] = *reinterpret_cast<const uint32_t*>(&sWl[r0 * 16 + tig * 2]);
                awl[1] = *reinterpret_cast<const uint32_t*>(&sWl[(r0 + 8) * 16 + tig * 2]);
                awl[2] = *reinterpret_cast<const uint32_t*>(&sWl[r0 * 16 + 8 + tig * 2]);
                awl[3] = *reinterpret_cast<const uint32_t*>(&sWl[(r0 + 8) * 16 + 8 + tig * 2]);
#pragma unroll
                for (int ntl = 0; ntl < 3; ntl++) {
                    float d[4] = {0.f, 0.f, 0.f, 0.f};
                    mma16816(d, awh, fbh[ntl]);
                    mma16816(d, awh, fbl[ntl]);
                    mma16816(d, awl, fbh[ntl]);
                    int col = (wid * 3 + ntl) * 8 + tig * 2;
                    int rloc = ms * 16 + gid;
                    *reinterpret_cast<float2*>(&sMv[rloc * 196 + col]) =
                        make_float2(d[0], d[1]);
                    *reinterpret_cast<float2*>(&sMv[(rloc + 8) * 196 + col]) =
                        make_float2(d[2], d[3]);
                }
            }
            __syncthreads();   // sMv ready

            // prefetch next tile's W+V (once, after first MMA phase)
            if (ph == 0 && t + 1 < tend) {
                stage_W(s ^ 1, t + 1);
                stage_V(s ^ 1, t + 1);
                CP_COMMIT();
            }

            // matvec: verts [ph*32, ph*32+32), 16 batches = 512 items
#pragma unroll
            for (int u = 0; u < 2; u++) {
                int item = tid + 256 * u;
                int bq = item >> 5;            // batch slot 0..15
                int vl = item & 31;            // local vertex within half
                int v  = ph * 32 + vl;
                int vg = t * 64 + v;
                if (vg >= NVV) continue;
                const float* mv = &sMv[vl * 196 + bq * 12];
                float4 m0 = *reinterpret_cast<const float4*>(mv);
                float4 m1 = *reinterpret_cast<const float4*>(mv + 4);
                float4 m2 = *reinterpret_cast<const float4*>(mv + 8);
                int b = b0 + bq;
                const float* vp = &sVf[bq * 192 + v * 3];
                float x = vp[0], yv = vp[1], z = vp[2];
                float o0 = fmaf(m0.x, x, fmaf(m0.y, yv, fmaf(m0.z, z, m0.w)));
                float o1 = fmaf(m1.x, x, fmaf(m1.y, yv, fmaf(m1.z, z, m1.w)));
                float o2 = fmaf(m2.x, x, fmaf(m2.y, yv, fmaf(m2.z, z, m2.w)));
                float* op = &outV[(size_t)b * CTOT + c0 + v * 3];
                op[0] = o0; op[1] = o1; op[2] = o2;

                int tp = -1;
                if (vg == 745) tp = 4; else if (vg == 317) tp = 8;
                else if (vg == 444) tp = 12; else if (vg == 556) tp = 16;
                else if (vg == 673) tp = 20;
                if (tp >= 0) {
                    outJ[(b * 21 + tp) * 3 + 0] = o0;
                    outJ[(b * 21 + tp) * 3 + 1] = o1;
                    outJ[(b * 21 + tp) * 3 + 2] = o2;
                }
            }
            __syncthreads();   // matvec done; sMv free for next phase
        }

        if (t + 1 < tend) { CP_WAIT(0); __syncthreads(); }
    }
}

// ---------------------------------------------------------------------------
extern "C" void kernel_launch(void* const* d_in, const int* in_sizes, int n_in,
                              void* d_out, int out_size) {
    const float* grmt  = (const float*)d_in[0];
    const float* frmt  = (const float*)d_in[1];
    const float* shape = (const float*)d_in[2];
    const float* trans = (const float*)d_in[3];
    const float* vt    = (const float*)d_in[4];
    const float* sd    = (const float*)d_in[5];
    const float* jreg  = (const float*)d_in[6];
    const float* pd    = (const float*)d_in[7];
    const float* lbs   = (const float*)d_in[8];

    float* out  = (float*)d_out;
    float* outV = out;
    float* outJ = out + (size_t)BB * CTOT;

    static bool attr_done = false;
    if (!attr_done) {
        cudaFuncSetAttribute(k3_gemm, cudaFuncAttributeMaxDynamicSharedMemorySize,
                             SM_K3);
        cudaFuncSetAttribute(k4_epi, cudaFuncAttributeMaxDynamicSharedMemorySize,
                             SM_K4);
        attr_done = true;
    }

    k0_prep<<<6452, 256>>>(vt, sd, pd, shape, frmt, jreg, lbs);
    k2_joints<<<BB / 4, 256>>>(grmt, frmt, shape, trans, outJ);
    k3_gemm<<<dim3(BB / 128, 13), 512, SM_K3>>>(vt);
    k4_epi<<<dim3(BB / 16, 4), 256, SM_K4>>>(outV, outJ);
}

// round 11
// speedup vs baseline: 1.3220x; 1.0425x over previous
#include <cuda_runtime.h>
#include <cuda_bf16.h>
#include <cstdint>

#define BB    8192
#define NVV   778
#define NJJ   16
#define CTOT  2334
#define CPAD  2496          // 13 * 192
#define GK    192           // padded K (145 feat + pad)
#define NVP   832           // 13 * 64 padded verts

// ---------------- device scratch (static; no runtime alloc) ----------------
__device__ __align__(16) float          g_V[(size_t)BB * CPAD];      // GEMM out + bias
__device__ __align__(16) __nv_bfloat16  g_A[BB * GK];
__device__ __align__(16) __nv_bfloat16  g_B[CPAD * GK];              // B^T [n][k]
__device__ __align__(16) __nv_bfloat16  g_Whi[NVP * 16];             // lbs hi/lo
__device__ __align__(16) __nv_bfloat16  g_Wlo[NVP * 16];
__device__ __align__(16) __nv_bfloat16  g_MH[(size_t)BB * 12 * 16];  // M'' hi [(b*12+m)*16+j]
__device__ __align__(16) __nv_bfloat16  g_ML[(size_t)BB * 12 * 16];  // M'' lo
__device__ __align__(16) float g_J0[NJJ * 3];
__device__ __align__(16) float g_JS[NJJ * 3 * 10];

__constant__ int c_par[16] = {0,0,1,2,0,4,5,0,7,8,0,10,11,0,13,14};
__constant__ int c_inv[16] = {0,5,6,7,9,10,11,17,18,19,13,14,15,1,2,3};

__device__ __forceinline__ void mma16816(float* d, const uint32_t* a,
                                         const uint32_t* b) {
    asm volatile(
        "mma.sync.aligned.m16n8k16.row.col.f32.bf16.bf16.f32 "
        "{%0,%1,%2,%3}, {%4,%5,%6,%7}, {%8,%9}, {%0,%1,%2,%3};"
        : "+f"(d[0]), "+f"(d[1]), "+f"(d[2]), "+f"(d[3])
        : "r"(a[0]), "r"(a[1]), "r"(a[2]), "r"(a[3]), "r"(b[0]), "r"(b[1]));
}

__device__ __forceinline__ uint32_t smem_u32(const void* p) {
    uint32_t a;
    asm("{ .reg .u64 t; cvta.to.shared.u64 t, %1; cvt.u32.u64 %0, t; }"
        : "=r"(a) : "l"(p));
    return a;
}
// L1-bypassing 16B async copy (fills smem from L2 directly)
__device__ __forceinline__ void cpasync16(uint32_t dst, const void* src) {
    asm volatile("cp.async.cg.shared.global [%0], [%1], 16;"
                 :: "r"(dst), "l"(src));
}
#define CP_COMMIT()  asm volatile("cp.async.commit_group;" ::: "memory")
#define CP_WAIT(n)   asm volatile("cp.async.wait_group %0;" :: "n"(n) : "memory")

// ---------------------------------------------------------------------------
// K0: merged prep.  [0,6144): A; [6144,6384): B; [6384,6400): jreg;
//                   [6400,6452): lbs hi/lo split
// ---------------------------------------------------------------------------
__global__ __launch_bounds__(256) void k0_prep(const float* __restrict__ vt,
                                               const float* __restrict__ sd,
                                               const float* __restrict__ pd,
                                               const float* __restrict__ shape,
                                               const float* __restrict__ finger,
                                               const float* __restrict__ jreg,
                                               const float* __restrict__ lbs) {
    __shared__ float red[33 * 256];
    const int blk = blockIdx.x, tid = threadIdx.x;

    if (blk < 6144) {                       // ---- A: feat bf16 [B x 192]
        int idx = blk * 256 + tid;
        int b = idx / GK, k = idx - b * GK;
        float val = 0.f;
        if (k < 10) val = shape[b * 10 + k];
        else if (k < 145) {
            int q = k - 10;
            val = finger[b * 135 + q];
            if (((q % 9) & 3) == 0) val -= 1.0f;
        }
        g_A[idx] = __float2bfloat16_rn(val);
        return;
    }
    if (blk < 6384) {                       // ---- B^T bf16 [n][k]
        int q = blk - 6144;
        int kg = q / 10, nb = q - kg * 10;
        int n = nb * 256 + tid;
        if (n >= CPAD) return;
        unsigned short hs[8];
#pragma unroll
        for (int i = 0; i < 8; i++) {
            int k = kg * 8 + i;
            float val = 0.f;
            if (n < CTOT) {
                if (k < 10)       val = sd[n * 10 + k];
                else if (k < 145) val = pd[(k - 10) * CTOT + n];
            }
            hs[i] = __bfloat16_as_ushort(__float2bfloat16_rn(val));
        }
        uint4 ph;
        ph.x = hs[0] | ((uint32_t)hs[1] << 16);
        ph.y = hs[2] | ((uint32_t)hs[3] << 16);
        ph.z = hs[4] | ((uint32_t)hs[5] << 16);
        ph.w = hs[6] | ((uint32_t)hs[7] << 16);
        *reinterpret_cast<uint4*>(&g_B[n * GK + kg * 8]) = ph;
        return;
    }
    if (blk >= 6400) {                      // ---- lbs hi/lo
        int idx = (blk - 6400) * 256 + tid;
        if (idx >= NVP * 16) return;
        int v = idx >> 4, j = idx & 15;
        float w = (v < NVV) ? lbs[v * 16 + j] : 0.f;
        __nv_bfloat16 hi = __float2bfloat16_rn(w);
        __nv_bfloat16 lo = __float2bfloat16_rn(w - __bfloat162float(hi));
        g_Whi[idx] = hi;
        g_Wlo[idx] = lo;
        return;
    }
    // ---- joint regressor: one block per joint
    const int j = blk - 6384;
    float acc[33];
#pragma unroll
    for (int o = 0; o < 33; o++) acc[o] = 0.f;
    for (int v = tid; v < NVV; v += 256) {
        float w = jreg[j * NVV + v];
#pragma unroll
        for (int k = 0; k < 3; k++) {
            acc[k] += w * vt[v * 3 + k];
#pragma unroll
            for (int l = 0; l < 10; l++)
                acc[3 + k * 10 + l] += w * sd[(v * 3 + k) * 10 + l];
        }
    }
    for (int o = 0; o < 33; o++) red[o * 256 + tid] = acc[o];
    __syncthreads();
    if (tid < 33) {
        float s = 0.f;
        for (int i = 0; i < 256; i++) s += red[tid * 256 + i];
        if (tid < 3) g_J0[j * 3 + tid] = s;
        else {
            int o = tid - 3;
            int k = o / 10, l = o - k * 10;
            g_JS[(j * 3 + k) * 10 + l] = s;
        }
    }
}

// ---------------------------------------------------------------------------
// K2: joint chain — 4 batches per CTA; writes M'' as split-bf16 (b*12+m)x16
// ---------------------------------------------------------------------------
__device__ __forceinline__ void mul4(const float* a, float* d) {
    float t[16];
#pragma unroll
    for (int r = 0; r < 4; r++)
#pragma unroll
        for (int c = 0; c < 4; c++)
            t[r * 4 + c] = a[r * 4 + 0] * d[0 + c] + a[r * 4 + 1] * d[4 + c] +
                           a[r * 4 + 2] * d[8 + c] + a[r * 4 + 3] * d[12 + c];
#pragma unroll
    for (int i = 0; i < 16; i++) d[i] = t[i];
}

__global__ __launch_bounds__(256) void k2_joints(const float* __restrict__ grmt,
                          const float* __restrict__ frmt,
                          const float* __restrict__ shape,
                          const float* __restrict__ trans,
                          float* __restrict__ outJ) {
    __shared__ float sJ[4][16][3];
    __shared__ float sM[4][16][16];
    __shared__ float sF[4][136];
    __shared__ float sg[4][9], st[4][3], ssh[4][10];
    const int tid = threadIdx.x;
    const int bs = tid >> 6;
    const int tl = tid & 63;
    const int b = blockIdx.x * 4 + bs;
    const int b0 = blockIdx.x * 4;

    for (int i = tid; i < 540; i += 256) {
        int s = i / 135, q = i - s * 135;
        sF[s][q] = frmt[(b0 + s) * 135 + q];
    }
    if (tl < 9)  sg[bs][tl]  = grmt[b * 9 + tl];
    if (tl < 3)  st[bs][tl]  = trans[b * 3 + tl];
    if (tl < 10) ssh[bs][tl] = shape[b * 10 + tl];
    __syncthreads();

    if (tl < 48) {
        int j = tl / 3, k = tl - j * 3;
        float a = g_J0[j * 3 + k];
#pragma unroll
        for (int l = 0; l < 10; l++) a += ssh[bs][l] * g_JS[(j * 3 + k) * 10 + l];
        sJ[bs][j][k] = a;
    }
    __syncthreads();

    if (tl < 16) {
        int j = tl;
        float R[9];
        if (j == 0) {
            R[0]=1;R[1]=0;R[2]=0;R[3]=0;R[4]=1;R[5]=0;R[6]=0;R[7]=0;R[8]=1;
        } else {
#pragma unroll
            for (int i = 0; i < 9; i++) R[i] = sF[bs][(j - 1) * 9 + i];
        }
        float t0 = sJ[bs][j][0], t1 = sJ[bs][j][1], t2 = sJ[bs][j][2];
        if (j > 0) {
            int p = c_par[j];
            t0 -= sJ[bs][p][0]; t1 -= sJ[bs][p][1]; t2 -= sJ[bs][p][2];
        }
        float* m = sM[bs][j];
        m[0]=R[0]; m[1]=R[1]; m[2]=R[2];  m[3]=t0;
        m[4]=R[3]; m[5]=R[4]; m[6]=R[5];  m[7]=t1;
        m[8]=R[6]; m[9]=R[7]; m[10]=R[8]; m[11]=t2;
        m[12]=0.f; m[13]=0.f; m[14]=0.f;  m[15]=1.f;
    }
    __syncthreads();

    if (tl < 5) {
        int j = 1 + 3 * tl;
        mul4(sM[bs][0], sM[bs][j]);
        mul4(sM[bs][j], sM[bs][j + 1]);
        mul4(sM[bs][j + 1], sM[bs][j + 2]);
    }
    __syncthreads();

    if (tl < 16) {
        int j = tl;
        const float* m = sM[bs][j];
        float jt0 = m[3], jt1 = m[7], jt2 = m[11];
        float J0 = sJ[bs][j][0], J1 = sJ[bs][j][1], J2 = sJ[bs][j][2];
        float tc0 = jt0 - (m[0] * J0 + m[1] * J1 + m[2]  * J2);
        float tc1 = jt1 - (m[4] * J0 + m[5] * J1 + m[6]  * J2);
        float tc2 = jt2 - (m[8] * J0 + m[9] * J1 + m[10] * J2);
        float row[12];
        int jp = c_inv[j];
#pragma unroll
        for (int r = 0; r < 3; r++) {
            float a = sg[bs][r * 3 + 0], bb = sg[bs][r * 3 + 1], cc = sg[bs][r * 3 + 2];
            row[r * 4 + 0] = a * m[0] + bb * m[4] + cc * m[8];
            row[r * 4 + 1] = a * m[1] + bb * m[5] + cc * m[9];
            row[r * 4 + 2] = a * m[2] + bb * m[6] + cc * m[10];
            row[r * 4 + 3] = a * tc0  + bb * tc1  + cc * tc2 + st[bs][r];
            outJ[(b * 21 + jp) * 3 + r] = a * jt0 + bb * jt1 + cc * jt2 + st[bs][r];
        }
#pragma unroll
        for (int mm = 0; mm < 12; mm++) {
            float x = row[mm];
            __nv_bfloat16 hi = __float2bfloat16_rn(x);
            __nv_bfloat16 lo = __float2bfloat16_rn(x - __bfloat162float(hi));
            size_t off = ((size_t)b * 12 + mm) * 16 + j;
            g_MH[off] = hi;
            g_ML[off] = lo;
        }
    }
}

// ---------------------------------------------------------------------------
// K3: single-bf16 mma.sync GEMM, cp.async 2-stage -> g_V (+fp32 bias)
//   CTA: 256 thr, tile 64(b) x 192(n), K=192 in 3 chunks. 2 CTAs/SM.
//   Stage: A 64x144B @0, B 192x144B @9216; stage 36864, x2 = 73728
// ---------------------------------------------------------------------------
#define STG_SZ  36864
#define SM_K3   73728

__global__ __launch_bounds__(256, 2) void k3_gemm(const float* __restrict__ vt) {
    extern __shared__ __align__(16) char smem[];
    __shared__ float sBias[192];
    const uint32_t sbase = smem_u32(smem);
    const int tid = threadIdx.x;
    const int wid = tid >> 5, lane = tid & 31;
    const int wm = wid & 1, wn = wid >> 1;      // 2 m-warps x 4 n-warps
    const int gid = lane >> 2, tig = lane & 3;
    const int b0 = blockIdx.x * 64;
    const int t  = blockIdx.y;

    if (tid < 192) {
        int c = t * 192 + tid;
        sBias[tid] = (c < CTOT) ? vt[c] : 0.f;
    }

    auto stage_chunk = [&](int s, int ch) {
        const uint32_t stg = sbase + s * STG_SZ;
        for (int i = tid; i < 2048; i += 256) {
            if (i < 512) {
                int r = i >> 3, q = i & 7;
                cpasync16(stg + r * 144 + q * 16,
                          &g_A[(b0 + r) * GK + ch * 64 + q * 8]);
            } else {
                int i2 = i - 512;
                int r = i2 >> 3, q = i2 & 7;
                cpasync16(stg + 9216 + r * 144 + q * 16,
                          &g_B[(t * 192 + r) * GK + ch * 64 + q * 8]);
            }
        }
    };

    float d[2][6][4];
#pragma unroll
    for (int mt = 0; mt < 2; mt++)
#pragma unroll
        for (int nt = 0; nt < 6; nt++)
#pragma unroll
            for (int q = 0; q < 4; q++) d[mt][nt][q] = 0.f;

    stage_chunk(0, 0); CP_COMMIT();
    stage_chunk(1, 1); CP_COMMIT();

    auto mma_chunk = [&](int s) {
        const char* stg = smem + s * STG_SZ;
#pragma unroll
        for (int ks = 0; ks < 4; ks++) {
            const int kb = ks * 32 + tig * 4;
            uint32_t ah[2][4];
#pragma unroll
            for (int mt = 0; mt < 2; mt++) {
                int r0 = wm * 32 + mt * 16 + gid;
                const char* ph = stg + r0 * 144 + kb;
                ah[mt][0] = *(const uint32_t*)(ph);
                ah[mt][1] = *(const uint32_t*)(ph + 8 * 144);
                ah[mt][2] = *(const uint32_t*)(ph + 16);
                ah[mt][3] = *(const uint32_t*)(ph + 8 * 144 + 16);
            }
            uint32_t bh[6][2];
#pragma unroll
            for (int nt = 0; nt < 6; nt++) {
                int n0 = wn * 48 + nt * 8 + gid;
                const char* ph = stg + 9216 + n0 * 144 + kb;
                bh[nt][0] = *(const uint32_t*)(ph);
                bh[nt][1] = *(const uint32_t*)(ph + 16);
            }
#pragma unroll
            for (int mt = 0; mt < 2; mt++)
#pragma unroll
                for (int nt = 0; nt < 6; nt++)
                    mma16816(d[mt][nt], ah[mt], bh[nt]);
        }
    };

    CP_WAIT(1); __syncthreads();
    mma_chunk(0);
    __syncthreads();
    stage_chunk(0, 2); CP_COMMIT();
    CP_WAIT(1); __syncthreads();
    mma_chunk(1);
    CP_WAIT(0); __syncthreads();
    mma_chunk(0);

#pragma unroll
    for (int mt = 0; mt < 2; mt++) {
        int r0 = b0 + wm * 32 + mt * 16 + gid;
#pragma unroll
        for (int nt = 0; nt < 6; nt++) {
            int cl = wn * 48 + nt * 8 + tig * 2;
            int c = t * 192 + cl;
            float bx = sBias[cl], by = sBias[cl + 1];
            *reinterpret_cast<float2*>(&g_V[(size_t)r0 * CPAD + c]) =
                make_float2(d[mt][nt][0] + bx, d[mt][nt][1] + by);
            *reinterpret_cast<float2*>(&g_V[(size_t)(r0 + 8) * CPAD + c]) =
                make_float2(d[mt][nt][2] + bx, d[mt][nt][3] + by);
        }
    }
}

// ---------------------------------------------------------------------------
// K4: LBS via tensor-core matrix blend, multi-tile CTAs, V prefetch.
//   (structure identical to R10; staging now bypasses L1 via cp.async.cg)
// ---------------------------------------------------------------------------
#define SM_K4 70144

__global__ __launch_bounds__(256, 3) void k4_epi(float* __restrict__ outV,
                                                 float* __restrict__ outJ) {
    extern __shared__ __align__(16) char smem[];
    const uint32_t sbase = smem_u32(smem);
    __nv_bfloat16* sMh = reinterpret_cast<__nv_bfloat16*>(smem);
    __nv_bfloat16* sMl = reinterpret_cast<__nv_bfloat16*>(smem + 6144);
    float*         sMv = reinterpret_cast<float*>(smem + 45056);

    const int tid = threadIdx.x;
    const int b0 = blockIdx.x * 16;
    const int y  = blockIdx.y;
    const int tstart = (y == 0) ? 0 : 1 + y * 3;      // {0,4,7,10}
    const int tend   = tstart + ((y == 0) ? 4 : 3);   // {4,7,10,13}

    auto stage_W = [&](int s, int t) {
        int split = tid >> 7, i2 = tid & 127;
        int row = i2 >> 1, half = i2 & 1;
        const __nv_bfloat16* src = split ? g_Wlo : g_Whi;
        cpasync16(sbase + 12288 + s * 4096 + split * 2048 +
                      (row * 16 + half * 8) * 2,
                  &src[(t * 64 + row) * 16 + half * 8]);
    };
    auto stage_V = [&](int s, int t) {
        for (int i = tid; i < 768; i += 256) {
            int r = i / 48, q = i - r * 48;
            cpasync16(sbase + 20480 + s * 12288 + (r * 192 + q * 4) * 4,
                      &g_V[(size_t)(b0 + r) * CPAD + t * 192 + q * 4]);
        }
    };

    // stage M'' (12KB) + first W and V slices
    for (int i = tid; i < 768; i += 256) {
        int split = i / 384, i2 = i - split * 384;
        int n = i2 >> 1, half = i2 & 1;
        const __nv_bfloat16* src = split ? g_ML : g_MH;
        cpasync16(sbase + split * 6144 + (n * 16 + half * 8) * 2,
                  &src[((size_t)b0 * 12 + n) * 16 + half * 8]);
    }
    stage_W(0, tstart);
    stage_V(0, tstart);
    CP_COMMIT();
    CP_WAIT(0);
    __syncthreads();

    const int wid = tid >> 5, lane = tid & 31;
    const int gid = lane >> 2, tig = lane & 3;

    // hoisted B fragments (M'' columns) — tile-invariant
    uint32_t fbh[3][2], fbl[3][2];
#pragma unroll
    for (int ntl = 0; ntl < 3; ntl++) {
        int n0 = (wid * 3 + ntl) * 8 + gid;
        fbh[ntl][0] = *reinterpret_cast<const uint32_t*>(&sMh[n0 * 16 + tig * 2]);
        fbh[ntl][1] = *reinterpret_cast<const uint32_t*>(&sMh[n0 * 16 + 8 + tig * 2]);
        fbl[ntl][0] = *reinterpret_cast<const uint32_t*>(&sMl[n0 * 16 + tig * 2]);
        fbl[ntl][1] = *reinterpret_cast<const uint32_t*>(&sMl[n0 * 16 + 8 + tig * 2]);
    }

    for (int t = tstart; t < tend; t++) {
        const int s = (t - tstart) & 1;
        const __nv_bfloat16* sWh =
            reinterpret_cast<const __nv_bfloat16*>(smem + 12288 + s * 4096);
        const __nv_bfloat16* sWl = sWh + 1024;
        const float* sVf =
            reinterpret_cast<const float*>(smem + 20480 + s * 12288);
        const int c0 = t * 192;

        // ---- MMA half-slab + matvec half, twice ----
#pragma unroll
        for (int ph = 0; ph < 2; ph++) {
#pragma unroll
            for (int ms = 0; ms < 2; ms++) {
                int mt = ph * 2 + ms;
                int r0 = mt * 16 + gid;
                uint32_t awh[4], awl[4];
                awh[0] = *reinterpret_cast<const uint32_t*>(&sWh[r0 * 16 + tig * 2]);
                awh[1] = *reinterpret_cast<const uint32_t*>(&sWh[(r0 + 8) * 16 + tig * 2]);
                awh[2] = *reinterpret_cast<const uint32_t*>(&sWh[r0 * 16 + 8 + tig * 2]);
                awh[3] = *reinterpret_cast<const uint32_t*>(&sWh[(r0 + 8) * 16 + 8 + tig * 2]);
                awl[0] = *reinterpret_cast<const uint32_t*>(&sWl[r0 * 16 + tig * 2]);
                awl[1] = *reinterpret_cast<const uint32_t*>(&sWl[(r0 + 8) * 16 + tig * 2]);
                awl[2] = *reinterpret_cast<const uint32_t*>(&sWl[r0 * 16 + 8 + tig * 2]);
                awl[3] = *reinterpret_cast<const uint32_t*>(&sWl[(r0 + 8) * 16 + 8 + tig * 2]);
#pragma unroll
                for (int ntl = 0; ntl < 3; ntl++) {
                    float d[4] = {0.f, 0.f, 0.f, 0.f};
                    mma16816(d, awh, fbh[ntl]);
                    mma16816(d, awh, fbl[ntl]);
                    mma16816(d, awl, fbh[ntl]);
                    int col = (wid * 3 + ntl) * 8 + tig * 2;
                    int rloc = ms * 16 + gid;
                    *reinterpret_cast<float2*>(&sMv[rloc * 196 + col]) =
                        make_float2(d[0], d[1]);
                    *reinterpret_cast<float2*>(&sMv[(rloc + 8) * 196 + col]) =
                        make_float2(d[2], d[3]);
                }
            }
            __syncthreads();   // sMv ready

            if (ph == 0 && t + 1 < tend) {
                stage_W(s ^ 1, t + 1);
                stage_V(s ^ 1, t + 1);
                CP_COMMIT();
            }

            // matvec: verts [ph*32, ph*32+32), 16 batches = 512 items
#pragma unroll
            for (int u = 0; u < 2; u++) {
                int item = tid + 256 * u;
                int bq = item >> 5;
                int vl = item & 31;
                int v  = ph * 32 + vl;
                int vg = t * 64 + v;
                if (vg >= NVV) continue;
                const float* mv = &sMv[vl * 196 + bq * 12];
                float4 m0 = *reinterpret_cast<const float4*>(mv);
                float4 m1 = *reinterpret_cast<const float4*>(mv + 4);
                float4 m2 = *reinterpret_cast<const float4*>(mv + 8);
                int b = b0 + bq;
                const float* vp = &sVf[bq * 192 + v * 3];
                float x = vp[0], yv = vp[1], z = vp[2];
                float o0 = fmaf(m0.x, x, fmaf(m0.y, yv, fmaf(m0.z, z, m0.w)));
                float o1 = fmaf(m1.x, x, fmaf(m1.y, yv, fmaf(m1.z, z, m1.w)));
                float o2 = fmaf(m2.x, x, fmaf(m2.y, yv, fmaf(m2.z, z, m2.w)));
                float* op = &outV[(size_t)b * CTOT + c0 + v * 3];
                op[0] = o0; op[1] = o1; op[2] = o2;

                int tp = -1;
                if (vg == 745) tp = 4; else if (vg == 317) tp = 8;
                else if (vg == 444) tp = 12; else if (vg == 556) tp = 16;
                else if (vg == 673) tp = 20;
                if (tp >= 0) {
                    outJ[(b * 21 + tp) * 3 + 0] = o0;
                    outJ[(b * 21 + tp) * 3 + 1] = o1;
                    outJ[(b * 21 + tp) * 3 + 2] = o2;
                }
            }
            __syncthreads();   // matvec done; sMv free for next phase
        }

        if (t + 1 < tend) { CP_WAIT(0); __syncthreads(); }
    }
}

// ---------------------------------------------------------------------------
extern "C" void kernel_launch(void* const* d_in, const int* in_sizes, int n_in,
                              void* d_out, int out_size) {
    const float* grmt  = (const float*)d_in[0];
    const float* frmt  = (const float*)d_in[1];
    const float* shape = (const float*)d_in[2];
    const float* trans = (const float*)d_in[3];
    const float* vt    = (const float*)d_in[4];
    const float* sd    = (const float*)d_in[5];
    const float* jreg  = (const float*)d_in[6];
    const float* pd    = (const float*)d_in[7];
    const float* lbs   = (const float*)d_in[8];

    float* out  = (float*)d_out;
    float* outV = out;
    float* outJ = out + (size_t)BB * CTOT;

    static bool attr_done = false;
    if (!attr_done) {
        cudaFuncSetAttribute(k3_gemm, cudaFuncAttributeMaxDynamicSharedMemorySize,
                             SM_K3);
        cudaFuncSetAttribute(k4_epi, cudaFuncAttributeMaxDynamicSharedMemorySize,
                             SM_K4);
        attr_done = true;
    }

    k0_prep<<<6452, 256>>>(vt, sd, pd, shape, frmt, jreg, lbs);
    k2_joints<<<BB / 4, 256>>>(grmt, frmt, shape, trans, outJ);
    k3_gemm<<<dim3(BB / 64, 13), 256, SM_K3>>>(vt);
    k4_epi<<<dim3(BB / 16, 4), 256, SM_K4>>>(outV, outJ);
}

// round 12
// speedup vs baseline: 1.3704x; 1.0366x over previous
#include <cuda_runtime.h>
#include <cuda_bf16.h>
#include <cstdint>

#define BB    8192
#define NVV   778
#define NJJ   16
#define CTOT  2334
#define CPAD  2496          // 13 * 192
#define GK    192           // padded K (145 feat + pad)
#define NVP   832           // 13 * 64 padded verts

// ---------------- device scratch (static; no runtime alloc) ----------------
__device__ __align__(16) float          g_V[(size_t)BB * CPAD];      // GEMM out + bias
__device__ __align__(16) __nv_bfloat16  g_A[BB * GK];
__device__ __align__(16) __nv_bfloat16  g_B[CPAD * GK];              // B^T [n][k]
__device__ __align__(16) __nv_bfloat16  g_Whi[NVP * 16];             // lbs hi/lo
__device__ __align__(16) __nv_bfloat16  g_Wlo[NVP * 16];
__device__ __align__(16) __nv_bfloat16  g_MH[(size_t)BB * 12 * 16];  // M'' hi [(b*12+m)*16+j]
__device__ __align__(16) __nv_bfloat16  g_ML[(size_t)BB * 12 * 16];  // M'' lo
__device__ __align__(16) float g_J0[NJJ * 3];
__device__ __align__(16) float g_JS[NJJ * 3 * 10];

__constant__ int c_par[16] = {0,0,1,2,0,4,5,0,7,8,0,10,11,0,13,14};
__constant__ int c_inv[16] = {0,5,6,7,9,10,11,17,18,19,13,14,15,1,2,3};

__device__ __forceinline__ void mma16816(float* d, const uint32_t* a,
                                         const uint32_t* b) {
    asm volatile(
        "mma.sync.aligned.m16n8k16.row.col.f32.bf16.bf16.f32 "
        "{%0,%1,%2,%3}, {%4,%5,%6,%7}, {%8,%9}, {%0,%1,%2,%3};"
        : "+f"(d[0]), "+f"(d[1]), "+f"(d[2]), "+f"(d[3])
        : "r"(a[0]), "r"(a[1]), "r"(a[2]), "r"(a[3]), "r"(b[0]), "r"(b[1]));
}

__device__ __forceinline__ uint32_t smem_u32(const void* p) {
    uint32_t a;
    asm("{ .reg .u64 t; cvta.to.shared.u64 t, %1; cvt.u32.u64 %0, t; }"
        : "=r"(a) : "l"(p));
    return a;
}
// L1-bypassing 16B async copy
__device__ __forceinline__ void cpasync16(uint32_t dst, const void* src) {
    asm volatile("cp.async.cg.shared.global [%0], [%1], 16;"
                 :: "r"(dst), "l"(src));
}
#define CP_COMMIT()  asm volatile("cp.async.commit_group;" ::: "memory")
#define CP_WAIT(n)   asm volatile("cp.async.wait_group %0;" :: "n"(n) : "memory")

// ---------------------------------------------------------------------------
// K0: merged prep. [0,768): A (8 elems/thread); [768,1008): B;
//                  [1008,1024): jreg; [1024,1076): lbs hi/lo split
// ---------------------------------------------------------------------------
__global__ __launch_bounds__(256) void k0_prep(const float* __restrict__ vt,
                                               const float* __restrict__ sd,
                                               const float* __restrict__ pd,
                                               const float* __restrict__ shape,
                                               const float* __restrict__ finger,
                                               const float* __restrict__ jreg,
                                               const float* __restrict__ lbs) {
    __shared__ float red[33 * 256];
    const int blk = blockIdx.x, tid = threadIdx.x;

    if (blk < 768) {                        // ---- A: feat bf16 [B x 192], 8/thr
        int idx = blk * 256 + tid;          // < 196608
        int b = idx / 24, g = idx - b * 24;
        unsigned short hs[8];
#pragma unroll
        for (int i = 0; i < 8; i++) {
            int k = g * 8 + i;
            float val = 0.f;
            if (k < 10) val = shape[b * 10 + k];
            else if (k < 145) {
                int q = k - 10;
                val = finger[b * 135 + q];
                if (((q % 9) & 3) == 0) val -= 1.0f;
            }
            hs[i] = __bfloat16_as_ushort(__float2bfloat16_rn(val));
        }
        uint4 ph;
        ph.x = hs[0] | ((uint32_t)hs[1] << 16);
        ph.y = hs[2] | ((uint32_t)hs[3] << 16);
        ph.z = hs[4] | ((uint32_t)hs[5] << 16);
        ph.w = hs[6] | ((uint32_t)hs[7] << 16);
        *reinterpret_cast<uint4*>(&g_A[b * GK + g * 8]) = ph;
        return;
    }
    if (blk < 1008) {                       // ---- B^T bf16 [n][k]
        int q = blk - 768;
        int kg = q / 10, nb = q - kg * 10;
        int n = nb * 256 + tid;
        if (n >= CPAD) return;
        unsigned short hs[8];
#pragma unroll
        for (int i = 0; i < 8; i++) {
            int k = kg * 8 + i;
            float val = 0.f;
            if (n < CTOT) {
                if (k < 10)       val = sd[n * 10 + k];
                else if (k < 145) val = pd[(k - 10) * CTOT + n];
            }
            hs[i] = __bfloat16_as_ushort(__float2bfloat16_rn(val));
        }
        uint4 ph;
        ph.x = hs[0] | ((uint32_t)hs[1] << 16);
        ph.y = hs[2] | ((uint32_t)hs[3] << 16);
        ph.z = hs[4] | ((uint32_t)hs[5] << 16);
        ph.w = hs[6] | ((uint32_t)hs[7] << 16);
        *reinterpret_cast<uint4*>(&g_B[n * GK + kg * 8]) = ph;
        return;
    }
    if (blk >= 1024) {                      // ---- lbs hi/lo
        int idx = (blk - 1024) * 256 + tid;
        if (idx >= NVP * 16) return;
        int v = idx >> 4, j = idx & 15;
        float w = (v < NVV) ? lbs[v * 16 + j] : 0.f;
        __nv_bfloat16 hi = __float2bfloat16_rn(w);
        __nv_bfloat16 lo = __float2bfloat16_rn(w - __bfloat162float(hi));
        g_Whi[idx] = hi;
        g_Wlo[idx] = lo;
        return;
    }
    // ---- joint regressor: one block per joint
    const int j = blk - 1008;
    float acc[33];
#pragma unroll
    for (int o = 0; o < 33; o++) acc[o] = 0.f;
    for (int v = tid; v < NVV; v += 256) {
        float w = jreg[j * NVV + v];
#pragma unroll
        for (int k = 0; k < 3; k++) {
            acc[k] += w * vt[v * 3 + k];
#pragma unroll
            for (int l = 0; l < 10; l++)
                acc[3 + k * 10 + l] += w * sd[(v * 3 + k) * 10 + l];
        }
    }
    for (int o = 0; o < 33; o++) red[o * 256 + tid] = acc[o];
    __syncthreads();
    if (tid < 33) {
        float s = 0.f;
        for (int i = 0; i < 256; i++) s += red[tid * 256 + i];
        if (tid < 3) g_J0[j * 3 + tid] = s;
        else {
            int o = tid - 3;
            int k = o / 10, l = o - k * 10;
            g_JS[(j * 3 + k) * 10 + l] = s;
        }
    }
}

// ---------------------------------------------------------------------------
// K2: joint chain — 4 batches per CTA; writes M'' as split-bf16 (b*12+m)x16
// ---------------------------------------------------------------------------
__device__ __forceinline__ void mul4(const float* a, float* d) {
    float t[16];
#pragma unroll
    for (int r = 0; r < 4; r++)
#pragma unroll
        for (int c = 0; c < 4; c++)
            t[r * 4 + c] = a[r * 4 + 0] * d[0 + c] + a[r * 4 + 1] * d[4 + c] +
                           a[r * 4 + 2] * d[8 + c] + a[r * 4 + 3] * d[12 + c];
#pragma unroll
    for (int i = 0; i < 16; i++) d[i] = t[i];
}

__global__ __launch_bounds__(256) void k2_joints(const float* __restrict__ grmt,
                          const float* __restrict__ frmt,
                          const float* __restrict__ shape,
                          const float* __restrict__ trans,
                          float* __restrict__ outJ) {
    __shared__ float sJ[4][16][3];
    __shared__ float sM[4][16][16];
    __shared__ float sF[4][136];
    __shared__ float sg[4][9], st[4][3], ssh[4][10];
    const int tid = threadIdx.x;
    const int bs = tid >> 6;
    const int tl = tid & 63;
    const int b = blockIdx.x * 4 + bs;
    const int b0 = blockIdx.x * 4;

    for (int i = tid; i < 540; i += 256) {
        int s = i / 135, q = i - s * 135;
        sF[s][q] = frmt[(b0 + s) * 135 + q];
    }
    if (tl < 9)  sg[bs][tl]  = grmt[b * 9 + tl];
    if (tl < 3)  st[bs][tl]  = trans[b * 3 + tl];
    if (tl < 10) ssh[bs][tl] = shape[b * 10 + tl];
    __syncthreads();

    if (tl < 48) {
        int j = tl / 3, k = tl - j * 3;
        float a = g_J0[j * 3 + k];
#pragma unroll
        for (int l = 0; l < 10; l++) a += ssh[bs][l] * g_JS[(j * 3 + k) * 10 + l];
        sJ[bs][j][k] = a;
    }
    __syncthreads();

    if (tl < 16) {
        int j = tl;
        float R[9];
        if (j == 0) {
            R[0]=1;R[1]=0;R[2]=0;R[3]=0;R[4]=1;R[5]=0;R[6]=0;R[7]=0;R[8]=1;
        } else {
#pragma unroll
            for (int i = 0; i < 9; i++) R[i] = sF[bs][(j - 1) * 9 + i];
        }
        float t0 = sJ[bs][j][0], t1 = sJ[bs][j][1], t2 = sJ[bs][j][2];
        if (j > 0) {
            int p = c_par[j];
            t0 -= sJ[bs][p][0]; t1 -= sJ[bs][p][1]; t2 -= sJ[bs][p][2];
        }
        float* m = sM[bs][j];
        m[0]=R[0]; m[1]=R[1]; m[2]=R[2];  m[3]=t0;
        m[4]=R[3]; m[5]=R[4]; m[6]=R[5];  m[7]=t1;
        m[8]=R[6]; m[9]=R[7]; m[10]=R[8]; m[11]=t2;
        m[12]=0.f; m[13]=0.f; m[14]=0.f;  m[15]=1.f;
    }
    __syncthreads();

    if (tl < 5) {
        int j = 1 + 3 * tl;
        mul4(sM[bs][0], sM[bs][j]);
        mul4(sM[bs][j], sM[bs][j + 1]);
        mul4(sM[bs][j + 1], sM[bs][j + 2]);
    }
    __syncthreads();

    if (tl < 16) {
        int j = tl;
        const float* m = sM[bs][j];
        float jt0 = m[3], jt1 = m[7], jt2 = m[11];
        float J0 = sJ[bs][j][0], J1 = sJ[bs][j][1], J2 = sJ[bs][j][2];
        float tc0 = jt0 - (m[0] * J0 + m[1] * J1 + m[2]  * J2);
        float tc1 = jt1 - (m[4] * J0 + m[5] * J1 + m[6]  * J2);
        float tc2 = jt2 - (m[8] * J0 + m[9] * J1 + m[10] * J2);
        float row[12];
        int jp = c_inv[j];
#pragma unroll
        for (int r = 0; r < 3; r++) {
            float a = sg[bs][r * 3 + 0], bb = sg[bs][r * 3 + 1], cc = sg[bs][r * 3 + 2];
            row[r * 4 + 0] = a * m[0] + bb * m[4] + cc * m[8];
            row[r * 4 + 1] = a * m[1] + bb * m[5] + cc * m[9];
            row[r * 4 + 2] = a * m[2] + bb * m[6] + cc * m[10];
            row[r * 4 + 3] = a * tc0  + bb * tc1  + cc * tc2 + st[bs][r];
            outJ[(b * 21 + jp) * 3 + r] = a * jt0 + bb * jt1 + cc * jt2 + st[bs][r];
        }
#pragma unroll
        for (int mm = 0; mm < 12; mm++) {
            float x = row[mm];
            __nv_bfloat16 hi = __float2bfloat16_rn(x);
            __nv_bfloat16 lo = __float2bfloat16_rn(x - __bfloat162float(hi));
            size_t off = ((size_t)b * 12 + mm) * 16 + j;
            g_MH[off] = hi;
            g_ML[off] = lo;
        }
    }
}

// ---------------------------------------------------------------------------
// K3: single-bf16 mma.sync GEMM, cp.async 2-stage -> g_V (+fp32 bias)
//   CTA: 256 thr, tile 64(b) x 192(n), 2 CTAs/SM.  (unchanged from R11)
// ---------------------------------------------------------------------------
#define STG_SZ  36864
#define SM_K3   73728

__global__ __launch_bounds__(256, 2) void k3_gemm(const float* __restrict__ vt) {
    extern __shared__ __align__(16) char smem[];
    __shared__ float sBias[192];
    const uint32_t sbase = smem_u32(smem);
    const int tid = threadIdx.x;
    const int wid = tid >> 5, lane = tid & 31;
    const int wm = wid & 1, wn = wid >> 1;
    const int gid = lane >> 2, tig = lane & 3;
    const int b0 = blockIdx.x * 64;
    const int t  = blockIdx.y;

    if (tid < 192) {
        int c = t * 192 + tid;
        sBias[tid] = (c < CTOT) ? vt[c] : 0.f;
    }

    auto stage_chunk = [&](int s, int ch) {
        const uint32_t stg = sbase + s * STG_SZ;
        for (int i = tid; i < 2048; i += 256) {
            if (i < 512) {
                int r = i >> 3, q = i & 7;
                cpasync16(stg + r * 144 + q * 16,
                          &g_A[(b0 + r) * GK + ch * 64 + q * 8]);
            } else {
                int i2 = i - 512;
                int r = i2 >> 3, q = i2 & 7;
                cpasync16(stg + 9216 + r * 144 + q * 16,
                          &g_B[(t * 192 + r) * GK + ch * 64 + q * 8]);
            }
        }
    };

    float d[2][6][4];
#pragma unroll
    for (int mt = 0; mt < 2; mt++)
#pragma unroll
        for (int nt = 0; nt < 6; nt++)
#pragma unroll
            for (int q = 0; q < 4; q++) d[mt][nt][q] = 0.f;

    stage_chunk(0, 0); CP_COMMIT();
    stage_chunk(1, 1); CP_COMMIT();

    auto mma_chunk = [&](int s) {
        const char* stg = smem + s * STG_SZ;
#pragma unroll
        for (int ks = 0; ks < 4; ks++) {
            const int kb = ks * 32 + tig * 4;
            uint32_t ah[2][4];
#pragma unroll
            for (int mt = 0; mt < 2; mt++) {
                int r0 = wm * 32 + mt * 16 + gid;
                const char* ph = stg + r0 * 144 + kb;
                ah[mt][0] = *(const uint32_t*)(ph);
                ah[mt][1] = *(const uint32_t*)(ph + 8 * 144);
                ah[mt][2] = *(const uint32_t*)(ph + 16);
                ah[mt][3] = *(const uint32_t*)(ph + 8 * 144 + 16);
            }
            uint32_t bh[6][2];
#pragma unroll
            for (int nt = 0; nt < 6; nt++) {
                int n0 = wn * 48 + nt * 8 + gid;
                const char* ph = stg + 9216 + n0 * 144 + kb;
                bh[nt][0] = *(const uint32_t*)(ph);
                bh[nt][1] = *(const uint32_t*)(ph + 16);
            }
#pragma unroll
            for (int mt = 0; mt < 2; mt++)
#pragma unroll
                for (int nt = 0; nt < 6; nt++)
                    mma16816(d[mt][nt], ah[mt], bh[nt]);
        }
    };

    CP_WAIT(1); __syncthreads();
    mma_chunk(0);
    __syncthreads();
    stage_chunk(0, 2); CP_COMMIT();
    CP_WAIT(1); __syncthreads();
    mma_chunk(1);
    CP_WAIT(0); __syncthreads();
    mma_chunk(0);

#pragma unroll
    for (int mt = 0; mt < 2; mt++) {
        int r0 = b0 + wm * 32 + mt * 16 + gid;
#pragma unroll
        for (int nt = 0; nt < 6; nt++) {
            int cl = wn * 48 + nt * 8 + tig * 2;
            int c = t * 192 + cl;
            float bx = sBias[cl], by = sBias[cl + 1];
            *reinterpret_cast<float2*>(&g_V[(size_t)r0 * CPAD + c]) =
                make_float2(d[mt][nt][0] + bx, d[mt][nt][1] + by);
            *reinterpret_cast<float2*>(&g_V[(size_t)(r0 + 8) * CPAD + c]) =
                make_float2(d[mt][nt][2] + bx, d[mt][nt][3] + by);
        }
    }
}

// ---------------------------------------------------------------------------
// K4: warp-autonomous LBS blend.  CTA: 256 thr, 16 batches x {4|3} tiles.
//   Warp wid's MMA columns = batches {2wid, 2wid+1}: no cross-warp exchange.
//   Per mt-slab: MMA -> private strip (16x26 f) -> __syncwarp -> matvec.
//   One __syncthreads per tile (buffer rotation only).
//   smem: sMh@0 6144 | sMl@6144 | sW dbuf@12288 2x4096 | sV dbuf@20480 2x12288
//         strips@45056 8x1664 = 13312  -> total 58368 B, 3 CTAs/SM
// ---------------------------------------------------------------------------
#define SM_K4 58368

__global__ __launch_bounds__(256, 3) void k4_epi(float* __restrict__ outV,
                                                 float* __restrict__ outJ) {
    extern __shared__ __align__(16) char smem[];
    const uint32_t sbase = smem_u32(smem);
    __nv_bfloat16* sMh = reinterpret_cast<__nv_bfloat16*>(smem);
    __nv_bfloat16* sMl = reinterpret_cast<__nv_bfloat16*>(smem + 6144);

    const int tid = threadIdx.x;
    const int b0 = blockIdx.x * 16;
    const int y  = blockIdx.y;
    const int tstart = (y == 0) ? 0 : 1 + y * 3;      // {0,4,7,10}
    const int tend   = tstart + ((y == 0) ? 4 : 3);   // {4,7,10,13}

    auto stage_W = [&](int s, int t) {
        int split = tid >> 7, i2 = tid & 127;
        int row = i2 >> 1, half = i2 & 1;
        const __nv_bfloat16* src = split ? g_Wlo : g_Whi;
        cpasync16(sbase + 12288 + s * 4096 + split * 2048 +
                      (row * 16 + half * 8) * 2,
                  &src[(t * 64 + row) * 16 + half * 8]);
    };
    auto stage_V = [&](int s, int t) {
        for (int i = tid; i < 768; i += 256) {
            int r = i / 48, q = i - r * 48;
            cpasync16(sbase + 20480 + s * 12288 + (r * 192 + q * 4) * 4,
                      &g_V[(size_t)(b0 + r) * CPAD + t * 192 + q * 4]);
        }
    };

    // stage M'' (12KB) + first W and V slices
    for (int i = tid; i < 768; i += 256) {
        int split = i / 384, i2 = i - split * 384;
        int n = i2 >> 1, half = i2 & 1;
        const __nv_bfloat16* src = split ? g_ML : g_MH;
        cpasync16(sbase + split * 6144 + (n * 16 + half * 8) * 2,
                  &src[((size_t)b0 * 12 + n) * 16 + half * 8]);
    }
    stage_W(0, tstart);
    stage_V(0, tstart);
    CP_COMMIT();
    CP_WAIT(0);
    __syncthreads();

    const int wid = tid >> 5, lane = tid & 31;
    const int gid = lane >> 2, tig = lane & 3;
    float* strip = reinterpret_cast<float*>(smem + 45056 + wid * 1664);
    const int half = lane >> 4, lv = lane & 15;
    const int bq = wid * 2 + half;
    const int bglob = b0 + bq;

    // hoisted B fragments (M'' columns) — tile-invariant
    uint32_t fbh[3][2], fbl[3][2];
#pragma unroll
    for (int ntl = 0; ntl < 3; ntl++) {
        int n0 = wid * 24 + ntl * 8 + gid;
        fbh[ntl][0] = *reinterpret_cast<const uint32_t*>(&sMh[n0 * 16 + tig * 2]);
        fbh[ntl][1] = *reinterpret_cast<const uint32_t*>(&sMh[n0 * 16 + 8 + tig * 2]);
        fbl[ntl][0] = *reinterpret_cast<const uint32_t*>(&sMl[n0 * 16 + tig * 2]);
        fbl[ntl][1] = *reinterpret_cast<const uint32_t*>(&sMl[n0 * 16 + 8 + tig * 2]);
    }

    for (int t = tstart; t < tend; t++) {
        const int s = (t - tstart) & 1;
        // prefetch next tile's W+V into the other buffer (async, no sync needed)
        if (t + 1 < tend) {
            stage_W(s ^ 1, t + 1);
            stage_V(s ^ 1, t + 1);
            CP_COMMIT();
        }
        const __nv_bfloat16* sWh =
            reinterpret_cast<const __nv_bfloat16*>(smem + 12288 + s * 4096);
        const __nv_bfloat16* sWl = sWh + 1024;
        const float* sVf =
            reinterpret_cast<const float*>(smem + 20480 + s * 12288);
        const int c0 = t * 192;

#pragma unroll
        for (int mt = 0; mt < 4; mt++) {
            int r0 = mt * 16 + gid;
            uint32_t awh[4], awl[4];
            awh[0] = *reinterpret_cast<const uint32_t*>(&sWh[r0 * 16 + tig * 2]);
            awh[1] = *reinterpret_cast<const uint32_t*>(&sWh[(r0 + 8) * 16 + tig * 2]);
            awh[2] = *reinterpret_cast<const uint32_t*>(&sWh[r0 * 16 + 8 + tig * 2]);
            awh[3] = *reinterpret_cast<const uint32_t*>(&sWh[(r0 + 8) * 16 + 8 + tig * 2]);
            awl[0] = *reinterpret_cast<const uint32_t*>(&sWl[r0 * 16 + tig * 2]);
            awl[1] = *reinterpret_cast<const uint32_t*>(&sWl[(r0 + 8) * 16 + tig * 2]);
            awl[2] = *reinterpret_cast<const uint32_t*>(&sWl[r0 * 16 + 8 + tig * 2]);
            awl[3] = *reinterpret_cast<const uint32_t*>(&sWl[(r0 + 8) * 16 + 8 + tig * 2]);
#pragma unroll
            for (int ntl = 0; ntl < 3; ntl++) {
                float d[4] = {0.f, 0.f, 0.f, 0.f};
                mma16816(d, awh, fbh[ntl]);
                mma16816(d, awh, fbl[ntl]);
                mma16816(d, awl, fbh[ntl]);
                int col = ntl * 8 + tig * 2;
                *reinterpret_cast<float2*>(&strip[gid * 26 + col]) =
                    make_float2(d[0], d[1]);
                *reinterpret_cast<float2*>(&strip[(gid + 8) * 26 + col]) =
                    make_float2(d[2], d[3]);
            }
            __syncwarp();

            // matvec: this warp's 2 batches x 16 verts (1 item/lane)
            int v = mt * 16 + lv;
            int vg = t * 64 + v;
            if (vg < NVV) {
                const float* mv = &strip[lv * 26 + half * 12];
                float2 a0 = *reinterpret_cast<const float2*>(mv);
                float2 a1 = *reinterpret_cast<const float2*>(mv + 2);
                float2 a2 = *reinterpret_cast<const float2*>(mv + 4);
                float2 a3 = *reinterpret_cast<const float2*>(mv + 6);
                float2 a4 = *reinterpret_cast<const float2*>(mv + 8);
                float2 a5 = *reinterpret_cast<const float2*>(mv + 10);
                const float* vp = &sVf[bq * 192 + v * 3];
                float x = vp[0], yv = vp[1], z = vp[2];
                float o0 = fmaf(a0.x, x, fmaf(a0.y, yv, fmaf(a1.x, z, a1.y)));
                float o1 = fmaf(a2.x, x, fmaf(a2.y, yv, fmaf(a3.x, z, a3.y)));
                float o2 = fmaf(a4.x, x, fmaf(a4.y, yv, fmaf(a5.x, z, a5.y)));
                float* op = &outV[(size_t)bglob * CTOT + c0 + v * 3];
                op[0] = o0; op[1] = o1; op[2] = o2;

                int tp = -1;
                if (vg == 745) tp = 4; else if (vg == 317) tp = 8;
                else if (vg == 444) tp = 12; else if (vg == 556) tp = 16;
                else if (vg == 673) tp = 20;
                if (tp >= 0) {
                    outJ[(bglob * 21 + tp) * 3 + 0] = o0;
                    outJ[(bglob * 21 + tp) * 3 + 1] = o1;
                    outJ[(bglob * 21 + tp) * 3 + 2] = o2;
                }
            }
            __syncwarp();
        }

        if (t + 1 < tend) CP_WAIT(0);
        __syncthreads();   // single per-tile barrier: buffer rotation
    }
}

// ---------------------------------------------------------------------------
extern "C" void kernel_launch(void* const* d_in, const int* in_sizes, int n_in,
                              void* d_out, int out_size) {
    const float* grmt  = (const float*)d_in[0];
    const float* frmt  = (const float*)d_in[1];
    const float* shape = (const float*)d_in[2];
    const float* trans = (const float*)d_in[3];
    const float* vt    = (const float*)d_in[4];
    const float* sd    = (const float*)d_in[5];
    const float* jreg  = (const float*)d_in[6];
    const float* pd    = (const float*)d_in[7];
    const float* lbs   = (const float*)d_in[8];

    float* out  = (float*)d_out;
    float* outV = out;
    float* outJ = out + (size_t)BB * CTOT;

    static bool attr_done = false;
    if (!attr_done) {
        cudaFuncSetAttribute(k3_gemm, cudaFuncAttributeMaxDynamicSharedMemorySize,
                             SM_K3);
        cudaFuncSetAttribute(k4_epi, cudaFuncAttributeMaxDynamicSharedMemorySize,
                             SM_K4);
        attr_done = true;
    }

    k0_prep<<<1076, 256>>>(vt, sd, pd, shape, frmt, jreg, lbs);
    k2_joints<<<BB / 4, 256>>>(grmt, frmt, shape, trans, outJ);
    k3_gemm<<<dim3(BB / 64, 13), 256, SM_K3>>>(vt);
    k4_epi<<<dim3(BB / 16, 4), 256, SM_K4>>>(outV, outJ);
}

// round 13
// speedup vs baseline: 1.4000x; 1.0216x over previous
#include <cuda_runtime.h>
#include <cuda_bf16.h>
#include <cstdint>

#define BB    8192
#define NVV   778
#define NJJ   16
#define CTOT  2334
#define CPAD  2496          // 13 * 192
#define GK    192           // padded K (145 feat + pad)
#define NVP   832           // 13 * 64 padded verts

// ---------------- device scratch (static; no runtime alloc) ----------------
__device__ __align__(16) float          g_V[(size_t)BB * CPAD];      // GEMM out + bias
__device__ __align__(16) __nv_bfloat16  g_A[BB * GK];
__device__ __align__(16) __nv_bfloat16  g_B[CPAD * GK];              // B^T [n][k]
__device__ __align__(16) __nv_bfloat16  g_Whi[NVP * 16];             // lbs hi/lo
__device__ __align__(16) __nv_bfloat16  g_Wlo[NVP * 16];
__device__ __align__(16) __nv_bfloat16  g_MH[(size_t)BB * 12 * 16];  // M'' hi [(b*12+m)*16+j]
__device__ __align__(16) __nv_bfloat16  g_ML[(size_t)BB * 12 * 16];  // M'' lo
__device__ __align__(16) float g_J0[NJJ * 3];
__device__ __align__(16) float g_JS[NJJ * 3 * 10];

__constant__ int c_par[16] = {0,0,1,2,0,4,5,0,7,8,0,10,11,0,13,14};
__constant__ int c_inv[16] = {0,5,6,7,9,10,11,17,18,19,13,14,15,1,2,3};

__device__ __forceinline__ void mma16816(float* d, const uint32_t* a,
                                         const uint32_t* b) {
    asm volatile(
        "mma.sync.aligned.m16n8k16.row.col.f32.bf16.bf16.f32 "
        "{%0,%1,%2,%3}, {%4,%5,%6,%7}, {%8,%9}, {%0,%1,%2,%3};"
        : "+f"(d[0]), "+f"(d[1]), "+f"(d[2]), "+f"(d[3])
        : "r"(a[0]), "r"(a[1]), "r"(a[2]), "r"(a[3]), "r"(b[0]), "r"(b[1]));
}

__device__ __forceinline__ uint32_t smem_u32(const void* p) {
    uint32_t a;
    asm("{ .reg .u64 t; cvta.to.shared.u64 t, %1; cvt.u32.u64 %0, t; }"
        : "=r"(a) : "l"(p));
    return a;
}
// L1-bypassing 16B async copy
__device__ __forceinline__ void cpasync16(uint32_t dst, const void* src) {
    asm volatile("cp.async.cg.shared.global [%0], [%1], 16;"
                 :: "r"(dst), "l"(src));
}
#define CP_COMMIT()  asm volatile("cp.async.commit_group;" ::: "memory")
#define CP_WAIT(n)   asm volatile("cp.async.wait_group %0;" :: "n"(n) : "memory")

// ---------------------------------------------------------------------------
// K0_SMALL: [0,16): jreg contractions; [16,68): lbs hi/lo split
// ---------------------------------------------------------------------------
__global__ __launch_bounds__(256) void k0_small(const float* __restrict__ vt,
                                                const float* __restrict__ sd,
                                                const float* __restrict__ jreg,
                                                const float* __restrict__ lbs) {
    __shared__ float red[33 * 256];
    const int blk = blockIdx.x, tid = threadIdx.x;

    if (blk >= 16) {                        // ---- lbs hi/lo
        int idx = (blk - 16) * 256 + tid;
        if (idx >= NVP * 16) return;
        int v = idx >> 4, j = idx & 15;
        float w = (v < NVV) ? lbs[v * 16 + j] : 0.f;
        __nv_bfloat16 hi = __float2bfloat16_rn(w);
        __nv_bfloat16 lo = __float2bfloat16_rn(w - __bfloat162float(hi));
        g_Whi[idx] = hi;
        g_Wlo[idx] = lo;
        return;
    }
    // ---- joint regressor: one block per joint
    const int j = blk;
    float acc[33];
#pragma unroll
    for (int o = 0; o < 33; o++) acc[o] = 0.f;
    for (int v = tid; v < NVV; v += 256) {
        float w = jreg[j * NVV + v];
#pragma unroll
        for (int k = 0; k < 3; k++) {
            acc[k] += w * vt[v * 3 + k];
#pragma unroll
            for (int l = 0; l < 10; l++)
                acc[3 + k * 10 + l] += w * sd[(v * 3 + k) * 10 + l];
        }
    }
    for (int o = 0; o < 33; o++) red[o * 256 + tid] = acc[o];
    __syncthreads();
    if (tid < 33) {
        float s = 0.f;
        for (int i = 0; i < 256; i++) s += red[tid * 256 + i];
        if (tid < 3) g_J0[j * 3 + tid] = s;
        else {
            int o = tid - 3;
            int k = o / 10, l = o - k * 10;
            g_JS[(j * 3 + k) * 10 + l] = s;
        }
    }
}

// ---------------------------------------------------------------------------
// K0_AB: [0,768): A (8 elems/thread); [768,1008): B
// ---------------------------------------------------------------------------
__global__ __launch_bounds__(256) void k0_AB(const float* __restrict__ sd,
                                             const float* __restrict__ pd,
                                             const float* __restrict__ shape,
                                             const float* __restrict__ finger) {
    const int blk = blockIdx.x, tid = threadIdx.x;

    if (blk < 768) {                        // ---- A: feat bf16 [B x 192], 8/thr
        int idx = blk * 256 + tid;          // < 196608
        int b = idx / 24, g = idx - b * 24;
        unsigned short hs[8];
#pragma unroll
        for (int i = 0; i < 8; i++) {
            int k = g * 8 + i;
            float val = 0.f;
            if (k < 10) val = shape[b * 10 + k];
            else if (k < 145) {
                int q = k - 10;
                val = finger[b * 135 + q];
                if (((q % 9) & 3) == 0) val -= 1.0f;
            }
            hs[i] = __bfloat16_as_ushort(__float2bfloat16_rn(val));
        }
        uint4 ph;
        ph.x = hs[0] | ((uint32_t)hs[1] << 16);
        ph.y = hs[2] | ((uint32_t)hs[3] << 16);
        ph.z = hs[4] | ((uint32_t)hs[5] << 16);
        ph.w = hs[6] | ((uint32_t)hs[7] << 16);
        *reinterpret_cast<uint4*>(&g_A[b * GK + g * 8]) = ph;
        return;
    }
    // ---- B^T bf16 [n][k]
    int q = blk - 768;
    int kg = q / 10, nb = q - kg * 10;
    int n = nb * 256 + tid;
    if (n >= CPAD) return;
    unsigned short hs[8];
#pragma unroll
    for (int i = 0; i < 8; i++) {
        int k = kg * 8 + i;
        float val = 0.f;
        if (n < CTOT) {
            if (k < 10)       val = sd[n * 10 + k];
            else if (k < 145) val = pd[(k - 10) * CTOT + n];
        }
        hs[i] = __bfloat16_as_ushort(__float2bfloat16_rn(val));
    }
    uint4 ph;
    ph.x = hs[0] | ((uint32_t)hs[1] << 16);
    ph.y = hs[2] | ((uint32_t)hs[3] << 16);
    ph.z = hs[4] | ((uint32_t)hs[5] << 16);
    ph.w = hs[6] | ((uint32_t)hs[7] << 16);
    *reinterpret_cast<uint4*>(&g_B[n * GK + kg * 8]) = ph;
}

// ---------------------------------------------------------------------------
// K2: joint chain — 4 batches per CTA; writes M'' as split-bf16 (b*12+m)x16
// ---------------------------------------------------------------------------
__device__ __forceinline__ void mul4(const float* a, float* d) {
    float t[16];
#pragma unroll
    for (int r = 0; r < 4; r++)
#pragma unroll
        for (int c = 0; c < 4; c++)
            t[r * 4 + c] = a[r * 4 + 0] * d[0 + c] + a[r * 4 + 1] * d[4 + c] +
                           a[r * 4 + 2] * d[8 + c] + a[r * 4 + 3] * d[12 + c];
#pragma unroll
    for (int i = 0; i < 16; i++) d[i] = t[i];
}

__global__ __launch_bounds__(256) void k2_joints(const float* __restrict__ grmt,
                          const float* __restrict__ frmt,
                          const float* __restrict__ shape,
                          const float* __restrict__ trans,
                          float* __restrict__ outJ) {
    __shared__ float sJ[4][16][3];
    __shared__ float sM[4][16][16];
    __shared__ float sF[4][136];
    __shared__ float sg[4][9], st[4][3], ssh[4][10];
    const int tid = threadIdx.x;
    const int bs = tid >> 6;
    const int tl = tid & 63;
    const int b = blockIdx.x * 4 + bs;
    const int b0 = blockIdx.x * 4;

    for (int i = tid; i < 540; i += 256) {
        int s = i / 135, q = i - s * 135;
        sF[s][q] = frmt[(b0 + s) * 135 + q];
    }
    if (tl < 9)  sg[bs][tl]  = grmt[b * 9 + tl];
    if (tl < 3)  st[bs][tl]  = trans[b * 3 + tl];
    if (tl < 10) ssh[bs][tl] = shape[b * 10 + tl];
    __syncthreads();

    if (tl < 48) {
        int j = tl / 3, k = tl - j * 3;
        float a = g_J0[j * 3 + k];
#pragma unroll
        for (int l = 0; l < 10; l++) a += ssh[bs][l] * g_JS[(j * 3 + k) * 10 + l];
        sJ[bs][j][k] = a;
    }
    __syncthreads();

    if (tl < 16) {
        int j = tl;
        float R[9];
        if (j == 0) {
            R[0]=1;R[1]=0;R[2]=0;R[3]=0;R[4]=1;R[5]=0;R[6]=0;R[7]=0;R[8]=1;
        } else {
#pragma unroll
            for (int i = 0; i < 9; i++) R[i] = sF[bs][(j - 1) * 9 + i];
        }
        float t0 = sJ[bs][j][0], t1 = sJ[bs][j][1], t2 = sJ[bs][j][2];
        if (j > 0) {
            int p = c_par[j];
            t0 -= sJ[bs][p][0]; t1 -= sJ[bs][p][1]; t2 -= sJ[bs][p][2];
        }
        float* m = sM[bs][j];
        m[0]=R[0]; m[1]=R[1]; m[2]=R[2];  m[3]=t0;
        m[4]=R[3]; m[5]=R[4]; m[6]=R[5];  m[7]=t1;
        m[8]=R[6]; m[9]=R[7]; m[10]=R[8]; m[11]=t2;
        m[12]=0.f; m[13]=0.f; m[14]=0.f;  m[15]=1.f;
    }
    __syncthreads();

    if (tl < 5) {
        int j = 1 + 3 * tl;
        mul4(sM[bs][0], sM[bs][j]);
        mul4(sM[bs][j], sM[bs][j + 1]);
        mul4(sM[bs][j + 1], sM[bs][j + 2]);
    }
    __syncthreads();

    if (tl < 16) {
        int j = tl;
        const float* m = sM[bs][j];
        float jt0 = m[3], jt1 = m[7], jt2 = m[11];
        float J0 = sJ[bs][j][0], J1 = sJ[bs][j][1], J2 = sJ[bs][j][2];
        float tc0 = jt0 - (m[0] * J0 + m[1] * J1 + m[2]  * J2);
        float tc1 = jt1 - (m[4] * J0 + m[5] * J1 + m[6]  * J2);
        float tc2 = jt2 - (m[8] * J0 + m[9] * J1 + m[10] * J2);
        float row[12];
        int jp = c_inv[j];
#pragma unroll
        for (int r = 0; r < 3; r++) {
            float a = sg[bs][r * 3 + 0], bb = sg[bs][r * 3 + 1], cc = sg[bs][r * 3 + 2];
            row[r * 4 + 0] = a * m[0] + bb * m[4] + cc * m[8];
            row[r * 4 + 1] = a * m[1] + bb * m[5] + cc * m[9];
            row[r * 4 + 2] = a * m[2] + bb * m[6] + cc * m[10];
            row[r * 4 + 3] = a * tc0  + bb * tc1  + cc * tc2 + st[bs][r];
            outJ[(b * 21 + jp) * 3 + r] = a * jt0 + bb * jt1 + cc * jt2 + st[bs][r];
        }
#pragma unroll
        for (int mm = 0; mm < 12; mm++) {
            float x = row[mm];
            __nv_bfloat16 hi = __float2bfloat16_rn(x);
            __nv_bfloat16 lo = __float2bfloat16_rn(x - __bfloat162float(hi));
            size_t off = ((size_t)b * 12 + mm) * 16 + j;
            g_MH[off] = hi;
            g_ML[off] = lo;
        }
    }
}

// ---------------------------------------------------------------------------
// K3: single-bf16 mma.sync GEMM, cp.async 2-stage -> g_V (+fp32 bias)
//   CTA: 256 thr, tile 64(b) x 192(n), 2 CTAs/SM.  (unchanged)
// ---------------------------------------------------------------------------
#define STG_SZ  36864
#define SM_K3   73728

__global__ __launch_bounds__(256, 2) void k3_gemm(const float* __restrict__ vt) {
    extern __shared__ __align__(16) char smem[];
    __shared__ float sBias[192];
    const uint32_t sbase = smem_u32(smem);
    const int tid = threadIdx.x;
    const int wid = tid >> 5, lane = tid & 31;
    const int wm = wid & 1, wn = wid >> 1;
    const int gid = lane >> 2, tig = lane & 3;
    const int b0 = blockIdx.x * 64;
    const int t  = blockIdx.y;

    if (tid < 192) {
        int c = t * 192 + tid;
        sBias[tid] = (c < CTOT) ? vt[c] : 0.f;
    }

    auto stage_chunk = [&](int s, int ch) {
        const uint32_t stg = sbase + s * STG_SZ;
        for (int i = tid; i < 2048; i += 256) {
            if (i < 512) {
                int r = i >> 3, q = i & 7;
                cpasync16(stg + r * 144 + q * 16,
                          &g_A[(b0 + r) * GK + ch * 64 + q * 8]);
            } else {
                int i2 = i - 512;
                int r = i2 >> 3, q = i2 & 7;
                cpasync16(stg + 9216 + r * 144 + q * 16,
                          &g_B[(t * 192 + r) * GK + ch * 64 + q * 8]);
            }
        }
    };

    float d[2][6][4];
#pragma unroll
    for (int mt = 0; mt < 2; mt++)
#pragma unroll
        for (int nt = 0; nt < 6; nt++)
#pragma unroll
            for (int q = 0; q < 4; q++) d[mt][nt][q] = 0.f;

    stage_chunk(0, 0); CP_COMMIT();
    stage_chunk(1, 1); CP_COMMIT();

    auto mma_chunk = [&](int s) {
        const char* stg = smem + s * STG_SZ;
#pragma unroll
        for (int ks = 0; ks < 4; ks++) {
            const int kb = ks * 32 + tig * 4;
            uint32_t ah[2][4];
#pragma unroll
            for (int mt = 0; mt < 2; mt++) {
                int r0 = wm * 32 + mt * 16 + gid;
                const char* ph = stg + r0 * 144 + kb;
                ah[mt][0] = *(const uint32_t*)(ph);
                ah[mt][1] = *(const uint32_t*)(ph + 8 * 144);
                ah[mt][2] = *(const uint32_t*)(ph + 16);
                ah[mt][3] = *(const uint32_t*)(ph + 8 * 144 + 16);
            }
            uint32_t bh[6][2];
#pragma unroll
            for (int nt = 0; nt < 6; nt++) {
                int n0 = wn * 48 + nt * 8 + gid;
                const char* ph = stg + 9216 + n0 * 144 + kb;
                bh[nt][0] = *(const uint32_t*)(ph);
                bh[nt][1] = *(const uint32_t*)(ph + 16);
            }
#pragma unroll
            for (int mt = 0; mt < 2; mt++)
#pragma unroll
                for (int nt = 0; nt < 6; nt++)
                    mma16816(d[mt][nt], ah[mt], bh[nt]);
        }
    };

    CP_WAIT(1); __syncthreads();
    mma_chunk(0);
    __syncthreads();
    stage_chunk(0, 2); CP_COMMIT();
    CP_WAIT(1); __syncthreads();
    mma_chunk(1);
    CP_WAIT(0); __syncthreads();
    mma_chunk(0);

#pragma unroll
    for (int mt = 0; mt < 2; mt++) {
        int r0 = b0 + wm * 32 + mt * 16 + gid;
#pragma unroll
        for (int nt = 0; nt < 6; nt++) {
            int cl = wn * 48 + nt * 8 + tig * 2;
            int c = t * 192 + cl;
            float bx = sBias[cl], by = sBias[cl + 1];
            *reinterpret_cast<float2*>(&g_V[(size_t)r0 * CPAD + c]) =
                make_float2(d[mt][nt][0] + bx, d[mt][nt][1] + by);
            *reinterpret_cast<float2*>(&g_V[(size_t)(r0 + 8) * CPAD + c]) =
                make_float2(d[mt][nt][2] + bx, d[mt][nt][3] + by);
        }
    }
}

// ---------------------------------------------------------------------------
// K4: warp-autonomous LBS blend (unchanged from R12)
// ---------------------------------------------------------------------------
#define SM_K4 58368

__global__ __launch_bounds__(256, 3) void k4_epi(float* __restrict__ outV,
                                                 float* __restrict__ outJ) {
    extern __shared__ __align__(16) char smem[];
    const uint32_t sbase = smem_u32(smem);
    __nv_bfloat16* sMh = reinterpret_cast<__nv_bfloat16*>(smem);
    __nv_bfloat16* sMl = reinterpret_cast<__nv_bfloat16*>(smem + 6144);

    const int tid = threadIdx.x;
    const int b0 = blockIdx.x * 16;
    const int y  = blockIdx.y;
    const int tstart = (y == 0) ? 0 : 1 + y * 3;      // {0,4,7,10}
    const int tend   = tstart + ((y == 0) ? 4 : 3);   // {4,7,10,13}

    auto stage_W = [&](int s, int t) {
        int split = tid >> 7, i2 = tid & 127;
        int row = i2 >> 1, half = i2 & 1;
        const __nv_bfloat16* src = split ? g_Wlo : g_Whi;
        cpasync16(sbase + 12288 + s * 4096 + split * 2048 +
                      (row * 16 + half * 8) * 2,
                  &src[(t * 64 + row) * 16 + half * 8]);
    };
    auto stage_V = [&](int s, int t) {
        for (int i = tid; i < 768; i += 256) {
            int r = i / 48, q = i - r * 48;
            cpasync16(sbase + 20480 + s * 12288 + (r * 192 + q * 4) * 4,
                      &g_V[(size_t)(b0 + r) * CPAD + t * 192 + q * 4]);
        }
    };

    for (int i = tid; i < 768; i += 256) {
        int split = i / 384, i2 = i - split * 384;
        int n = i2 >> 1, half = i2 & 1;
        const __nv_bfloat16* src = split ? g_ML : g_MH;
        cpasync16(sbase + split * 6144 + (n * 16 + half * 8) * 2,
                  &src[((size_t)b0 * 12 + n) * 16 + half * 8]);
    }
    stage_W(0, tstart);
    stage_V(0, tstart);
    CP_COMMIT();
    CP_WAIT(0);
    __syncthreads();

    const int wid = tid >> 5, lane = tid & 31;
    const int gid = lane >> 2, tig = lane & 3;
    float* strip = reinterpret_cast<float*>(smem + 45056 + wid * 1664);
    const int half = lane >> 4, lv = lane & 15;
    const int bq = wid * 2 + half;
    const int bglob = b0 + bq;

    uint32_t fbh[3][2], fbl[3][2];
#pragma unroll
    for (int ntl = 0; ntl < 3; ntl++) {
        int n0 = wid * 24 + ntl * 8 + gid;
        fbh[ntl][0] = *reinterpret_cast<const uint32_t*>(&sMh[n0 * 16 + tig * 2]);
        fbh[ntl][1] = *reinterpret_cast<const uint32_t*>(&sMh[n0 * 16 + 8 + tig * 2]);
        fbl[ntl][0] = *reinterpret_cast<const uint32_t*>(&sMl[n0 * 16 + tig * 2]);
        fbl[ntl][1] = *reinterpret_cast<const uint32_t*>(&sMl[n0 * 16 + 8 + tig * 2]);
    }

    for (int t = tstart; t < tend; t++) {
        const int s = (t - tstart) & 1;
        if (t + 1 < tend) {
            stage_W(s ^ 1, t + 1);
            stage_V(s ^ 1, t + 1);
            CP_COMMIT();
        }
        const __nv_bfloat16* sWh =
            reinterpret_cast<const __nv_bfloat16*>(smem + 12288 + s * 4096);
        const __nv_bfloat16* sWl = sWh + 1024;
        const float* sVf =
            reinterpret_cast<const float*>(smem + 20480 + s * 12288);
        const int c0 = t * 192;

#pragma unroll
        for (int mt = 0; mt < 4; mt++) {
            int r0 = mt * 16 + gid;
            uint32_t awh[4], awl[4];
            awh[0] = *reinterpret_cast<const uint32_t*>(&sWh[r0 * 16 + tig * 2]);
            awh[1] = *reinterpret_cast<const uint32_t*>(&sWh[(r0 + 8) * 16 + tig * 2]);
            awh[2] = *reinterpret_cast<const uint32_t*>(&sWh[r0 * 16 + 8 + tig * 2]);
            awh[3] = *reinterpret_cast<const uint32_t*>(&sWh[(r0 + 8) * 16 + 8 + tig * 2]);
            awl[0] = *reinterpret_cast<const uint32_t*>(&sWl[r0 * 16 + tig * 2]);
            awl[1] = *reinterpret_cast<const uint32_t*>(&sWl[(r0 + 8) * 16 + tig * 2]);
            awl[2] = *reinterpret_cast<const uint32_t*>(&sWl[r0 * 16 + 8 + tig * 2]);
            awl[3] = *reinterpret_cast<const uint32_t*>(&sWl[(r0 + 8) * 16 + 8 + tig * 2]);
#pragma unroll
            for (int ntl = 0; ntl < 3; ntl++) {
                float d[4] = {0.f, 0.f, 0.f, 0.f};
                mma16816(d, awh, fbh[ntl]);
                mma16816(d, awh, fbl[ntl]);
                mma16816(d, awl, fbh[ntl]);
                int col = ntl * 8 + tig * 2;
                *reinterpret_cast<float2*>(&strip[gid * 26 + col]) =
                    make_float2(d[0], d[1]);
                *reinterpret_cast<float2*>(&strip[(gid + 8) * 26 + col]) =
                    make_float2(d[2], d[3]);
            }
            __syncwarp();

            int v = mt * 16 + lv;
            int vg = t * 64 + v;
            if (vg < NVV) {
                const float* mv = &strip[lv * 26 + half * 12];
                float2 a0 = *reinterpret_cast<const float2*>(mv);
                float2 a1 = *reinterpret_cast<const float2*>(mv + 2);
                float2 a2 = *reinterpret_cast<const float2*>(mv + 4);
                float2 a3 = *reinterpret_cast<const float2*>(mv + 6);
                float2 a4 = *reinterpret_cast<const float2*>(mv + 8);
                float2 a5 = *reinterpret_cast<const float2*>(mv + 10);
                const float* vp = &sVf[bq * 192 + v * 3];
                float x = vp[0], yv = vp[1], z = vp[2];
                float o0 = fmaf(a0.x, x, fmaf(a0.y, yv, fmaf(a1.x, z, a1.y)));
                float o1 = fmaf(a2.x, x, fmaf(a2.y, yv, fmaf(a3.x, z, a3.y)));
                float o2 = fmaf(a4.x, x, fmaf(a4.y, yv, fmaf(a5.x, z, a5.y)));
                float* op = &outV[(size_t)bglob * CTOT + c0 + v * 3];
                op[0] = o0; op[1] = o1; op[2] = o2;

                int tp = -1;
                if (vg == 745) tp = 4; else if (vg == 317) tp = 8;
                else if (vg == 444) tp = 12; else if (vg == 556) tp = 16;
                else if (vg == 673) tp = 20;
                if (tp >= 0) {
                    outJ[(bglob * 21 + tp) * 3 + 0] = o0;
                    outJ[(bglob * 21 + tp) * 3 + 1] = o1;
                    outJ[(bglob * 21 + tp) * 3 + 2] = o2;
                }
            }
            __syncwarp();
        }

        if (t + 1 < tend) CP_WAIT(0);
        __syncthreads();
    }
}

// ---------------------------------------------------------------------------
extern "C" void kernel_launch(void* const* d_in, const int* in_sizes, int n_in,
                              void* d_out, int out_size) {
    const float* grmt  = (const float*)d_in[0];
    const float* frmt  = (const float*)d_in[1];
    const float* shape = (const float*)d_in[2];
    const float* trans = (const float*)d_in[3];
    const float* vt    = (const float*)d_in[4];
    const float* sd    = (const float*)d_in[5];
    const float* jreg  = (const float*)d_in[6];
    const float* pd    = (const float*)d_in[7];
    const float* lbs   = (const float*)d_in[8];

    float* out  = (float*)d_out;
    float* outV = out;
    float* outJ = out + (size_t)BB * CTOT;

    static cudaStream_t sB = nullptr;
    static cudaEvent_t evRoot = nullptr, evB = nullptr;
    static bool attr_done = false;
    if (!attr_done) {
        cudaFuncSetAttribute(k3_gemm, cudaFuncAttributeMaxDynamicSharedMemorySize,
                             SM_K3);
        cudaFuncSetAttribute(k4_epi, cudaFuncAttributeMaxDynamicSharedMemorySize,
                             SM_K4);
        cudaStreamCreateWithFlags(&sB, cudaStreamNonBlocking);
        cudaEventCreateWithFlags(&evRoot, cudaEventDisableTiming);
        cudaEventCreateWithFlags(&evB, cudaEventDisableTiming);
        attr_done = true;
    }

    // fork: branch stream runs k0_small -> k2 concurrent with k0_AB -> k3
    cudaEventRecord(evRoot, 0);
    cudaStreamWaitEvent(sB, evRoot, 0);

    k0_small<<<68, 256, 0, sB>>>(vt, sd, jreg, lbs);
    k2_joints<<<BB / 4, 256, 0, sB>>>(grmt, frmt, shape, trans, outJ);
    cudaEventRecord(evB, sB);

    k0_AB<<<1008, 256>>>(sd, pd, shape, frmt);
    k3_gemm<<<dim3(BB / 64, 13), 256, SM_K3>>>(vt);

    // join, then epilogue
    cudaStreamWaitEvent(0, evB, 0);
    k4_epi<<<dim3(BB / 16, 4), 256, SM_K4>>>(outV, outJ);
}

// round 14
// speedup vs baseline: 1.4425x; 1.0304x over previous
#include <cuda_runtime.h>
#include <cuda_bf16.h>
#include <cstdint>

#define BB    8192
#define NVV   778
#define NJJ   16
#define CTOT  2334
#define CPAD  2496          // 13 * 192
#define GK    160           // padded K (145 feat + 15 pad)
#define NVP   832           // 13 * 64 padded verts

// ---------------- device scratch (static; no runtime alloc) ----------------
__device__ __align__(16) float          g_V[(size_t)BB * CPAD];      // GEMM out + bias
__device__ __align__(16) __nv_bfloat16  g_A[BB * GK];
__device__ __align__(16) __nv_bfloat16  g_B[CPAD * GK];              // B^T [n][k]
__device__ __align__(16) __nv_bfloat16  g_Whi[NVP * 16];             // lbs hi/lo
__device__ __align__(16) __nv_bfloat16  g_Wlo[NVP * 16];
__device__ __align__(16) __nv_bfloat16  g_MH[(size_t)BB * 12 * 16];  // M'' hi [(b*12+m)*16+j]
__device__ __align__(16) __nv_bfloat16  g_ML[(size_t)BB * 12 * 16];  // M'' lo
__device__ __align__(16) float g_J0[NJJ * 3];
__device__ __align__(16) float g_JS[NJJ * 3 * 10];

__constant__ int c_par[16] = {0,0,1,2,0,4,5,0,7,8,0,10,11,0,13,14};
__constant__ int c_inv[16] = {0,5,6,7,9,10,11,17,18,19,13,14,15,1,2,3};

__device__ __forceinline__ void mma16816(float* d, const uint32_t* a,
                                         const uint32_t* b) {
    asm volatile(
        "mma.sync.aligned.m16n8k16.row.col.f32.bf16.bf16.f32 "
        "{%0,%1,%2,%3}, {%4,%5,%6,%7}, {%8,%9}, {%0,%1,%2,%3};"
        : "+f"(d[0]), "+f"(d[1]), "+f"(d[2]), "+f"(d[3])
        : "r"(a[0]), "r"(a[1]), "r"(a[2]), "r"(a[3]), "r"(b[0]), "r"(b[1]));
}

__device__ __forceinline__ uint32_t smem_u32(const void* p) {
    uint32_t a;
    asm("{ .reg .u64 t; cvta.to.shared.u64 t, %1; cvt.u32.u64 %0, t; }"
        : "=r"(a) : "l"(p));
    return a;
}
// L1-bypassing 16B async copy
__device__ __forceinline__ void cpasync16(uint32_t dst, const void* src) {
    asm volatile("cp.async.cg.shared.global [%0], [%1], 16;"
                 :: "r"(dst), "l"(src));
}
#define CP_COMMIT()  asm volatile("cp.async.commit_group;" ::: "memory")
#define CP_WAIT(n)   asm volatile("cp.async.wait_group %0;" :: "n"(n) : "memory")

// ---------------------------------------------------------------------------
// K0_SMALL: [0,16): jreg contractions; [16,68): lbs hi/lo split
// ---------------------------------------------------------------------------
__global__ __launch_bounds__(256) void k0_small(const float* __restrict__ vt,
                                                const float* __restrict__ sd,
                                                const float* __restrict__ jreg,
                                                const float* __restrict__ lbs) {
    __shared__ float red[33 * 256];
    const int blk = blockIdx.x, tid = threadIdx.x;

    if (blk >= 16) {                        // ---- lbs hi/lo
        int idx = (blk - 16) * 256 + tid;
        if (idx >= NVP * 16) return;
        int v = idx >> 4, j = idx & 15;
        float w = (v < NVV) ? lbs[v * 16 + j] : 0.f;
        __nv_bfloat16 hi = __float2bfloat16_rn(w);
        __nv_bfloat16 lo = __float2bfloat16_rn(w - __bfloat162float(hi));
        g_Whi[idx] = hi;
        g_Wlo[idx] = lo;
        return;
    }
    // ---- joint regressor: one block per joint
    const int j = blk;
    float acc[33];
#pragma unroll
    for (int o = 0; o < 33; o++) acc[o] = 0.f;
    for (int v = tid; v < NVV; v += 256) {
        float w = jreg[j * NVV + v];
#pragma unroll
        for (int k = 0; k < 3; k++) {
            acc[k] += w * vt[v * 3 + k];
#pragma unroll
            for (int l = 0; l < 10; l++)
                acc[3 + k * 10 + l] += w * sd[(v * 3 + k) * 10 + l];
        }
    }
    for (int o = 0; o < 33; o++) red[o * 256 + tid] = acc[o];
    __syncthreads();
    if (tid < 33) {
        float s = 0.f;
        for (int i = 0; i < 256; i++) s += red[tid * 256 + i];
        if (tid < 3) g_J0[j * 3 + tid] = s;
        else {
            int o = tid - 3;
            int k = o / 10, l = o - k * 10;
            g_JS[(j * 3 + k) * 10 + l] = s;
        }
    }
}

// ---------------------------------------------------------------------------
// K0_AB: [0,640): A (8 elems/thread, 20 groups/row); [640,840): B
// ---------------------------------------------------------------------------
__global__ __launch_bounds__(256) void k0_AB(const float* __restrict__ sd,
                                             const float* __restrict__ pd,
                                             const float* __restrict__ shape,
                                             const float* __restrict__ finger) {
    const int blk = blockIdx.x, tid = threadIdx.x;

    if (blk < 640) {                        // ---- A: feat bf16 [B x 160], 8/thr
        int idx = blk * 256 + tid;          // < 163840
        int b = idx / 20, g = idx - b * 20;
        unsigned short hs[8];
#pragma unroll
        for (int i = 0; i < 8; i++) {
            int k = g * 8 + i;
            float val = 0.f;
            if (k < 10) val = shape[b * 10 + k];
            else if (k < 145) {
                int q = k - 10;
                val = finger[b * 135 + q];
                if (((q % 9) & 3) == 0) val -= 1.0f;
            }
            hs[i] = __bfloat16_as_ushort(__float2bfloat16_rn(val));
        }
        uint4 ph;
        ph.x = hs[0] | ((uint32_t)hs[1] << 16);
        ph.y = hs[2] | ((uint32_t)hs[3] << 16);
        ph.z = hs[4] | ((uint32_t)hs[5] << 16);
        ph.w = hs[6] | ((uint32_t)hs[7] << 16);
        *reinterpret_cast<uint4*>(&g_A[b * GK + g * 8]) = ph;
        return;
    }
    // ---- B^T bf16 [n][k]
    int q = blk - 640;
    int kg = q / 10, nb = q - kg * 10;      // kg 0..19
    int n = nb * 256 + tid;
    if (n >= CPAD) return;
    unsigned short hs[8];
#pragma unroll
    for (int i = 0; i < 8; i++) {
        int k = kg * 8 + i;
        float val = 0.f;
        if (n < CTOT) {
            if (k < 10)       val = sd[n * 10 + k];
            else if (k < 145) val = pd[(k - 10) * CTOT + n];
        }
        hs[i] = __bfloat16_as_ushort(__float2bfloat16_rn(val));
    }
    uint4 ph;
    ph.x = hs[0] | ((uint32_t)hs[1] << 16);
    ph.y = hs[2] | ((uint32_t)hs[3] << 16);
    ph.z = hs[4] | ((uint32_t)hs[5] << 16);
    ph.w = hs[6] | ((uint32_t)hs[7] << 16);
    *reinterpret_cast<uint4*>(&g_B[n * GK + kg * 8]) = ph;
}

// ---------------------------------------------------------------------------
// K2: joint chain — 4 batches per CTA; writes M'' as split-bf16 (b*12+m)x16
// ---------------------------------------------------------------------------
__device__ __forceinline__ void mul4(const float* a, float* d) {
    float t[16];
#pragma unroll
    for (int r = 0; r < 4; r++)
#pragma unroll
        for (int c = 0; c < 4; c++)
            t[r * 4 + c] = a[r * 4 + 0] * d[0 + c] + a[r * 4 + 1] * d[4 + c] +
                           a[r * 4 + 2] * d[8 + c] + a[r * 4 + 3] * d[12 + c];
#pragma unroll
    for (int i = 0; i < 16; i++) d[i] = t[i];
}

__global__ __launch_bounds__(256) void k2_joints(const float* __restrict__ grmt,
                          const float* __restrict__ frmt,
                          const float* __restrict__ shape,
                          const float* __restrict__ trans,
                          float* __restrict__ outJ) {
    __shared__ float sJ[4][16][3];
    __shared__ float sM[4][16][16];
    __shared__ float sF[4][136];
    __shared__ float sg[4][9], st[4][3], ssh[4][10];
    const int tid = threadIdx.x;
    const int bs = tid >> 6;
    const int tl = tid & 63;
    const int b = blockIdx.x * 4 + bs;
    const int b0 = blockIdx.x * 4;

    for (int i = tid; i < 540; i += 256) {
        int s = i / 135, q = i - s * 135;
        sF[s][q] = frmt[(b0 + s) * 135 + q];
    }
    if (tl < 9)  sg[bs][tl]  = grmt[b * 9 + tl];
    if (tl < 3)  st[bs][tl]  = trans[b * 3 + tl];
    if (tl < 10) ssh[bs][tl] = shape[b * 10 + tl];
    __syncthreads();

    if (tl < 48) {
        int j = tl / 3, k = tl - j * 3;
        float a = g_J0[j * 3 + k];
#pragma unroll
        for (int l = 0; l < 10; l++) a += ssh[bs][l] * g_JS[(j * 3 + k) * 10 + l];
        sJ[bs][j][k] = a;
    }
    __syncthreads();

    if (tl < 16) {
        int j = tl;
        float R[9];
        if (j == 0) {
            R[0]=1;R[1]=0;R[2]=0;R[3]=0;R[4]=1;R[5]=0;R[6]=0;R[7]=0;R[8]=1;
        } else {
#pragma unroll
            for (int i = 0; i < 9; i++) R[i] = sF[bs][(j - 1) * 9 + i];
        }
        float t0 = sJ[bs][j][0], t1 = sJ[bs][j][1], t2 = sJ[bs][j][2];
        if (j > 0) {
            int p = c_par[j];
            t0 -= sJ[bs][p][0]; t1 -= sJ[bs][p][1]; t2 -= sJ[bs][p][2];
        }
        float* m = sM[bs][j];
        m[0]=R[0]; m[1]=R[1]; m[2]=R[2];  m[3]=t0;
        m[4]=R[3]; m[5]=R[4]; m[6]=R[5];  m[7]=t1;
        m[8]=R[6]; m[9]=R[7]; m[10]=R[8]; m[11]=t2;
        m[12]=0.f; m[13]=0.f; m[14]=0.f;  m[15]=1.f;
    }
    __syncthreads();

    if (tl < 5) {
        int j = 1 + 3 * tl;
        mul4(sM[bs][0], sM[bs][j]);
        mul4(sM[bs][j], sM[bs][j + 1]);
        mul4(sM[bs][j + 1], sM[bs][j + 2]);
    }
    __syncthreads();

    if (tl < 16) {
        int j = tl;
        const float* m = sM[bs][j];
        float jt0 = m[3], jt1 = m[7], jt2 = m[11];
        float J0 = sJ[bs][j][0], J1 = sJ[bs][j][1], J2 = sJ[bs][j][2];
        float tc0 = jt0 - (m[0] * J0 + m[1] * J1 + m[2]  * J2);
        float tc1 = jt1 - (m[4] * J0 + m[5] * J1 + m[6]  * J2);
        float tc2 = jt2 - (m[8] * J0 + m[9] * J1 + m[10] * J2);
        float row[12];
        int jp = c_inv[j];
#pragma unroll
        for (int r = 0; r < 3; r++) {
            float a = sg[bs][r * 3 + 0], bb = sg[bs][r * 3 + 1], cc = sg[bs][r * 3 + 2];
            row[r * 4 + 0] = a * m[0] + bb * m[4] + cc * m[8];
            row[r * 4 + 1] = a * m[1] + bb * m[5] + cc * m[9];
            row[r * 4 + 2] = a * m[2] + bb * m[6] + cc * m[10];
            row[r * 4 + 3] = a * tc0  + bb * tc1  + cc * tc2 + st[bs][r];
            outJ[(b * 21 + jp) * 3 + r] = a * jt0 + bb * jt1 + cc * jt2 + st[bs][r];
        }
#pragma unroll
        for (int mm = 0; mm < 12; mm++) {
            float x = row[mm];
            __nv_bfloat16 hi = __float2bfloat16_rn(x);
            __nv_bfloat16 lo = __float2bfloat16_rn(x - __bfloat162float(hi));
            size_t off = ((size_t)b * 12 + mm) * 16 + j;
            g_MH[off] = hi;
            g_ML[off] = lo;
        }
    }
}

// ---------------------------------------------------------------------------
// K3: single-bf16 mma.sync GEMM, cp.async 2-stage -> g_V (+fp32 bias)
//   CTA: 256 thr, tile 64(b) x 192(n), K=160 in chunks 64+64+32. 2 CTAs/SM.
// ---------------------------------------------------------------------------
#define STG_SZ  36864
#define SM_K3   73728

__global__ __launch_bounds__(256, 2) void k3_gemm(const float* __restrict__ vt) {
    extern __shared__ __align__(16) char smem[];
    __shared__ float sBias[192];
    const uint32_t sbase = smem_u32(smem);
    const int tid = threadIdx.x;
    const int wid = tid >> 5, lane = tid & 31;
    const int wm = wid & 1, wn = wid >> 1;
    const int gid = lane >> 2, tig = lane & 3;
    const int b0 = blockIdx.x * 64;
    const int t  = blockIdx.y;

    if (tid < 192) {
        int c = t * 192 + tid;
        sBias[tid] = (c < CTOT) ? vt[c] : 0.f;
    }

    // stage one K-chunk of width KC starting at koff into stage s
    auto stage_chunk = [&](int s, int koff, int KC) {
        const uint32_t stg = sbase + s * STG_SZ;
        const int perRow = KC >> 3;           // uint4s per row
        const int aTasks = 64 * perRow;
        const int total  = 256 * perRow;
        for (int i = tid; i < total; i += 256) {
            if (i < aTasks) {
                int r = i / perRow, q = i - r * perRow;
                cpasync16(stg + r * 144 + q * 16,
                          &g_A[(b0 + r) * GK + koff + q * 8]);
            } else {
                int i2 = i - aTasks;
                int r = i2 / perRow, q = i2 - r * perRow;
                cpasync16(stg + 9216 + r * 144 + q * 16,
                          &g_B[(t * 192 + r) * GK + koff + q * 8]);
            }
        }
    };

    float d[2][6][4];
#pragma unroll
    for (int mt = 0; mt < 2; mt++)
#pragma unroll
        for (int nt = 0; nt < 6; nt++)
#pragma unroll
            for (int q = 0; q < 4; q++) d[mt][nt][q] = 0.f;

    stage_chunk(0, 0, 64);  CP_COMMIT();
    stage_chunk(1, 64, 64); CP_COMMIT();

    auto mma_chunk = [&](int s, int KS) {
        const char* stg = smem + s * STG_SZ;
        for (int ks = 0; ks < KS; ks++) {
            const int kb = ks * 32 + tig * 4;
            uint32_t ah[2][4];
#pragma unroll
            for (int mt = 0; mt < 2; mt++) {
                int r0 = wm * 32 + mt * 16 + gid;
                const char* ph = stg + r0 * 144 + kb;
                ah[mt][0] = *(const uint32_t*)(ph);
                ah[mt][1] = *(const uint32_t*)(ph + 8 * 144);
                ah[mt][2] = *(const uint32_t*)(ph + 16);
                ah[mt][3] = *(const uint32_t*)(ph + 8 * 144 + 16);
            }
            uint32_t bh[6][2];
#pragma unroll
            for (int nt = 0; nt < 6; nt++) {
                int n0 = wn * 48 + nt * 8 + gid;
                const char* ph = stg + 9216 + n0 * 144 + kb;
                bh[nt][0] = *(const uint32_t*)(ph);
                bh[nt][1] = *(const uint32_t*)(ph + 16);
            }
#pragma unroll
            for (int mt = 0; mt < 2; mt++)
#pragma unroll
                for (int nt = 0; nt < 6; nt++)
                    mma16816(d[mt][nt], ah[mt], bh[nt]);
        }
    };

    CP_WAIT(1); __syncthreads();
    mma_chunk(0, 4);
    __syncthreads();
    stage_chunk(0, 128, 32); CP_COMMIT();
    CP_WAIT(1); __syncthreads();
    mma_chunk(1, 4);
    CP_WAIT(0); __syncthreads();
    mma_chunk(0, 2);

#pragma unroll
    for (int mt = 0; mt < 2; mt++) {
        int r0 = b0 + wm * 32 + mt * 16 + gid;
#pragma unroll
        for (int nt = 0; nt < 6; nt++) {
            int cl = wn * 48 + nt * 8 + tig * 2;
            int c = t * 192 + cl;
            float bx = sBias[cl], by = sBias[cl + 1];
            *reinterpret_cast<float2*>(&g_V[(size_t)r0 * CPAD + c]) =
                make_float2(d[mt][nt][0] + bx, d[mt][nt][1] + by);
            *reinterpret_cast<float2*>(&g_V[(size_t)(r0 + 8) * CPAD + c]) =
                make_float2(d[mt][nt][2] + bx, d[mt][nt][3] + by);
        }
    }
}

// ---------------------------------------------------------------------------
// K4: warp-autonomous LBS blend, 4 CTAs/SM.
//   smem: region A @0 (13312): M'' hi/lo during init, strips after hoist
//         sW dbuf @13312 (2x4096) | sV dbuf @21504 (2x12288)  total 46080
// ---------------------------------------------------------------------------
#define SM_K4 46080

__global__ __launch_bounds__(256, 4) void k4_epi(float* __restrict__ outV,
                                                 float* __restrict__ outJ) {
    extern __shared__ __align__(16) char smem[];
    const uint32_t sbase = smem_u32(smem);
    __nv_bfloat16* sMh = reinterpret_cast<__nv_bfloat16*>(smem);
    __nv_bfloat16* sMl = reinterpret_cast<__nv_bfloat16*>(smem + 6144);

    const int tid = threadIdx.x;
    const int b0 = blockIdx.x * 16;
    const int y  = blockIdx.y;
    const int tstart = (y == 0) ? 0 : 1 + y * 3;      // {0,4,7,10}
    const int tend   = tstart + ((y == 0) ? 4 : 3);   // {4,7,10,13}

    auto stage_W = [&](int s, int t) {
        int split = tid >> 7, i2 = tid & 127;
        int row = i2 >> 1, half = i2 & 1;
        const __nv_bfloat16* src = split ? g_Wlo : g_Whi;
        cpasync16(sbase + 13312 + s * 4096 + split * 2048 +
                      (row * 16 + half * 8) * 2,
                  &src[(t * 64 + row) * 16 + half * 8]);
    };
    auto stage_V = [&](int s, int t) {
        for (int i = tid; i < 768; i += 256) {
            int r = i / 48, q = i - r * 48;
            cpasync16(sbase + 21504 + s * 12288 + (r * 192 + q * 4) * 4,
                      &g_V[(size_t)(b0 + r) * CPAD + t * 192 + q * 4]);
        }
    };

    // stage M'' (12KB into region A) + first W and V slices
    for (int i = tid; i < 768; i += 256) {
        int split = i / 384, i2 = i - split * 384;
        int n = i2 >> 1, half = i2 & 1;
        const __nv_bfloat16* src = split ? g_ML : g_MH;
        cpasync16(sbase + split * 6144 + (n * 16 + half * 8) * 2,
                  &src[((size_t)b0 * 12 + n) * 16 + half * 8]);
    }
    stage_W(0, tstart);
    stage_V(0, tstart);
    CP_COMMIT();
    CP_WAIT(0);
    __syncthreads();

    const int wid = tid >> 5, lane = tid & 31;
    const int gid = lane >> 2, tig = lane & 3;
    float* strip = reinterpret_cast<float*>(smem + wid * 1664);  // region A reuse
    const int half = lane >> 4, lv = lane & 15;
    const int bq = wid * 2 + half;
    const int bglob = b0 + bq;

    // hoist B fragments (M'' columns) — tile-invariant
    uint32_t fbh[3][2], fbl[3][2];
#pragma unroll
    for (int ntl = 0; ntl < 3; ntl++) {
        int n0 = wid * 24 + ntl * 8 + gid;
        fbh[ntl][0] = *reinterpret_cast<const uint32_t*>(&sMh[n0 * 16 + tig * 2]);
        fbh[ntl][1] = *reinterpret_cast<const uint32_t*>(&sMh[n0 * 16 + 8 + tig * 2]);
        fbl[ntl][0] = *reinterpret_cast<const uint32_t*>(&sMl[n0 * 16 + tig * 2]);
        fbl[ntl][1] = *reinterpret_cast<const uint32_t*>(&sMl[n0 * 16 + 8 + tig * 2]);
    }
    __syncthreads();   // all M'' reads done before strips overwrite region A

    for (int t = tstart; t < tend; t++) {
        const int s = (t - tstart) & 1;
        if (t + 1 < tend) {
            stage_W(s ^ 1, t + 1);
            stage_V(s ^ 1, t + 1);
            CP_COMMIT();
        }
        const __nv_bfloat16* sWh =
            reinterpret_cast<const __nv_bfloat16*>(smem + 13312 + s * 4096);
        const __nv_bfloat16* sWl = sWh + 1024;
        const float* sVf =
            reinterpret_cast<const float*>(smem + 21504 + s * 12288);
        const int c0 = t * 192;

#pragma unroll
        for (int mt = 0; mt < 4; mt++) {
            int r0 = mt * 16 + gid;
            uint32_t awh[4], awl[4];
            awh[0] = *reinterpret_cast<const uint32_t*>(&sWh[r0 * 16 + tig * 2]);
            awh[1] = *reinterpret_cast<const uint32_t*>(&sWh[(r0 + 8) * 16 + tig * 2]);
            awh[2] = *reinterpret_cast<const uint32_t*>(&sWh[r0 * 16 + 8 + tig * 2]);
            awh[3] = *reinterpret_cast<const uint32_t*>(&sWh[(r0 + 8) * 16 + 8 + tig * 2]);
            awl[0] = *reinterpret_cast<const uint32_t*>(&sWl[r0 * 16 + tig * 2]);
            awl[1] = *reinterpret_cast<const uint32_t*>(&sWl[(r0 + 8) * 16 + tig * 2]);
            awl[2] = *reinterpret_cast<const uint32_t*>(&sWl[r0 * 16 + 8 + tig * 2]);
            awl[3] = *reinterpret_cast<const uint32_t*>(&sWl[(r0 + 8) * 16 + 8 + tig * 2]);
#pragma unroll
            for (int ntl = 0; ntl < 3; ntl++) {
                float d[4] = {0.f, 0.f, 0.f, 0.f};
                mma16816(d, awh, fbh[ntl]);
                mma16816(d, awh, fbl[ntl]);
                mma16816(d, awl, fbh[ntl]);
                int col = ntl * 8 + tig * 2;
                *reinterpret_cast<float2*>(&strip[gid * 26 + col]) =
                    make_float2(d[0], d[1]);
                *reinterpret_cast<float2*>(&strip[(gid + 8) * 26 + col]) =
                    make_float2(d[2], d[3]);
            }
            __syncwarp();

            int v = mt * 16 + lv;
            int vg = t * 64 + v;
            if (vg < NVV) {
                const float* mv = &strip[lv * 26 + half * 12];
                float2 a0 = *reinterpret_cast<const float2*>(mv);
                float2 a1 = *reinterpret_cast<const float2*>(mv + 2);
                float2 a2 = *reinterpret_cast<const float2*>(mv + 4);
                float2 a3 = *reinterpret_cast<const float2*>(mv + 6);
                float2 a4 = *reinterpret_cast<const float2*>(mv + 8);
                float2 a5 = *reinterpret_cast<const float2*>(mv + 10);
                const float* vp = &sVf[bq * 192 + v * 3];
                float x = vp[0], yv = vp[1], z = vp[2];
                float o0 = fmaf(a0.x, x, fmaf(a0.y, yv, fmaf(a1.x, z, a1.y)));
                float o1 = fmaf(a2.x, x, fmaf(a2.y, yv, fmaf(a3.x, z, a3.y)));
                float o2 = fmaf(a4.x, x, fmaf(a4.y, yv, fmaf(a5.x, z, a5.y)));
                float* op = &outV[(size_t)bglob * CTOT + c0 + v * 3];
                op[0] = o0; op[1] = o1; op[2] = o2;

                int tp = -1;
                if (vg == 745) tp = 4; else if (vg == 317) tp = 8;
                else if (vg == 444) tp = 12; else if (vg == 556) tp = 16;
                else if (vg == 673) tp = 20;
                if (tp >= 0) {
                    outJ[(bglob * 21 + tp) * 3 + 0] = o0;
                    outJ[(bglob * 21 + tp) * 3 + 1] = o1;
                    outJ[(bglob * 21 + tp) * 3 + 2] = o2;
                }
            }
            __syncwarp();
        }

        if (t + 1 < tend) CP_WAIT(0);
        __syncthreads();
    }
}

// ---------------------------------------------------------------------------
extern "C" void kernel_launch(void* const* d_in, const int* in_sizes, int n_in,
                              void* d_out, int out_size) {
    const float* grmt  = (const float*)d_in[0];
    const float* frmt  = (const float*)d_in[1];
    const float* shape = (const float*)d_in[2];
    const float* trans = (const float*)d_in[3];
    const float* vt    = (const float*)d_in[4];
    const float* sd    = (const float*)d_in[5];
    const float* jreg  = (const float*)d_in[6];
    const float* pd    = (const float*)d_in[7];
    const float* lbs   = (const float*)d_in[8];

    float* out  = (float*)d_out;
    float* outV = out;
    float* outJ = out + (size_t)BB * CTOT;

    static cudaStream_t sB = nullptr;
    static cudaEvent_t evRoot = nullptr, evB = nullptr;
    static bool attr_done = false;
    if (!attr_done) {
        cudaFuncSetAttribute(k3_gemm, cudaFuncAttributeMaxDynamicSharedMemorySize,
                             SM_K3);
        cudaFuncSetAttribute(k4_epi, cudaFuncAttributeMaxDynamicSharedMemorySize,
                             SM_K4);
        cudaStreamCreateWithFlags(&sB, cudaStreamNonBlocking);
        cudaEventCreateWithFlags(&evRoot, cudaEventDisableTiming);
        cudaEventCreateWithFlags(&evB, cudaEventDisableTiming);
        attr_done = true;
    }

    // fork: branch stream runs k0_small -> k2 concurrent with k0_AB -> k3
    cudaEventRecord(evRoot, 0);
    cudaStreamWaitEvent(sB, evRoot, 0);

    k0_small<<<68, 256, 0, sB>>>(vt, sd, jreg, lbs);
    k2_joints<<<BB / 4, 256, 0, sB>>>(grmt, frmt, shape, trans, outJ);
    cudaEventRecord(evB, sB);

    k0_AB<<<840, 256>>>(sd, pd, shape, frmt);
    k3_gemm<<<dim3(BB / 64, 13), 256, SM_K3>>>(vt);

    // join, then epilogue
    cudaStreamWaitEvent(0, evB, 0);
    k4_epi<<<dim3(BB / 16, 4), 256, SM_K4>>>(outV, outJ);
}